// round 2
// baseline (speedup 1.0000x reference)
#include <cuda_runtime.h>
#include <math.h>

// ---------------------------------------------------------------------------
// Problem constants
//   x,y: [64,128,64]  -> 64 sets, 128 items, 64 features
//   HEADS=2, HS=64, LEAKY=0.3
//   Pipeline: set_norm -> QKV proj -> masked attention -> Wh proj -> Wc proj
//             -> fused cross-set bilinear leaky score -> Wc2
// ---------------------------------------------------------------------------

#define NSET   64
#define NITEM  128
#define DFEAT  64
#define ROWS_ONE (NSET * NITEM)        // 8192 rows per tensor
#define ROWS_ALL (2 * ROWS_ONE)        // 16384 rows (x then y)

// scratch (static device globals; allocation APIs are forbidden)
__device__ float g_xyn [ROWS_ALL * 64];    // normalized x;y
__device__ float g_Q   [ROWS_ALL * 128];
__device__ float g_K   [ROWS_ALL * 128];
__device__ float g_V   [ROWS_ALL * 128];
__device__ float g_att [ROWS_ALL * 128];   // concat-head attention output
__device__ float g_h   [ROWS_ALL * 64];    // after Wh
__device__ float g_p   [ROWS_ALL * 128];   // after Wc  (xp rows 0..8191, yp rows 8192..)

// ---------------------------------------------------------------------------
// Kernel 1: masked set normalization. One block per set, 256 threads.
// ---------------------------------------------------------------------------
__global__ __launch_bounds__(256) void setnorm_kernel(
    const float* __restrict__ X, const int* __restrict__ sz, float* __restrict__ O)
{
    const int n   = blockIdx.x;
    const int tid = threadIdx.x;
    const float* xb = X + n * (NITEM * DFEAT);
    float*       ob = O + n * (NITEM * DFEAT);

    __shared__ float rmask[NITEM];
    __shared__ float red[256];
    __shared__ float s_mean, s_inv;

    if (tid < NITEM) {
        float s = 0.f;
        #pragma unroll
        for (int e = 0; e < DFEAT; e++) s += xb[tid * DFEAT + e];
        rmask[tid] = (s != 0.0f) ? 1.0f : 0.0f;
    }

    float tot = 0.f;
    for (int idx = tid; idx < NITEM * DFEAT; idx += 256) tot += xb[idx];
    red[tid] = tot; __syncthreads();
    for (int s = 128; s > 0; s >>= 1) {
        if (tid < s) red[tid] += red[tid + s];
        __syncthreads();
    }
    const float denom = (float)sz[n] * (float)DFEAT;
    if (tid == 0) s_mean = red[0] / denom;
    __syncthreads();
    const float mean = s_mean;

    float ss = 0.f;
    for (int idx = tid; idx < NITEM * DFEAT; idx += 256) {
        float d = xb[idx] - mean;
        ss += d * d * rmask[idx >> 6];
    }
    __syncthreads();
    red[tid] = ss; __syncthreads();
    for (int s = 128; s > 0; s >>= 1) {
        if (tid < s) red[tid] += red[tid + s];
        __syncthreads();
    }
    if (tid == 0) s_inv = 1.0f / (sqrtf(red[0] / denom) + 1e-8f);
    __syncthreads();
    const float inv = s_inv;

    for (int idx = tid; idx < NITEM * DFEAT; idx += 256)
        ob[idx] = (xb[idx] - mean) * inv * rmask[idx >> 6];
}

// ---------------------------------------------------------------------------
// Kernel 2: generic small SGEMM  C[M,N] = A[M,K] @ B[K,N]
// BM=BN=64, BK=16, 256 threads, 4x4 microtile.
// ---------------------------------------------------------------------------
__global__ __launch_bounds__(256) void sgemm_kernel(
    const float* __restrict__ A, const float* __restrict__ B,
    float* __restrict__ C, int M, int N, int K)
{
    __shared__ float As[16][65];
    __shared__ float Bs[16][65];
    const int bx = blockIdx.x, by = blockIdx.y;
    const int tid = threadIdx.x;
    const int tx = tid & 15, ty = tid >> 4;

    float acc[4][4] = {};
    for (int k0 = 0; k0 < K; k0 += 16) {
        #pragma unroll
        for (int i = tid; i < 64 * 16; i += 256) {
            int r = i >> 4, kk = i & 15;
            As[kk][r] = A[(by * 64 + r) * K + k0 + kk];
        }
        #pragma unroll
        for (int i = tid; i < 16 * 64; i += 256) {
            int kk = i >> 6, c = i & 63;
            Bs[kk][c] = B[(k0 + kk) * N + bx * 64 + c];
        }
        __syncthreads();
        #pragma unroll
        for (int kk = 0; kk < 16; kk++) {
            float a[4], b[4];
            #pragma unroll
            for (int i = 0; i < 4; i++) a[i] = As[kk][ty * 4 + i];
            #pragma unroll
            for (int j = 0; j < 4; j++) b[j] = Bs[kk][tx * 4 + j];
            #pragma unroll
            for (int i = 0; i < 4; i++)
                #pragma unroll
                for (int j = 0; j < 4; j++)
                    acc[i][j] = fmaf(a[i], b[j], acc[i][j]);
        }
        __syncthreads();
    }
    #pragma unroll
    for (int i = 0; i < 4; i++)
        #pragma unroll
        for (int j = 0; j < 4; j++)
            C[(by * 64 + ty * 4 + i) * N + bx * 64 + tx * 4 + j] = acc[i][j];
}

// ---------------------------------------------------------------------------
// Kernel 3: masked attention per (global set g in 0..127, head).
// Q,K,V are [16384,128], head h uses cols [64h,64h+64).
// mask = (score != 0); max over ALL entries (incl. zeros) per reference.
// 128 threads: one thread per query row.
// ---------------------------------------------------------------------------
#define ATTN_SMEM ((2 * 128 * 64 + 128 * 129) * 4)

__global__ __launch_bounds__(128) void attn_kernel(
    const float* __restrict__ Q, const float* __restrict__ K,
    const float* __restrict__ V, float* __restrict__ O)
{
    extern __shared__ float sm[];
    float* Ksh = sm;                 // [128][64]
    float* Vsh = sm + 128 * 64;      // [128][64]
    float* Ssh = sm + 2 * 128 * 64;  // [128][129]

    const int g = blockIdx.x, h = blockIdx.y;
    const int tid = threadIdx.x;     // 0..127 = query row
    const int rowbase = g * NITEM;
    const int hc = h * 64;

    for (int idx = tid; idx < 128 * 64; idx += 128) {
        int i = idx >> 6, e = idx & 63;
        Ksh[idx] = K[(rowbase + i) * 128 + hc + e];
        Vsh[idx] = V[(rowbase + i) * 128 + hc + e];
    }
    __syncthreads();

    // q row into registers
    float4 q[16];
    const float4* qg = (const float4*)&Q[(rowbase + tid) * 128 + hc];
    #pragma unroll
    for (int i = 0; i < 16; i++) q[i] = qg[i];

    float* srow = &Ssh[tid * 129];
    float m = -3.4e38f;
    for (int j = 0; j < 128; j++) {
        const float4* kr = (const float4*)&Ksh[j * 64];
        float d0 = 0.f, d1 = 0.f, d2 = 0.f, d3 = 0.f;
        #pragma unroll
        for (int i = 0; i < 16; i += 4) {
            float4 k0 = kr[i], k1 = kr[i+1], k2 = kr[i+2], k3 = kr[i+3];
            d0 += q[i  ].x*k0.x + q[i  ].y*k0.y + q[i  ].z*k0.z + q[i  ].w*k0.w;
            d1 += q[i+1].x*k1.x + q[i+1].y*k1.y + q[i+1].z*k1.z + q[i+1].w*k1.w;
            d2 += q[i+2].x*k2.x + q[i+2].y*k2.y + q[i+2].z*k2.z + q[i+2].w*k2.w;
            d3 += q[i+3].x*k3.x + q[i+3].y*k3.y + q[i+3].z*k3.z + q[i+3].w*k3.w;
        }
        float s = (d0 + d1 + d2 + d3) * 0.125f;   // /sqrt(64)
        srow[j] = s;
        m = fmaxf(m, s);
    }

    float den = 1e-10f;
    for (int j = 0; j < 128; j++) {
        float s = srow[j];
        float p = (s != 0.0f) ? expf(s - m) : 0.0f;
        srow[j] = p;
        den += p;
    }
    const float invd = 1.0f / den;

    float4 acc[16];
    #pragma unroll
    for (int i = 0; i < 16; i++) acc[i] = make_float4(0.f, 0.f, 0.f, 0.f);
    for (int j = 0; j < 128; j++) {
        float p = srow[j];
        if (p == 0.0f) continue;
        const float4* vr = (const float4*)&Vsh[j * 64];
        #pragma unroll
        for (int i = 0; i < 16; i++) {
            float4 v = vr[i];
            acc[i].x = fmaf(p, v.x, acc[i].x);
            acc[i].y = fmaf(p, v.y, acc[i].y);
            acc[i].z = fmaf(p, v.z, acc[i].z);
            acc[i].w = fmaf(p, v.w, acc[i].w);
        }
    }

    float4* og = (float4*)&O[(rowbase + tid) * 128 + hc];
    #pragma unroll
    for (int i = 0; i < 16; i++)
        og[i] = make_float4(acc[i].x * invd, acc[i].y * invd,
                            acc[i].z * invd, acc[i].w * invd);
}

// ---------------------------------------------------------------------------
// Kernel 4: fused cross-set score. One block per (a,b) pair.
// For head h: S = Xp_a[:,64h:64h+64] @ Yp_b[:,64h:64h+64]^T  (128x128x64),
// reduce sum(leaky(S)), then scale and combine with Wc2. Score tensor never
// materialized. Channel-major smem tiles, 8x8 register microtile.
// ---------------------------------------------------------------------------
#define PSTR 132
#define CROSS_SMEM (2 * 128 * PSTR * 4)

__global__ __launch_bounds__(256) void cross_kernel(
    const float* __restrict__ P, const int* __restrict__ xsz,
    const float* __restrict__ Wc2, float* __restrict__ out)
{
    extern __shared__ float sm[];
    float* xs = sm;                  // [128 channels][PSTR rows]
    float* ys = sm + 128 * PSTR;

    const int b = blockIdx.x, a = blockIdx.y;
    const int tid = threadIdx.x;     // 256
    const float* xp = P + (size_t)a * NITEM * 128;
    const float* yp = P + (size_t)ROWS_ONE * 128 + (size_t)b * NITEM * 128;

    for (int idx = tid; idx < NITEM * 128; idx += 256) {
        int i = idx >> 7, c = idx & 127;      // i = item row, c = channel
        xs[c * PSTR + i] = xp[idx];
        ys[c * PSTR + i] = yp[idx];
    }
    __syncthreads();

    const int tx = tid & 15, ty = tid >> 4;
    const int r0 = ty * 8, c0 = tx * 8;

    float hsum[2];
    #pragma unroll
    for (int h = 0; h < 2; h++) {
        float acc[64];
        #pragma unroll
        for (int i = 0; i < 64; i++) acc[i] = 0.f;

        #pragma unroll 4
        for (int k = 0; k < 64; k++) {
            const int ch = h * 64 + k;
            float xa[8], yb[8];
            *(float4*)&xa[0] = *(const float4*)(xs + ch * PSTR + r0);
            *(float4*)&xa[4] = *(const float4*)(xs + ch * PSTR + r0 + 4);
            *(float4*)&yb[0] = *(const float4*)(ys + ch * PSTR + c0);
            *(float4*)&yb[4] = *(const float4*)(ys + ch * PSTR + c0 + 4);
            #pragma unroll
            for (int i = 0; i < 8; i++)
                #pragma unroll
                for (int j = 0; j < 8; j++)
                    acc[i * 8 + j] = fmaf(xa[i], yb[j], acc[i * 8 + j]);
        }
        float s = 0.f;
        #pragma unroll
        for (int i = 0; i < 64; i++) {
            float v = acc[i];
            s += (v > 0.f) ? v : 0.3f * v;   // leaky_relu
        }
        hsum[h] = s;
    }
    __syncthreads();   // tiles no longer needed; reuse smem for reduction

    float* red = sm;   // 512 floats
    red[tid]       = hsum[0];
    red[256 + tid] = hsum[1];
    __syncthreads();
    for (int s = 128; s > 0; s >>= 1) {
        if (tid < s) {
            red[tid]       += red[tid + s];
            red[256 + tid] += red[256 + tid + s];
        }
        __syncthreads();
    }
    if (tid == 0) {
        // /scale(8) /nItem[b] (= x_size[b] per reference quirk) /Iy(128)
        float scale = 1.0f / (8.0f * (float)xsz[b] * 128.0f);
        out[a * NSET + b] = red[0] * scale * Wc2[0] + red[256] * scale * Wc2[1];
    }
}

// ---------------------------------------------------------------------------
// Launch
// ---------------------------------------------------------------------------
extern "C" void kernel_launch(void* const* d_in, const int* in_sizes, int n_in,
                              void* d_out, int out_size)
{
    const float* x    = (const float*)d_in[0];
    const float* y    = (const float*)d_in[1];
    const float* Wq   = (const float*)d_in[2];
    const float* Wk   = (const float*)d_in[3];
    const float* Wv   = (const float*)d_in[4];
    const float* Wh   = (const float*)d_in[5];
    const float* Wc   = (const float*)d_in[6];
    const float* Wc2  = (const float*)d_in[7];
    const int*   xsz  = (const int*)d_in[8];
    const int*   ysz  = (const int*)d_in[9];
    float* out = (float*)d_out;

    float *pXYN, *pQ, *pK, *pV, *pA, *pH, *pP;
    cudaGetSymbolAddress((void**)&pXYN, g_xyn);
    cudaGetSymbolAddress((void**)&pQ,   g_Q);
    cudaGetSymbolAddress((void**)&pK,   g_K);
    cudaGetSymbolAddress((void**)&pV,   g_V);
    cudaGetSymbolAddress((void**)&pA,   g_att);
    cudaGetSymbolAddress((void**)&pH,   g_h);
    cudaGetSymbolAddress((void**)&pP,   g_p);

    cudaFuncSetAttribute(attn_kernel,  cudaFuncAttributeMaxDynamicSharedMemorySize, ATTN_SMEM);
    cudaFuncSetAttribute(cross_kernel, cudaFuncAttributeMaxDynamicSharedMemorySize, CROSS_SMEM);

    // 1) set norm (x, then y)
    setnorm_kernel<<<NSET, 256>>>(x, xsz, pXYN);
    setnorm_kernel<<<NSET, 256>>>(y, ysz, pXYN + (size_t)ROWS_ONE * 64);

    // 2) QKV projections over all 16384 rows
    sgemm_kernel<<<dim3(2, ROWS_ALL / 64), 256>>>(pXYN, Wq, pQ, ROWS_ALL, 128, 64);
    sgemm_kernel<<<dim3(2, ROWS_ALL / 64), 256>>>(pXYN, Wk, pK, ROWS_ALL, 128, 64);
    sgemm_kernel<<<dim3(2, ROWS_ALL / 64), 256>>>(pXYN, Wv, pV, ROWS_ALL, 128, 64);

    // 3) masked attention: 128 global sets x 2 heads
    attn_kernel<<<dim3(2 * NSET, 2), 128, ATTN_SMEM>>>(pQ, pK, pV, pA);

    // 4) head-merge projection Wh, then cross projection Wc
    sgemm_kernel<<<dim3(1, ROWS_ALL / 64), 256>>>(pA, Wh, pH, ROWS_ALL, 64, 128);
    sgemm_kernel<<<dim3(2, ROWS_ALL / 64), 256>>>(pH, Wc, pP, ROWS_ALL, 128, 64);

    // 5) fused cross-set scoring
    cross_kernel<<<dim3(NSET, NSET), 256, CROSS_SMEM>>>(pP, xsz, Wc2, out);
}

// round 3
// speedup vs baseline: 2.2622x; 2.2622x over previous
#include <cuda_runtime.h>
#include <math.h>

// ---------------------------------------------------------------------------
//   x,y: [64,128,64], HEADS=2, HS=64, LEAKY=0.3
//   set_norm -> QKV proj -> masked attention -> Wh -> Wc -> fused tf32
//   tensor-core cross-set bilinear leaky score -> Wc2
// ---------------------------------------------------------------------------

#define NSET   64
#define NITEM  128
#define DFEAT  64
#define ROWS_ONE (NSET * NITEM)        // 8192
#define ROWS_ALL (2 * ROWS_ONE)        // 16384

__device__ float g_xyn [ROWS_ALL * 64];
__device__ float g_Q   [ROWS_ALL * 128];
__device__ float g_K   [ROWS_ALL * 128];
__device__ float g_V   [ROWS_ALL * 128];
__device__ float g_att [ROWS_ALL * 128];
__device__ float g_h   [ROWS_ALL * 64];
__device__ float g_p   [ROWS_ALL * 128];

// ---------------------------------------------------------------------------
// Kernel 1: masked set normalization
// ---------------------------------------------------------------------------
__global__ __launch_bounds__(256) void setnorm_kernel(
    const float* __restrict__ X, const int* __restrict__ sz, float* __restrict__ O)
{
    const int n   = blockIdx.x;
    const int tid = threadIdx.x;
    const float* xb = X + n * (NITEM * DFEAT);
    float*       ob = O + n * (NITEM * DFEAT);

    __shared__ float rmask[NITEM];
    __shared__ float red[256];
    __shared__ float s_mean, s_inv;

    if (tid < NITEM) {
        float s = 0.f;
        #pragma unroll
        for (int e = 0; e < DFEAT; e++) s += xb[tid * DFEAT + e];
        rmask[tid] = (s != 0.0f) ? 1.0f : 0.0f;
    }

    float tot = 0.f;
    for (int idx = tid; idx < NITEM * DFEAT; idx += 256) tot += xb[idx];
    red[tid] = tot; __syncthreads();
    for (int s = 128; s > 0; s >>= 1) {
        if (tid < s) red[tid] += red[tid + s];
        __syncthreads();
    }
    const float denom = (float)sz[n] * (float)DFEAT;
    if (tid == 0) s_mean = red[0] / denom;
    __syncthreads();
    const float mean = s_mean;

    float ss = 0.f;
    for (int idx = tid; idx < NITEM * DFEAT; idx += 256) {
        float d = xb[idx] - mean;
        ss += d * d * rmask[idx >> 6];
    }
    __syncthreads();
    red[tid] = ss; __syncthreads();
    for (int s = 128; s > 0; s >>= 1) {
        if (tid < s) red[tid] += red[tid + s];
        __syncthreads();
    }
    if (tid == 0) s_inv = 1.0f / (sqrtf(red[0] / denom) + 1e-8f);
    __syncthreads();
    const float inv = s_inv;

    for (int idx = tid; idx < NITEM * DFEAT; idx += 256)
        ob[idx] = (xb[idx] - mean) * inv * rmask[idx >> 6];
}

// ---------------------------------------------------------------------------
// Kernel 2: small SGEMM  C[M,N] = A[M,K] @ B[K,N]
// ---------------------------------------------------------------------------
__global__ __launch_bounds__(256) void sgemm_kernel(
    const float* __restrict__ A, const float* __restrict__ B,
    float* __restrict__ C, int M, int N, int K)
{
    __shared__ float As[16][65];
    __shared__ float Bs[16][65];
    const int bx = blockIdx.x, by = blockIdx.y;
    const int tid = threadIdx.x;
    const int tx = tid & 15, ty = tid >> 4;

    float acc[4][4] = {};
    for (int k0 = 0; k0 < K; k0 += 16) {
        #pragma unroll
        for (int i = tid; i < 64 * 16; i += 256) {
            int r = i >> 4, kk = i & 15;
            As[kk][r] = A[(by * 64 + r) * K + k0 + kk];
        }
        #pragma unroll
        for (int i = tid; i < 16 * 64; i += 256) {
            int kk = i >> 6, c = i & 63;
            Bs[kk][c] = B[(k0 + kk) * N + bx * 64 + c];
        }
        __syncthreads();
        #pragma unroll
        for (int kk = 0; kk < 16; kk++) {
            float a[4], b[4];
            #pragma unroll
            for (int i = 0; i < 4; i++) a[i] = As[kk][ty * 4 + i];
            #pragma unroll
            for (int j = 0; j < 4; j++) b[j] = Bs[kk][tx * 4 + j];
            #pragma unroll
            for (int i = 0; i < 4; i++)
                #pragma unroll
                for (int j = 0; j < 4; j++)
                    acc[i][j] = fmaf(a[i], b[j], acc[i][j]);
        }
        __syncthreads();
    }
    #pragma unroll
    for (int i = 0; i < 4; i++)
        #pragma unroll
        for (int j = 0; j < 4; j++)
            C[(by * 64 + ty * 4 + i) * N + bx * 64 + tx * 4 + j] = acc[i][j];
}

// ---------------------------------------------------------------------------
// Kernel 3: masked attention
// ---------------------------------------------------------------------------
#define ATTN_SMEM ((2 * 128 * 64 + 128 * 129) * 4)

__global__ __launch_bounds__(128) void attn_kernel(
    const float* __restrict__ Q, const float* __restrict__ K,
    const float* __restrict__ V, float* __restrict__ O)
{
    extern __shared__ float sm[];
    float* Ksh = sm;
    float* Vsh = sm + 128 * 64;
    float* Ssh = sm + 2 * 128 * 64;

    const int g = blockIdx.x, h = blockIdx.y;
    const int tid = threadIdx.x;
    const int rowbase = g * NITEM;
    const int hc = h * 64;

    for (int idx = tid; idx < 128 * 64; idx += 128) {
        int i = idx >> 6, e = idx & 63;
        Ksh[idx] = K[(rowbase + i) * 128 + hc + e];
        Vsh[idx] = V[(rowbase + i) * 128 + hc + e];
    }
    __syncthreads();

    float4 q[16];
    const float4* qg = (const float4*)&Q[(rowbase + tid) * 128 + hc];
    #pragma unroll
    for (int i = 0; i < 16; i++) q[i] = qg[i];

    float* srow = &Ssh[tid * 129];
    float m = -3.4e38f;
    for (int j = 0; j < 128; j++) {
        const float4* kr = (const float4*)&Ksh[j * 64];
        float d0 = 0.f, d1 = 0.f, d2 = 0.f, d3 = 0.f;
        #pragma unroll
        for (int i = 0; i < 16; i += 4) {
            float4 k0 = kr[i], k1 = kr[i+1], k2 = kr[i+2], k3 = kr[i+3];
            d0 += q[i  ].x*k0.x + q[i  ].y*k0.y + q[i  ].z*k0.z + q[i  ].w*k0.w;
            d1 += q[i+1].x*k1.x + q[i+1].y*k1.y + q[i+1].z*k1.z + q[i+1].w*k1.w;
            d2 += q[i+2].x*k2.x + q[i+2].y*k2.y + q[i+2].z*k2.z + q[i+2].w*k2.w;
            d3 += q[i+3].x*k3.x + q[i+3].y*k3.y + q[i+3].z*k3.z + q[i+3].w*k3.w;
        }
        float s = (d0 + d1 + d2 + d3) * 0.125f;
        srow[j] = s;
        m = fmaxf(m, s);
    }

    float den = 1e-10f;
    for (int j = 0; j < 128; j++) {
        float s = srow[j];
        float p = (s != 0.0f) ? expf(s - m) : 0.0f;
        srow[j] = p;
        den += p;
    }
    const float invd = 1.0f / den;

    float4 acc[16];
    #pragma unroll
    for (int i = 0; i < 16; i++) acc[i] = make_float4(0.f, 0.f, 0.f, 0.f);
    for (int j = 0; j < 128; j++) {
        float p = srow[j];
        if (p == 0.0f) continue;
        const float4* vr = (const float4*)&Vsh[j * 64];
        #pragma unroll
        for (int i = 0; i < 16; i++) {
            float4 v = vr[i];
            acc[i].x = fmaf(p, v.x, acc[i].x);
            acc[i].y = fmaf(p, v.y, acc[i].y);
            acc[i].z = fmaf(p, v.z, acc[i].z);
            acc[i].w = fmaf(p, v.w, acc[i].w);
        }
    }

    float4* og = (float4*)&O[(rowbase + tid) * 128 + hc];
    #pragma unroll
    for (int i = 0; i < 16; i++)
        og[i] = make_float4(acc[i].x * invd, acc[i].y * invd,
                            acc[i].z * invd, acc[i].w * invd);
}

// ---------------------------------------------------------------------------
// Kernel 4: fused cross-set score on tf32 tensor cores (mma.sync.m16n8k8).
// One block (256 thr = 8 warps) per (a,b) pair. Per head: load 128x64 tf32
// tiles of Xp_a / Yp_b into smem, compute S = X @ Y^T with warp-level MMA
// (warp tile 32x64 = 2x8 fragments), then leaky-sum the accumulator
// registers (epilogue is layout-agnostic: each C elem appears exactly once).
// ---------------------------------------------------------------------------
#define XPITCH 68                          // 64 + 4 pad: rows 4 banks apart
#define CROSS_SMEM (2 * 128 * XPITCH * 4)  // 69632 B -> 3 blocks/SM

__device__ __forceinline__ unsigned f2tf32(float x) {
    unsigned r;
    asm("cvt.rna.tf32.f32 %0, %1;" : "=r"(r) : "f"(x));
    return r;
}

__global__ __launch_bounds__(256) void cross_tc_kernel(
    const float* __restrict__ P, const int* __restrict__ xsz,
    const float* __restrict__ Wc2, float* __restrict__ out)
{
    extern __shared__ unsigned smu[];
    unsigned* Xs = smu;                  // [128][XPITCH] tf32 bits
    unsigned* Ys = smu + 128 * XPITCH;
    __shared__ float red[16];

    const int b = blockIdx.x, a = blockIdx.y;
    const int tid  = threadIdx.x;
    const int lane = tid & 31, w = tid >> 5;
    const int gi = lane >> 2, ti = lane & 3;       // fragment group/thread idx
    const int r0 = (w & 3) * 32, c0 = (w >> 2) * 64;

    const float* xp = P + (size_t)a * NITEM * 128;
    const float* yp = P + (size_t)(ROWS_ONE + b * NITEM) * 128;

    float hsum[2];
    #pragma unroll
    for (int h = 0; h < 2; h++) {
        if (h) __syncthreads();            // all reads of prev tiles done
        // ---- load + tf32-round this head's 128x64 tiles ----
        for (int idx = tid; idx < 128 * 16; idx += 256) {
            int row = idx >> 4, c4 = (idx & 15) << 2;
            float4 xv = *(const float4*)&xp[row * 128 + h * 64 + c4];
            float4 yv = *(const float4*)&yp[row * 128 + h * 64 + c4];
            unsigned* xd = Xs + row * XPITCH + c4;
            unsigned* yd = Ys + row * XPITCH + c4;
            xd[0] = f2tf32(xv.x); xd[1] = f2tf32(xv.y);
            xd[2] = f2tf32(xv.z); xd[3] = f2tf32(xv.w);
            yd[0] = f2tf32(yv.x); yd[1] = f2tf32(yv.y);
            yd[2] = f2tf32(yv.z); yd[3] = f2tf32(yv.w);
        }
        __syncthreads();

        // ---- 32x64 warp tile: acc[m(2)][n(8)][4] ----
        float acc[64];
        #pragma unroll
        for (int i = 0; i < 64; i++) acc[i] = 0.f;

        #pragma unroll
        for (int k0 = 0; k0 < 64; k0 += 8) {
            unsigned af[2][4];
            #pragma unroll
            for (int m = 0; m < 2; m++) {
                const unsigned* ab = Xs + (r0 + m * 16 + gi) * XPITCH + k0 + ti;
                af[m][0] = ab[0];
                af[m][1] = ab[8 * XPITCH];
                af[m][2] = ab[4];
                af[m][3] = ab[8 * XPITCH + 4];
            }
            #pragma unroll
            for (int n = 0; n < 8; n++) {
                const unsigned* bb = Ys + (c0 + n * 8 + gi) * XPITCH + k0 + ti;
                unsigned b0 = bb[0], b1 = bb[4];
                #pragma unroll
                for (int m = 0; m < 2; m++) {
                    float* c = &acc[m * 32 + n * 4];
                    asm volatile(
                        "mma.sync.aligned.m16n8k8.row.col.f32.tf32.tf32.f32 "
                        "{%0,%1,%2,%3}, {%4,%5,%6,%7}, {%8,%9}, {%0,%1,%2,%3};"
                        : "+f"(c[0]), "+f"(c[1]), "+f"(c[2]), "+f"(c[3])
                        : "r"(af[m][0]), "r"(af[m][1]), "r"(af[m][2]), "r"(af[m][3]),
                          "r"(b0), "r"(b1));
                }
            }
        }

        // ---- leaky-relu sum over this thread's accumulators ----
        float s = 0.f;
        #pragma unroll
        for (int i = 0; i < 64; i++) {
            float v = acc[i];
            s += (v > 0.f) ? v : 0.3f * v;
        }
        hsum[h] = s;
    }

    // ---- block reduction ----
    float s0 = hsum[0], s1 = hsum[1];
    #pragma unroll
    for (int o = 16; o > 0; o >>= 1) {
        s0 += __shfl_xor_sync(0xffffffffu, s0, o);
        s1 += __shfl_xor_sync(0xffffffffu, s1, o);
    }
    if (lane == 0) { red[w] = s0; red[8 + w] = s1; }
    __syncthreads();
    if (tid == 0) {
        float S0 = 0.f, S1 = 0.f;
        #pragma unroll
        for (int i = 0; i < 8; i++) { S0 += red[i]; S1 += red[8 + i]; }
        // leaky(s)/8 (scale) / nItem[b](= x_size[b], reference quirk) / 128
        float scale = 1.0f / (8.0f * (float)xsz[b] * 128.0f);
        out[a * NSET + b] = (S0 * Wc2[0] + S1 * Wc2[1]) * scale;
    }
}

// ---------------------------------------------------------------------------
// Launch
// ---------------------------------------------------------------------------
extern "C" void kernel_launch(void* const* d_in, const int* in_sizes, int n_in,
                              void* d_out, int out_size)
{
    const float* x    = (const float*)d_in[0];
    const float* y    = (const float*)d_in[1];
    const float* Wq   = (const float*)d_in[2];
    const float* Wk   = (const float*)d_in[3];
    const float* Wv   = (const float*)d_in[4];
    const float* Wh   = (const float*)d_in[5];
    const float* Wc   = (const float*)d_in[6];
    const float* Wc2  = (const float*)d_in[7];
    const int*   xsz  = (const int*)d_in[8];
    const int*   ysz  = (const int*)d_in[9];
    float* out = (float*)d_out;

    float *pXYN, *pQ, *pK, *pV, *pA, *pH, *pP;
    cudaGetSymbolAddress((void**)&pXYN, g_xyn);
    cudaGetSymbolAddress((void**)&pQ,   g_Q);
    cudaGetSymbolAddress((void**)&pK,   g_K);
    cudaGetSymbolAddress((void**)&pV,   g_V);
    cudaGetSymbolAddress((void**)&pA,   g_att);
    cudaGetSymbolAddress((void**)&pH,   g_h);
    cudaGetSymbolAddress((void**)&pP,   g_p);

    cudaFuncSetAttribute(attn_kernel,     cudaFuncAttributeMaxDynamicSharedMemorySize, ATTN_SMEM);
    cudaFuncSetAttribute(cross_tc_kernel, cudaFuncAttributeMaxDynamicSharedMemorySize, CROSS_SMEM);

    setnorm_kernel<<<NSET, 256>>>(x, xsz, pXYN);
    setnorm_kernel<<<NSET, 256>>>(y, ysz, pXYN + (size_t)ROWS_ONE * 64);

    sgemm_kernel<<<dim3(2, ROWS_ALL / 64), 256>>>(pXYN, Wq, pQ, ROWS_ALL, 128, 64);
    sgemm_kernel<<<dim3(2, ROWS_ALL / 64), 256>>>(pXYN, Wk, pK, ROWS_ALL, 128, 64);
    sgemm_kernel<<<dim3(2, ROWS_ALL / 64), 256>>>(pXYN, Wv, pV, ROWS_ALL, 128, 64);

    attn_kernel<<<dim3(2 * NSET, 2), 128, ATTN_SMEM>>>(pQ, pK, pV, pA);

    sgemm_kernel<<<dim3(1, ROWS_ALL / 64), 256>>>(pA, Wh, pH, ROWS_ALL, 64, 128);
    sgemm_kernel<<<dim3(2, ROWS_ALL / 64), 256>>>(pH, Wc, pP, ROWS_ALL, 128, 64);

    cross_tc_kernel<<<dim3(NSET, NSET), 256, CROSS_SMEM>>>(pP, xsz, Wc2, out);
}

// round 4
// speedup vs baseline: 2.7069x; 1.1966x over previous
#include <cuda_runtime.h>
#include <cuda_bf16.h>
#include <math.h>

// ---------------------------------------------------------------------------
//   x,y: [64,128,64], HEADS=2, HS=64, LEAKY=0.3
//   set_norm -> fused QKV proj -> masked attention -> att@(Wh@Wc) [bf16 out]
//   -> bf16 tensor-core cross-set bilinear leaky score -> Wc2
// ---------------------------------------------------------------------------

#define NSET   64
#define NITEM  128
#define DFEAT  64
#define ROWS_ONE (NSET * NITEM)        // 8192
#define ROWS_ALL (2 * ROWS_ONE)        // 16384

__device__ float g_xyn [ROWS_ALL * 64];
__device__ float g_Q   [ROWS_ALL * 128];
__device__ float g_K   [ROWS_ALL * 128];
__device__ float g_V   [ROWS_ALL * 128];
__device__ float g_att [ROWS_ALL * 128];
__device__ float g_wf  [128 * 128];                 // Wh @ Wc
__device__ __nv_bfloat16 g_pb [ROWS_ALL * 128];     // P in bf16

// ---------------------------------------------------------------------------
// Kernel 1: masked set normalization
// ---------------------------------------------------------------------------
__global__ __launch_bounds__(256) void setnorm_kernel(
    const float* __restrict__ X, const int* __restrict__ sz, float* __restrict__ O)
{
    const int n   = blockIdx.x;
    const int tid = threadIdx.x;
    const float* xb = X + n * (NITEM * DFEAT);
    float*       ob = O + n * (NITEM * DFEAT);

    __shared__ float rmask[NITEM];
    __shared__ float red[256];
    __shared__ float s_mean, s_inv;

    if (tid < NITEM) {
        float s = 0.f;
        #pragma unroll
        for (int e = 0; e < DFEAT; e++) s += xb[tid * DFEAT + e];
        rmask[tid] = (s != 0.0f) ? 1.0f : 0.0f;
    }

    float tot = 0.f;
    for (int idx = tid; idx < NITEM * DFEAT; idx += 256) tot += xb[idx];
    red[tid] = tot; __syncthreads();
    for (int s = 128; s > 0; s >>= 1) {
        if (tid < s) red[tid] += red[tid + s];
        __syncthreads();
    }
    const float denom = (float)sz[n] * (float)DFEAT;
    if (tid == 0) s_mean = red[0] / denom;
    __syncthreads();
    const float mean = s_mean;

    float ss = 0.f;
    for (int idx = tid; idx < NITEM * DFEAT; idx += 256) {
        float d = xb[idx] - mean;
        ss += d * d * rmask[idx >> 6];
    }
    __syncthreads();
    red[tid] = ss; __syncthreads();
    for (int s = 128; s > 0; s >>= 1) {
        if (tid < s) red[tid] += red[tid + s];
        __syncthreads();
    }
    if (tid == 0) s_inv = 1.0f / (sqrtf(red[0] / denom) + 1e-8f);
    __syncthreads();
    const float inv = s_inv;

    for (int idx = tid; idx < NITEM * DFEAT; idx += 256)
        ob[idx] = (xb[idx] - mean) * inv * rmask[idx >> 6];
}

// ---------------------------------------------------------------------------
// Kernel 2a: generic SGEMM (fp32 out)  C[M,N] = A[M,K] @ B[K,N]
// ---------------------------------------------------------------------------
__global__ __launch_bounds__(256) void sgemm_kernel(
    const float* __restrict__ A, const float* __restrict__ B,
    float* __restrict__ C, int M, int N, int K)
{
    __shared__ float As[16][65];
    __shared__ float Bs[16][65];
    const int bx = blockIdx.x, by = blockIdx.y;
    const int tid = threadIdx.x;
    const int tx = tid & 15, ty = tid >> 4;

    float acc[4][4] = {};
    for (int k0 = 0; k0 < K; k0 += 16) {
        #pragma unroll
        for (int i = tid; i < 64 * 16; i += 256) {
            int r = i >> 4, kk = i & 15;
            As[kk][r] = A[(by * 64 + r) * K + k0 + kk];
        }
        #pragma unroll
        for (int i = tid; i < 16 * 64; i += 256) {
            int kk = i >> 6, c = i & 63;
            Bs[kk][c] = B[(k0 + kk) * N + bx * 64 + c];
        }
        __syncthreads();
        #pragma unroll
        for (int kk = 0; kk < 16; kk++) {
            float a[4], b[4];
            #pragma unroll
            for (int i = 0; i < 4; i++) a[i] = As[kk][ty * 4 + i];
            #pragma unroll
            for (int j = 0; j < 4; j++) b[j] = Bs[kk][tx * 4 + j];
            #pragma unroll
            for (int i = 0; i < 4; i++)
                #pragma unroll
                for (int j = 0; j < 4; j++)
                    acc[i][j] = fmaf(a[i], b[j], acc[i][j]);
        }
        __syncthreads();
    }
    #pragma unroll
    for (int i = 0; i < 4; i++)
        #pragma unroll
        for (int j = 0; j < 4; j++)
            C[(by * 64 + ty * 4 + i) * N + bx * 64 + tx * 4 + j] = acc[i][j];
}

// ---------------------------------------------------------------------------
// Kernel 2b: fused QKV projection. grid (6, 256); bx>>1 selects W/out.
// C[:,bx64] = A[16384,64] @ W[64,128]
// ---------------------------------------------------------------------------
__global__ __launch_bounds__(256) void qkv_kernel(
    const float* __restrict__ A,
    const float* __restrict__ Wq, const float* __restrict__ Wk,
    const float* __restrict__ Wv,
    float* __restrict__ Q, float* __restrict__ K_, float* __restrict__ V)
{
    __shared__ float As[16][65];
    __shared__ float Bs[16][65];
    const int bx = blockIdx.x, by = blockIdx.y;
    const int sel = bx >> 1, bxx = bx & 1;
    const float* B = (sel == 0) ? Wq : (sel == 1) ? Wk : Wv;
    float*       C = (sel == 0) ? Q  : (sel == 1) ? K_ : V;
    const int tid = threadIdx.x;
    const int tx = tid & 15, ty = tid >> 4;

    float acc[4][4] = {};
    #pragma unroll
    for (int k0 = 0; k0 < 64; k0 += 16) {
        #pragma unroll
        for (int i = tid; i < 64 * 16; i += 256) {
            int r = i >> 4, kk = i & 15;
            As[kk][r] = A[(by * 64 + r) * 64 + k0 + kk];
        }
        #pragma unroll
        for (int i = tid; i < 16 * 64; i += 256) {
            int kk = i >> 6, c = i & 63;
            Bs[kk][c] = B[(k0 + kk) * 128 + bxx * 64 + c];
        }
        __syncthreads();
        #pragma unroll
        for (int kk = 0; kk < 16; kk++) {
            float a[4], b[4];
            #pragma unroll
            for (int i = 0; i < 4; i++) a[i] = As[kk][ty * 4 + i];
            #pragma unroll
            for (int j = 0; j < 4; j++) b[j] = Bs[kk][tx * 4 + j];
            #pragma unroll
            for (int i = 0; i < 4; i++)
                #pragma unroll
                for (int j = 0; j < 4; j++)
                    acc[i][j] = fmaf(a[i], b[j], acc[i][j]);
        }
        __syncthreads();
    }
    #pragma unroll
    for (int i = 0; i < 4; i++)
        #pragma unroll
        for (int j = 0; j < 4; j++)
            C[(by * 64 + ty * 4 + i) * 128 + bxx * 64 + tx * 4 + j] = acc[i][j];
}

// ---------------------------------------------------------------------------
// Kernel 2c: projection with bf16 output.  P[M,128] = A[M,128] @ Wf[128,128]
// ---------------------------------------------------------------------------
__global__ __launch_bounds__(256) void proj_bf16_kernel(
    const float* __restrict__ A, const float* __restrict__ B,
    __nv_bfloat16* __restrict__ C)
{
    __shared__ float As[16][65];
    __shared__ float Bs[16][65];
    const int bx = blockIdx.x, by = blockIdx.y;
    const int tid = threadIdx.x;
    const int tx = tid & 15, ty = tid >> 4;

    float acc[4][4] = {};
    #pragma unroll
    for (int k0 = 0; k0 < 128; k0 += 16) {
        #pragma unroll
        for (int i = tid; i < 64 * 16; i += 256) {
            int r = i >> 4, kk = i & 15;
            As[kk][r] = A[(by * 64 + r) * 128 + k0 + kk];
        }
        #pragma unroll
        for (int i = tid; i < 16 * 64; i += 256) {
            int kk = i >> 6, c = i & 63;
            Bs[kk][c] = B[(k0 + kk) * 128 + bx * 64 + c];
        }
        __syncthreads();
        #pragma unroll
        for (int kk = 0; kk < 16; kk++) {
            float a[4], b[4];
            #pragma unroll
            for (int i = 0; i < 4; i++) a[i] = As[kk][ty * 4 + i];
            #pragma unroll
            for (int j = 0; j < 4; j++) b[j] = Bs[kk][tx * 4 + j];
            #pragma unroll
            for (int i = 0; i < 4; i++)
                #pragma unroll
                for (int j = 0; j < 4; j++)
                    acc[i][j] = fmaf(a[i], b[j], acc[i][j]);
        }
        __syncthreads();
    }
    #pragma unroll
    for (int i = 0; i < 4; i++)
        #pragma unroll
        for (int j = 0; j < 4; j++)
            C[(by * 64 + ty * 4 + i) * 128 + bx * 64 + tx * 4 + j] =
                __float2bfloat16(acc[i][j]);
}

// ---------------------------------------------------------------------------
// Kernel 3: masked attention (unchanged)
// ---------------------------------------------------------------------------
#define ATTN_SMEM ((2 * 128 * 64 + 128 * 129) * 4)

__global__ __launch_bounds__(128) void attn_kernel(
    const float* __restrict__ Q, const float* __restrict__ K,
    const float* __restrict__ V, float* __restrict__ O)
{
    extern __shared__ float sm[];
    float* Ksh = sm;
    float* Vsh = sm + 128 * 64;
    float* Ssh = sm + 2 * 128 * 64;

    const int g = blockIdx.x, h = blockIdx.y;
    const int tid = threadIdx.x;
    const int rowbase = g * NITEM;
    const int hc = h * 64;

    for (int idx = tid; idx < 128 * 64; idx += 128) {
        int i = idx >> 6, e = idx & 63;
        Ksh[idx] = K[(rowbase + i) * 128 + hc + e];
        Vsh[idx] = V[(rowbase + i) * 128 + hc + e];
    }
    __syncthreads();

    float4 q[16];
    const float4* qg = (const float4*)&Q[(rowbase + tid) * 128 + hc];
    #pragma unroll
    for (int i = 0; i < 16; i++) q[i] = qg[i];

    float* srow = &Ssh[tid * 129];
    float m = -3.4e38f;
    for (int j = 0; j < 128; j++) {
        const float4* kr = (const float4*)&Ksh[j * 64];
        float d0 = 0.f, d1 = 0.f, d2 = 0.f, d3 = 0.f;
        #pragma unroll
        for (int i = 0; i < 16; i += 4) {
            float4 k0 = kr[i], k1 = kr[i+1], k2 = kr[i+2], k3 = kr[i+3];
            d0 += q[i  ].x*k0.x + q[i  ].y*k0.y + q[i  ].z*k0.z + q[i  ].w*k0.w;
            d1 += q[i+1].x*k1.x + q[i+1].y*k1.y + q[i+1].z*k1.z + q[i+1].w*k1.w;
            d2 += q[i+2].x*k2.x + q[i+2].y*k2.y + q[i+2].z*k2.z + q[i+2].w*k2.w;
            d3 += q[i+3].x*k3.x + q[i+3].y*k3.y + q[i+3].z*k3.z + q[i+3].w*k3.w;
        }
        float s = (d0 + d1 + d2 + d3) * 0.125f;
        srow[j] = s;
        m = fmaxf(m, s);
    }

    float den = 1e-10f;
    for (int j = 0; j < 128; j++) {
        float s = srow[j];
        float p = (s != 0.0f) ? expf(s - m) : 0.0f;
        srow[j] = p;
        den += p;
    }
    const float invd = 1.0f / den;

    float4 acc[16];
    #pragma unroll
    for (int i = 0; i < 16; i++) acc[i] = make_float4(0.f, 0.f, 0.f, 0.f);
    for (int j = 0; j < 128; j++) {
        float p = srow[j];
        if (p == 0.0f) continue;
        const float4* vr = (const float4*)&Vsh[j * 64];
        #pragma unroll
        for (int i = 0; i < 16; i++) {
            float4 v = vr[i];
            acc[i].x = fmaf(p, v.x, acc[i].x);
            acc[i].y = fmaf(p, v.y, acc[i].y);
            acc[i].z = fmaf(p, v.z, acc[i].z);
            acc[i].w = fmaf(p, v.w, acc[i].w);
        }
    }

    float4* og = (float4*)&O[(rowbase + tid) * 128 + hc];
    #pragma unroll
    for (int i = 0; i < 16; i++)
        og[i] = make_float4(acc[i].x * invd, acc[i].y * invd,
                            acc[i].z * invd, acc[i].w * invd);
}

// ---------------------------------------------------------------------------
// Kernel 4: fused cross-set score on bf16 tensor cores (mma.sync.m16n8k16).
// One block (256 thr = 8 warps) per (a,b). Tiles stored as 32-bit words
// (2 bf16 each), row pitch 68 words -> bank = (4*gi + ti) conflict-free.
// Epilogue leaky-sums accumulator regs (layout-agnostic).
// ---------------------------------------------------------------------------
#define BPW 68                               // words per tile row (64 + 4 pad)
#define CROSS_SMEM (2 * 128 * BPW * 4)       // 69632 B

__global__ __launch_bounds__(256) void cross_bf16_kernel(
    const __nv_bfloat16* __restrict__ P, const int* __restrict__ xsz,
    const float* __restrict__ Wc2, float* __restrict__ out)
{
    extern __shared__ unsigned smu[];
    unsigned* Xs = smu;                    // [128][BPW] packed bf16x2
    unsigned* Ys = smu + 128 * BPW;
    __shared__ float red[16];

    const int b = blockIdx.x, a = blockIdx.y;
    const int tid  = threadIdx.x;
    const int lane = tid & 31, w = tid >> 5;
    const int gi = lane >> 2, ti = lane & 3;
    const int r0 = (w & 3) * 32, c0 = (w >> 2) * 64;

    const __nv_bfloat16* xp = P + (size_t)a * NITEM * 128;
    const __nv_bfloat16* yp = P + (size_t)(ROWS_ONE + b * NITEM) * 128;

    // ---- load both full 128x128 bf16 tiles (one shot, both heads) ----
    for (int idx = tid; idx < 128 * 16; idx += 256) {
        int row = idx >> 4, w4 = (idx & 15) << 2;      // 4 words = 8 bf16
        uint4 xv = *(const uint4*)(xp + row * 128 + (w4 << 1));
        uint4 yv = *(const uint4*)(yp + row * 128 + (w4 << 1));
        *(uint4*)(Xs + row * BPW + w4) = xv;
        *(uint4*)(Ys + row * BPW + w4) = yv;
    }
    __syncthreads();

    float hsum[2];
    #pragma unroll
    for (int h = 0; h < 2; h++) {
        const int hw = h * 32;                         // head col offset, words
        float acc[64];
        #pragma unroll
        for (int i = 0; i < 64; i++) acc[i] = 0.f;

        #pragma unroll
        for (int ks = 0; ks < 4; ks++) {               // k-step = 16 bf16 = 8 words
            const int kw = hw + ks * 8;
            unsigned af[2][4];
            #pragma unroll
            for (int m = 0; m < 2; m++) {
                const unsigned* ab = Xs + (r0 + m * 16 + gi) * BPW + kw + ti;
                af[m][0] = ab[0];
                af[m][1] = ab[8 * BPW];
                af[m][2] = ab[4];
                af[m][3] = ab[8 * BPW + 4];
            }
            #pragma unroll
            for (int n = 0; n < 8; n++) {
                const unsigned* bb = Ys + (c0 + n * 8 + gi) * BPW + kw + ti;
                unsigned b0 = bb[0], b1 = bb[4];
                #pragma unroll
                for (int m = 0; m < 2; m++) {
                    float* c = &acc[m * 32 + n * 4];
                    asm volatile(
                        "mma.sync.aligned.m16n8k16.row.col.f32.bf16.bf16.f32 "
                        "{%0,%1,%2,%3}, {%4,%5,%6,%7}, {%8,%9}, {%0,%1,%2,%3};"
                        : "+f"(c[0]), "+f"(c[1]), "+f"(c[2]), "+f"(c[3])
                        : "r"(af[m][0]), "r"(af[m][1]), "r"(af[m][2]), "r"(af[m][3]),
                          "r"(b0), "r"(b1));
                }
            }
        }

        float s = 0.f;
        #pragma unroll
        for (int i = 0; i < 64; i++) {
            float v = acc[i];
            s += (v > 0.f) ? v : 0.3f * v;
        }
        hsum[h] = s;
    }

    float s0 = hsum[0], s1 = hsum[1];
    #pragma unroll
    for (int o = 16; o > 0; o >>= 1) {
        s0 += __shfl_xor_sync(0xffffffffu, s0, o);
        s1 += __shfl_xor_sync(0xffffffffu, s1, o);
    }
    if (lane == 0) { red[w] = s0; red[8 + w] = s1; }
    __syncthreads();
    if (tid == 0) {
        float S0 = 0.f, S1 = 0.f;
        #pragma unroll
        for (int i = 0; i < 8; i++) { S0 += red[i]; S1 += red[8 + i]; }
        float scale = 1.0f / (8.0f * (float)xsz[b] * 128.0f);
        out[a * NSET + b] = (S0 * Wc2[0] + S1 * Wc2[1]) * scale;
    }
}

// ---------------------------------------------------------------------------
// Launch
// ---------------------------------------------------------------------------
extern "C" void kernel_launch(void* const* d_in, const int* in_sizes, int n_in,
                              void* d_out, int out_size)
{
    const float* x    = (const float*)d_in[0];
    const float* y    = (const float*)d_in[1];
    const float* Wq   = (const float*)d_in[2];
    const float* Wk   = (const float*)d_in[3];
    const float* Wv   = (const float*)d_in[4];
    const float* Wh   = (const float*)d_in[5];
    const float* Wc   = (const float*)d_in[6];
    const float* Wc2  = (const float*)d_in[7];
    const int*   xsz  = (const int*)d_in[8];
    const int*   ysz  = (const int*)d_in[9];
    float* out = (float*)d_out;

    float *pXYN, *pQ, *pK, *pV, *pA, *pWf;
    __nv_bfloat16* pPb;
    cudaGetSymbolAddress((void**)&pXYN, g_xyn);
    cudaGetSymbolAddress((void**)&pQ,   g_Q);
    cudaGetSymbolAddress((void**)&pK,   g_K);
    cudaGetSymbolAddress((void**)&pV,   g_V);
    cudaGetSymbolAddress((void**)&pA,   g_att);
    cudaGetSymbolAddress((void**)&pWf,  g_wf);
    cudaGetSymbolAddress((void**)&pPb,  g_pb);

    cudaFuncSetAttribute(attn_kernel,       cudaFuncAttributeMaxDynamicSharedMemorySize, ATTN_SMEM);
    cudaFuncSetAttribute(cross_bf16_kernel, cudaFuncAttributeMaxDynamicSharedMemorySize, CROSS_SMEM);

    // Wf = Wh @ Wc  (independent; overlaps with setnorm)
    sgemm_kernel<<<dim3(2, 2), 256>>>(Wh, Wc, pWf, 128, 128, 64);

    setnorm_kernel<<<NSET, 256>>>(x, xsz, pXYN);
    setnorm_kernel<<<NSET, 256>>>(y, ysz, pXYN + (size_t)ROWS_ONE * 64);

    qkv_kernel<<<dim3(6, ROWS_ALL / 64), 256>>>(pXYN, Wq, Wk, Wv, pQ, pK, pV);

    attn_kernel<<<dim3(2 * NSET, 2), 128, ATTN_SMEM>>>(pQ, pK, pV, pA);

    // P = att @ Wf  (bf16 output)
    proj_bf16_kernel<<<dim3(2, ROWS_ALL / 64), 256>>>(pA, pWf, pPb);

    cross_bf16_kernel<<<dim3(NSET, NSET), 256, CROSS_SMEM>>>(pPb, xsz, Wc2, out);
}

// round 5
// speedup vs baseline: 3.1499x; 1.1637x over previous
#include <cuda_runtime.h>
#include <cuda_bf16.h>
#include <math.h>

// ---------------------------------------------------------------------------
//   x,y: [64,128,64], HEADS=2, HS=64, LEAKY=0.3
//   set_norm -> tf32-TC QKV proj -> masked attention -> tf32-TC att@(Wh@Wc)
//   [bf16 out] -> bf16-TC (ldmatrix) cross-set bilinear leaky score -> Wc2
// ---------------------------------------------------------------------------

#define NSET   64
#define NITEM  128
#define DFEAT  64
#define ROWS_ONE (NSET * NITEM)        // 8192
#define ROWS_ALL (2 * ROWS_ONE)        // 16384

__device__ float g_xyn [ROWS_ALL * 64];
__device__ float g_Q   [ROWS_ALL * 128];
__device__ float g_K   [ROWS_ALL * 128];
__device__ float g_V   [ROWS_ALL * 128];
__device__ float g_att [ROWS_ALL * 128];
__device__ float g_wf  [128 * 128];                 // Wh @ Wc
__device__ __nv_bfloat16 g_pb [ROWS_ALL * 128];     // P in bf16

__device__ __forceinline__ unsigned f2tf32(float x) {
    unsigned r;
    asm("cvt.rna.tf32.f32 %0, %1;" : "=r"(r) : "f"(x));
    return r;
}
__device__ __forceinline__ unsigned smem_u32(const void* p) {
    return (unsigned)__cvta_generic_to_shared(p);
}

// ---------------------------------------------------------------------------
// Kernel 1: masked set normalization
// ---------------------------------------------------------------------------
__global__ __launch_bounds__(256) void setnorm_kernel(
    const float* __restrict__ X, const int* __restrict__ sz, float* __restrict__ O)
{
    const int n   = blockIdx.x;
    const int tid = threadIdx.x;
    const float* xb = X + n * (NITEM * DFEAT);
    float*       ob = O + n * (NITEM * DFEAT);

    __shared__ float rmask[NITEM];
    __shared__ float red[256];
    __shared__ float s_mean, s_inv;

    if (tid < NITEM) {
        float s = 0.f;
        #pragma unroll
        for (int e = 0; e < DFEAT; e++) s += xb[tid * DFEAT + e];
        rmask[tid] = (s != 0.0f) ? 1.0f : 0.0f;
    }

    float tot = 0.f;
    for (int idx = tid; idx < NITEM * DFEAT; idx += 256) tot += xb[idx];
    red[tid] = tot; __syncthreads();
    for (int s = 128; s > 0; s >>= 1) {
        if (tid < s) red[tid] += red[tid + s];
        __syncthreads();
    }
    const float denom = (float)sz[n] * (float)DFEAT;
    if (tid == 0) s_mean = red[0] / denom;
    __syncthreads();
    const float mean = s_mean;

    float ss = 0.f;
    for (int idx = tid; idx < NITEM * DFEAT; idx += 256) {
        float d = xb[idx] - mean;
        ss += d * d * rmask[idx >> 6];
    }
    __syncthreads();
    red[tid] = ss; __syncthreads();
    for (int s = 128; s > 0; s >>= 1) {
        if (tid < s) red[tid] += red[tid + s];
        __syncthreads();
    }
    if (tid == 0) s_inv = 1.0f / (sqrtf(red[0] / denom) + 1e-8f);
    __syncthreads();
    const float inv = s_inv;

    for (int idx = tid; idx < NITEM * DFEAT; idx += 256)
        ob[idx] = (xb[idx] - mean) * inv * rmask[idx >> 6];
}

// ---------------------------------------------------------------------------
// Kernel 2a: small fp32 SGEMM (for Wf = Wh @ Wc only)
// ---------------------------------------------------------------------------
__global__ __launch_bounds__(256) void sgemm_kernel(
    const float* __restrict__ A, const float* __restrict__ B,
    float* __restrict__ C, int M, int N, int K)
{
    __shared__ float As[16][65];
    __shared__ float Bs[16][65];
    const int bx = blockIdx.x, by = blockIdx.y;
    const int tid = threadIdx.x;
    const int tx = tid & 15, ty = tid >> 4;

    float acc[4][4] = {};
    for (int k0 = 0; k0 < K; k0 += 16) {
        #pragma unroll
        for (int i = tid; i < 64 * 16; i += 256) {
            int r = i >> 4, kk = i & 15;
            As[kk][r] = A[(by * 64 + r) * K + k0 + kk];
        }
        #pragma unroll
        for (int i = tid; i < 16 * 64; i += 256) {
            int kk = i >> 6, c = i & 63;
            Bs[kk][c] = B[(k0 + kk) * N + bx * 64 + c];
        }
        __syncthreads();
        #pragma unroll
        for (int kk = 0; kk < 16; kk++) {
            float a[4], b[4];
            #pragma unroll
            for (int i = 0; i < 4; i++) a[i] = As[kk][ty * 4 + i];
            #pragma unroll
            for (int j = 0; j < 4; j++) b[j] = Bs[kk][tx * 4 + j];
            #pragma unroll
            for (int i = 0; i < 4; i++)
                #pragma unroll
                for (int j = 0; j < 4; j++)
                    acc[i][j] = fmaf(a[i], b[j], acc[i][j]);
        }
        __syncthreads();
    }
    #pragma unroll
    for (int i = 0; i < 4; i++)
        #pragma unroll
        for (int j = 0; j < 4; j++)
            C[(by * 64 + ty * 4 + i) * N + bx * 64 + tx * 4 + j] = acc[i][j];
}

// ---------------------------------------------------------------------------
// Kernel 2b: QKV projection on tf32 tensor cores.
// grid (6, 128): bx>>1 selects (Wq,Q)/(Wk,K)/(Wv,V), bx&1 selects 64-col half.
// Block tile 128x64, K=64. 8 warps, warp tile 32x32 (2 m-frags x 4 n-frags).
// ---------------------------------------------------------------------------
#define QAP 68
#define QKV_SMEM ((128 + 64) * QAP * 4)      // 52224 B

__global__ __launch_bounds__(256) void qkv_tc_kernel(
    const float* __restrict__ A,
    const float* __restrict__ Wq, const float* __restrict__ Wk,
    const float* __restrict__ Wv,
    float* __restrict__ Q, float* __restrict__ Ko, float* __restrict__ V)
{
    extern __shared__ unsigned smu[];
    unsigned* As = smu;                  // [128][QAP] tf32, rows=m, cols=k
    unsigned* Bs = smu + 128 * QAP;      // [64][QAP]  tf32, rows=n, cols=k
    const int bx = blockIdx.x, by = blockIdx.y;
    const int sel = bx >> 1, bxx = bx & 1;
    const float* W = (sel == 0) ? Wq : (sel == 1) ? Wk : Wv;
    float*       C = (sel == 0) ? Q  : (sel == 1) ? Ko : V;
    const int tid = threadIdx.x, lane = tid & 31, w = tid >> 5;
    const int gi = lane >> 2, ti = lane & 3;
    const int r0 = (w & 3) * 32, c0 = (w >> 2) * 32;

    const float* Ab = A + (size_t)by * 128 * 64;
    for (int idx = tid; idx < 128 * 16; idx += 256) {
        int row = idx >> 4, c4 = (idx & 15) << 2;
        float4 v = *(const float4*)(Ab + row * 64 + c4);
        unsigned* d = As + row * QAP + c4;
        d[0] = f2tf32(v.x); d[1] = f2tf32(v.y);
        d[2] = f2tf32(v.z); d[3] = f2tf32(v.w);
    }
    for (int idx = tid; idx < 64 * 64; idx += 256) {
        int k = idx >> 6, n = idx & 63;
        Bs[n * QAP + k] = f2tf32(W[k * 128 + bxx * 64 + n]);
    }
    __syncthreads();

    float acc[32];
    #pragma unroll
    for (int i = 0; i < 32; i++) acc[i] = 0.f;

    #pragma unroll
    for (int k0 = 0; k0 < 64; k0 += 8) {
        unsigned af[2][4];
        #pragma unroll
        for (int m = 0; m < 2; m++) {
            const unsigned* ab = As + (r0 + m * 16 + gi) * QAP + k0 + ti;
            af[m][0] = ab[0];
            af[m][1] = ab[8 * QAP];
            af[m][2] = ab[4];
            af[m][3] = ab[8 * QAP + 4];
        }
        #pragma unroll
        for (int nf = 0; nf < 4; nf++) {
            const unsigned* bb = Bs + (c0 + nf * 8 + gi) * QAP + k0 + ti;
            unsigned b0 = bb[0], b1 = bb[4];
            #pragma unroll
            for (int m = 0; m < 2; m++) {
                float* c = &acc[(m * 4 + nf) * 4];
                asm volatile(
                    "mma.sync.aligned.m16n8k8.row.col.f32.tf32.tf32.f32 "
                    "{%0,%1,%2,%3}, {%4,%5,%6,%7}, {%8,%9}, {%0,%1,%2,%3};"
                    : "+f"(c[0]), "+f"(c[1]), "+f"(c[2]), "+f"(c[3])
                    : "r"(af[m][0]), "r"(af[m][1]), "r"(af[m][2]), "r"(af[m][3]),
                      "r"(b0), "r"(b1));
            }
        }
    }

    #pragma unroll
    for (int m = 0; m < 2; m++)
        #pragma unroll
        for (int nf = 0; nf < 4; nf++) {
            const float* c = &acc[(m * 4 + nf) * 4];
            int row = by * 128 + r0 + m * 16 + gi;
            int col = bxx * 64 + c0 + nf * 8 + 2 * ti;
            C[row * 128 + col]           = c[0];
            C[row * 128 + col + 1]       = c[1];
            C[(row + 8) * 128 + col]     = c[2];
            C[(row + 8) * 128 + col + 1] = c[3];
        }
}

// ---------------------------------------------------------------------------
// Kernel 2c: P = att @ Wf on tf32 tensor cores, bf16 output.
// grid (2, 128). Block tile 128x64, K=128.
// ---------------------------------------------------------------------------
#define PAP 132
#define PROJ_SMEM ((128 + 64) * PAP * 4)     // 101376 B

__global__ __launch_bounds__(256) void proj_tc_kernel(
    const float* __restrict__ A, const float* __restrict__ B,
    __nv_bfloat16* __restrict__ C)
{
    extern __shared__ unsigned smu[];
    unsigned* As = smu;                  // [128][PAP]
    unsigned* Bs = smu + 128 * PAP;      // [64][PAP]
    const int bx = blockIdx.x, by = blockIdx.y;
    const int tid = threadIdx.x, lane = tid & 31, w = tid >> 5;
    const int gi = lane >> 2, ti = lane & 3;
    const int r0 = (w & 3) * 32, c0 = (w >> 2) * 32;

    const float* Ab = A + (size_t)by * 128 * 128;
    for (int idx = tid; idx < 128 * 32; idx += 256) {
        int row = idx >> 5, c4 = (idx & 31) << 2;
        float4 v = *(const float4*)(Ab + row * 128 + c4);
        unsigned* d = As + row * PAP + c4;
        d[0] = f2tf32(v.x); d[1] = f2tf32(v.y);
        d[2] = f2tf32(v.z); d[3] = f2tf32(v.w);
    }
    for (int idx = tid; idx < 64 * 128; idx += 256) {
        int k = idx >> 6, n = idx & 63;
        Bs[n * PAP + k] = f2tf32(B[k * 128 + bx * 64 + n]);
    }
    __syncthreads();

    float acc[32];
    #pragma unroll
    for (int i = 0; i < 32; i++) acc[i] = 0.f;

    #pragma unroll
    for (int k0 = 0; k0 < 128; k0 += 8) {
        unsigned af[2][4];
        #pragma unroll
        for (int m = 0; m < 2; m++) {
            const unsigned* ab = As + (r0 + m * 16 + gi) * PAP + k0 + ti;
            af[m][0] = ab[0];
            af[m][1] = ab[8 * PAP];
            af[m][2] = ab[4];
            af[m][3] = ab[8 * PAP + 4];
        }
        #pragma unroll
        for (int nf = 0; nf < 4; nf++) {
            const unsigned* bb = Bs + (c0 + nf * 8 + gi) * PAP + k0 + ti;
            unsigned b0 = bb[0], b1 = bb[4];
            #pragma unroll
            for (int m = 0; m < 2; m++) {
                float* c = &acc[(m * 4 + nf) * 4];
                asm volatile(
                    "mma.sync.aligned.m16n8k8.row.col.f32.tf32.tf32.f32 "
                    "{%0,%1,%2,%3}, {%4,%5,%6,%7}, {%8,%9}, {%0,%1,%2,%3};"
                    : "+f"(c[0]), "+f"(c[1]), "+f"(c[2]), "+f"(c[3])
                    : "r"(af[m][0]), "r"(af[m][1]), "r"(af[m][2]), "r"(af[m][3]),
                      "r"(b0), "r"(b1));
            }
        }
    }

    #pragma unroll
    for (int m = 0; m < 2; m++)
        #pragma unroll
        for (int nf = 0; nf < 4; nf++) {
            const float* c = &acc[(m * 4 + nf) * 4];
            int row = by * 128 + r0 + m * 16 + gi;
            int col = bx * 64 + c0 + nf * 8 + 2 * ti;
            *(__nv_bfloat162*)(C + row * 128 + col) =
                __float22bfloat162_rn(make_float2(c[0], c[1]));
            *(__nv_bfloat162*)(C + (row + 8) * 128 + col) =
                __float22bfloat162_rn(make_float2(c[2], c[3]));
        }
}

// ---------------------------------------------------------------------------
// Kernel 3: masked attention (unchanged)
// ---------------------------------------------------------------------------
#define ATTN_SMEM ((2 * 128 * 64 + 128 * 129) * 4)

__global__ __launch_bounds__(128) void attn_kernel(
    const float* __restrict__ Q, const float* __restrict__ K,
    const float* __restrict__ V, float* __restrict__ O)
{
    extern __shared__ float sm[];
    float* Ksh = sm;
    float* Vsh = sm + 128 * 64;
    float* Ssh = sm + 2 * 128 * 64;

    const int g = blockIdx.x, h = blockIdx.y;
    const int tid = threadIdx.x;
    const int rowbase = g * NITEM;
    const int hc = h * 64;

    for (int idx = tid; idx < 128 * 64; idx += 128) {
        int i = idx >> 6, e = idx & 63;
        Ksh[idx] = K[(rowbase + i) * 128 + hc + e];
        Vsh[idx] = V[(rowbase + i) * 128 + hc + e];
    }
    __syncthreads();

    float4 q[16];
    const float4* qg = (const float4*)&Q[(rowbase + tid) * 128 + hc];
    #pragma unroll
    for (int i = 0; i < 16; i++) q[i] = qg[i];

    float* srow = &Ssh[tid * 129];
    float m = -3.4e38f;
    for (int j = 0; j < 128; j++) {
        const float4* kr = (const float4*)&Ksh[j * 64];
        float d0 = 0.f, d1 = 0.f, d2 = 0.f, d3 = 0.f;
        #pragma unroll
        for (int i = 0; i < 16; i += 4) {
            float4 k0 = kr[i], k1 = kr[i+1], k2 = kr[i+2], k3 = kr[i+3];
            d0 += q[i  ].x*k0.x + q[i  ].y*k0.y + q[i  ].z*k0.z + q[i  ].w*k0.w;
            d1 += q[i+1].x*k1.x + q[i+1].y*k1.y + q[i+1].z*k1.z + q[i+1].w*k1.w;
            d2 += q[i+2].x*k2.x + q[i+2].y*k2.y + q[i+2].z*k2.z + q[i+2].w*k2.w;
            d3 += q[i+3].x*k3.x + q[i+3].y*k3.y + q[i+3].z*k3.z + q[i+3].w*k3.w;
        }
        float s = (d0 + d1 + d2 + d3) * 0.125f;
        srow[j] = s;
        m = fmaxf(m, s);
    }

    float den = 1e-10f;
    for (int j = 0; j < 128; j++) {
        float s = srow[j];
        float p = (s != 0.0f) ? expf(s - m) : 0.0f;
        srow[j] = p;
        den += p;
    }
    const float invd = 1.0f / den;

    float4 acc[16];
    #pragma unroll
    for (int i = 0; i < 16; i++) acc[i] = make_float4(0.f, 0.f, 0.f, 0.f);
    for (int j = 0; j < 128; j++) {
        float p = srow[j];
        if (p == 0.0f) continue;
        const float4* vr = (const float4*)&Vsh[j * 64];
        #pragma unroll
        for (int i = 0; i < 16; i++) {
            float4 v = vr[i];
            acc[i].x = fmaf(p, v.x, acc[i].x);
            acc[i].y = fmaf(p, v.y, acc[i].y);
            acc[i].z = fmaf(p, v.z, acc[i].z);
            acc[i].w = fmaf(p, v.w, acc[i].w);
        }
    }

    float4* og = (float4*)&O[(rowbase + tid) * 128 + hc];
    #pragma unroll
    for (int i = 0; i < 16; i++)
        og[i] = make_float4(acc[i].x * invd, acc[i].y * invd,
                            acc[i].z * invd, acc[i].w * invd);
}

// ---------------------------------------------------------------------------
// Kernel 4: fused cross-set score, bf16 m16n8k16 with ldmatrix fragment loads.
// One block (8 warps) per (a,b). Tiles [128][BPW] words (bf16x2), pitch 68
// keeps both scalar-LDS and LDSM phases conflict-free.
// ---------------------------------------------------------------------------
#define BPW 68
#define CROSS_SMEM (2 * 128 * BPW * 4)       // 69632 B

__global__ __launch_bounds__(256) void cross_bf16_kernel(
    const __nv_bfloat16* __restrict__ P, const int* __restrict__ xsz,
    const float* __restrict__ Wc2, float* __restrict__ out)
{
    extern __shared__ unsigned smu[];
    unsigned* Xs = smu;                    // [128][BPW] packed bf16x2
    unsigned* Ys = smu + 128 * BPW;
    __shared__ float red[16];

    const int b = blockIdx.x, a = blockIdx.y;
    const int tid  = threadIdx.x;
    const int lane = tid & 31, w = tid >> 5;
    const int r0 = (w & 3) * 32, c0 = (w >> 2) * 64;
    const int lrow = lane & 15;            // ldmatrix row within 16
    const int lhi  = lane >> 4;            // 0/1 -> +16B column group

    const __nv_bfloat16* xp = P + (size_t)a * NITEM * 128;
    const __nv_bfloat16* yp = P + (size_t)(ROWS_ONE + b * NITEM) * 128;

    for (int idx = tid; idx < 128 * 16; idx += 256) {
        int row = idx >> 4, w4 = (idx & 15) << 2;
        uint4 xv = *(const uint4*)(xp + row * 128 + (w4 << 1));
        uint4 yv = *(const uint4*)(yp + row * 128 + (w4 << 1));
        *(uint4*)(Xs + row * BPW + w4) = xv;
        *(uint4*)(Ys + row * BPW + w4) = yv;
    }
    __syncthreads();

    const unsigned xbase = smem_u32(Xs);
    const unsigned ybase = smem_u32(Ys);

    float hsum[2];
    #pragma unroll
    for (int h = 0; h < 2; h++) {
        const int hw = h * 32;
        float acc[64];
        #pragma unroll
        for (int i = 0; i < 64; i++) acc[i] = 0.f;

        #pragma unroll
        for (int ks = 0; ks < 4; ks++) {
            const int kw = hw + ks * 8;
            unsigned af[2][4];
            #pragma unroll
            for (int m = 0; m < 2; m++) {
                unsigned addr = xbase +
                    ((r0 + m * 16 + lrow) * BPW + kw) * 4 + lhi * 16;
                asm volatile(
                    "ldmatrix.sync.aligned.m8n8.x4.shared.b16 {%0,%1,%2,%3}, [%4];"
                    : "=r"(af[m][0]), "=r"(af[m][1]), "=r"(af[m][2]), "=r"(af[m][3])
                    : "r"(addr));
            }
            unsigned bf[8][2];
            #pragma unroll
            for (int nn = 0; nn < 4; nn++) {
                unsigned t0, t1, t2, t3;
                unsigned addr = ybase +
                    ((c0 + nn * 16 + lrow) * BPW + kw) * 4 + lhi * 16;
                asm volatile(
                    "ldmatrix.sync.aligned.m8n8.x4.shared.b16 {%0,%1,%2,%3}, [%4];"
                    : "=r"(t0), "=r"(t1), "=r"(t2), "=r"(t3)
                    : "r"(addr));
                bf[nn * 2][0]     = t0; bf[nn * 2][1]     = t2;
                bf[nn * 2 + 1][0] = t1; bf[nn * 2 + 1][1] = t3;
            }
            #pragma unroll
            for (int n = 0; n < 8; n++)
                #pragma unroll
                for (int m = 0; m < 2; m++) {
                    float* c = &acc[m * 32 + n * 4];
                    asm volatile(
                        "mma.sync.aligned.m16n8k16.row.col.f32.bf16.bf16.f32 "
                        "{%0,%1,%2,%3}, {%4,%5,%6,%7}, {%8,%9}, {%0,%1,%2,%3};"
                        : "+f"(c[0]), "+f"(c[1]), "+f"(c[2]), "+f"(c[3])
                        : "r"(af[m][0]), "r"(af[m][1]), "r"(af[m][2]), "r"(af[m][3]),
                          "r"(bf[n][0]), "r"(bf[n][1]));
                }
        }

        float s = 0.f;
        #pragma unroll
        for (int i = 0; i < 64; i++) {
            float v = acc[i];
            s += (v > 0.f) ? v : 0.3f * v;
        }
        hsum[h] = s;
    }

    float s0 = hsum[0], s1 = hsum[1];
    #pragma unroll
    for (int o = 16; o > 0; o >>= 1) {
        s0 += __shfl_xor_sync(0xffffffffu, s0, o);
        s1 += __shfl_xor_sync(0xffffffffu, s1, o);
    }
    if (lane == 0) { red[w] = s0; red[8 + w] = s1; }
    __syncthreads();
    if (tid == 0) {
        float S0 = 0.f, S1 = 0.f;
        #pragma unroll
        for (int i = 0; i < 8; i++) { S0 += red[i]; S1 += red[8 + i]; }
        float scale = 1.0f / (8.0f * (float)xsz[b] * 128.0f);
        out[a * NSET + b] = (S0 * Wc2[0] + S1 * Wc2[1]) * scale;
    }
}

// ---------------------------------------------------------------------------
// Launch
// ---------------------------------------------------------------------------
extern "C" void kernel_launch(void* const* d_in, const int* in_sizes, int n_in,
                              void* d_out, int out_size)
{
    const float* x    = (const float*)d_in[0];
    const float* y    = (const float*)d_in[1];
    const float* Wq   = (const float*)d_in[2];
    const float* Wk   = (const float*)d_in[3];
    const float* Wv   = (const float*)d_in[4];
    const float* Wh   = (const float*)d_in[5];
    const float* Wc   = (const float*)d_in[6];
    const float* Wc2  = (const float*)d_in[7];
    const int*   xsz  = (const int*)d_in[8];
    const int*   ysz  = (const int*)d_in[9];
    float* out = (float*)d_out;

    float *pXYN, *pQ, *pK, *pV, *pA, *pWf;
    __nv_bfloat16* pPb;
    cudaGetSymbolAddress((void**)&pXYN, g_xyn);
    cudaGetSymbolAddress((void**)&pQ,   g_Q);
    cudaGetSymbolAddress((void**)&pK,   g_K);
    cudaGetSymbolAddress((void**)&pV,   g_V);
    cudaGetSymbolAddress((void**)&pA,   g_att);
    cudaGetSymbolAddress((void**)&pWf,  g_wf);
    cudaGetSymbolAddress((void**)&pPb,  g_pb);

    cudaFuncSetAttribute(attn_kernel,       cudaFuncAttributeMaxDynamicSharedMemorySize, ATTN_SMEM);
    cudaFuncSetAttribute(cross_bf16_kernel, cudaFuncAttributeMaxDynamicSharedMemorySize, CROSS_SMEM);
    cudaFuncSetAttribute(qkv_tc_kernel,     cudaFuncAttributeMaxDynamicSharedMemorySize, QKV_SMEM);
    cudaFuncSetAttribute(proj_tc_kernel,    cudaFuncAttributeMaxDynamicSharedMemorySize, PROJ_SMEM);

    // Wf = Wh @ Wc  (independent; overlaps with setnorm)
    sgemm_kernel<<<dim3(2, 2), 256>>>(Wh, Wc, pWf, 128, 128, 64);

    setnorm_kernel<<<NSET, 256>>>(x, xsz, pXYN);
    setnorm_kernel<<<NSET, 256>>>(y, ysz, pXYN + (size_t)ROWS_ONE * 64);

    qkv_tc_kernel<<<dim3(6, ROWS_ALL / 128), 256, QKV_SMEM>>>(
        pXYN, Wq, Wk, Wv, pQ, pK, pV);

    attn_kernel<<<dim3(2 * NSET, 2), 128, ATTN_SMEM>>>(pQ, pK, pV, pA);

    proj_tc_kernel<<<dim3(2, ROWS_ALL / 128), 256, PROJ_SMEM>>>(pA, pWf, pPb);

    cross_bf16_kernel<<<dim3(NSET, NSET), 256, CROSS_SMEM>>>(pPb, xsz, Wc2, out);
}

// round 8
// speedup vs baseline: 4.8317x; 1.5339x over previous
#include <cuda_runtime.h>
#include <cuda_fp16.h>
#include <math.h>

// ---------------------------------------------------------------------------
//   x,y: [64,128,64], HEADS=2, HS=64, LEAKY=0.3
//   set_norm -> merged tf32-TC QKV -> full-TC masked attention (tf32 QK^T,
//   frag softmax, fp16 PV) -> tf32-TC att@(Wh@Wc) [fp16 out]
//   -> fp16-TC (ldmatrix) cross-set bilinear leaky score -> Wc2
// ---------------------------------------------------------------------------

#define NSET   64
#define NITEM  128
#define DFEAT  64
#define ROWS_ONE (NSET * NITEM)        // 8192
#define ROWS_ALL (2 * ROWS_ONE)        // 16384

__device__ float g_xyn [ROWS_ALL * 64];
__device__ float g_Q   [ROWS_ALL * 128];
__device__ float g_K   [ROWS_ALL * 128];
__device__ float g_V   [ROWS_ALL * 128];
__device__ float g_att [ROWS_ALL * 128];
__device__ float g_wf  [128 * 128];                 // Wh @ Wc
__device__ __half g_ph [ROWS_ALL * 128];            // P in fp16

__device__ __forceinline__ unsigned f2tf32(float x) {
    unsigned r;
    asm("cvt.rna.tf32.f32 %0, %1;" : "=r"(r) : "f"(x));
    return r;
}
__device__ __forceinline__ unsigned smem_u32(const void* p) {
    return (unsigned)__cvta_generic_to_shared(p);
}
__device__ __forceinline__ unsigned pack_h16(float a, float b) {
    __half2 t = __floats2half2_rn(a, b);
    return *(unsigned*)&t;
}

// ---------------------------------------------------------------------------
// Kernel 1: masked set normalization
// ---------------------------------------------------------------------------
__global__ __launch_bounds__(256) void setnorm_kernel(
    const float* __restrict__ X, const int* __restrict__ sz, float* __restrict__ O)
{
    const int n   = blockIdx.x;
    const int tid = threadIdx.x;
    const float* xb = X + n * (NITEM * DFEAT);
    float*       ob = O + n * (NITEM * DFEAT);

    __shared__ float rmask[NITEM];
    __shared__ float red[256];
    __shared__ float s_mean, s_inv;

    if (tid < NITEM) {
        float s = 0.f;
        #pragma unroll
        for (int e = 0; e < DFEAT; e++) s += xb[tid * DFEAT + e];
        rmask[tid] = (s != 0.0f) ? 1.0f : 0.0f;
    }

    float tot = 0.f;
    for (int idx = tid; idx < NITEM * DFEAT; idx += 256) tot += xb[idx];
    red[tid] = tot; __syncthreads();
    for (int s = 128; s > 0; s >>= 1) {
        if (tid < s) red[tid] += red[tid + s];
        __syncthreads();
    }
    const float denom = (float)sz[n] * (float)DFEAT;
    if (tid == 0) s_mean = red[0] / denom;
    __syncthreads();
    const float mean = s_mean;

    float ss = 0.f;
    for (int idx = tid; idx < NITEM * DFEAT; idx += 256) {
        float d = xb[idx] - mean;
        ss += d * d * rmask[idx >> 6];
    }
    __syncthreads();
    red[tid] = ss; __syncthreads();
    for (int s = 128; s > 0; s >>= 1) {
        if (tid < s) red[tid] += red[tid + s];
        __syncthreads();
    }
    if (tid == 0) s_inv = 1.0f / (sqrtf(red[0] / denom) + 1e-8f);
    __syncthreads();
    const float inv = s_inv;

    for (int idx = tid; idx < NITEM * DFEAT; idx += 256)
        ob[idx] = (xb[idx] - mean) * inv * rmask[idx >> 6];
}

// ---------------------------------------------------------------------------
// Kernel 2a: small fp32 SGEMM (for Wf = Wh @ Wc only)
// ---------------------------------------------------------------------------
__global__ __launch_bounds__(256) void sgemm_kernel(
    const float* __restrict__ A, const float* __restrict__ B,
    float* __restrict__ C, int M, int N, int K)
{
    __shared__ float As[16][65];
    __shared__ float Bs[16][65];
    const int bx = blockIdx.x, by = blockIdx.y;
    const int tid = threadIdx.x;
    const int tx = tid & 15, ty = tid >> 4;

    float acc[4][4] = {};
    for (int k0 = 0; k0 < K; k0 += 16) {
        #pragma unroll
        for (int i = tid; i < 64 * 16; i += 256) {
            int r = i >> 4, kk = i & 15;
            As[kk][r] = A[(by * 64 + r) * K + k0 + kk];
        }
        #pragma unroll
        for (int i = tid; i < 16 * 64; i += 256) {
            int kk = i >> 6, c = i & 63;
            Bs[kk][c] = B[(k0 + kk) * N + bx * 64 + c];
        }
        __syncthreads();
        #pragma unroll
        for (int kk = 0; kk < 16; kk++) {
            float a[4], b[4];
            #pragma unroll
            for (int i = 0; i < 4; i++) a[i] = As[kk][ty * 4 + i];
            #pragma unroll
            for (int j = 0; j < 4; j++) b[j] = Bs[kk][tx * 4 + j];
            #pragma unroll
            for (int i = 0; i < 4; i++)
                #pragma unroll
                for (int j = 0; j < 4; j++)
                    acc[i][j] = fmaf(a[i], b[j], acc[i][j]);
        }
        __syncthreads();
    }
    #pragma unroll
    for (int i = 0; i < 4; i++)
        #pragma unroll
        for (int j = 0; j < 4; j++)
            C[(by * 64 + ty * 4 + i) * N + bx * 64 + tx * 4 + j] = acc[i][j];
}

// ---------------------------------------------------------------------------
// Kernel 2b: MERGED QKV on tf32 tensor cores.
// ---------------------------------------------------------------------------
#define QAP 68
#define QKV_SMEM (2 * 128 * QAP * 4)         // 69632 B

__global__ __launch_bounds__(256) void qkv_merged_kernel(
    const float* __restrict__ A,
    const float* __restrict__ Wq, const float* __restrict__ Wk,
    const float* __restrict__ Wv,
    float* __restrict__ Q, float* __restrict__ Ko, float* __restrict__ V)
{
    extern __shared__ unsigned smu[];
    unsigned* As = smu;                  // [128 m][QAP k]
    unsigned* Bs = smu + 128 * QAP;      // [128 n][QAP k]
    const int by = blockIdx.x;
    const int tid = threadIdx.x, lane = tid & 31, w = tid >> 5;
    const int gi = lane >> 2, ti = lane & 3;
    const int r0 = (w & 3) * 32, c0 = (w >> 2) * 64;

    const float* Ab = A + (size_t)by * 128 * 64;
    for (int idx = tid; idx < 128 * 16; idx += 256) {
        int row = idx >> 4, c4 = (idx & 15) << 2;
        float4 v = *(const float4*)(Ab + row * 64 + c4);
        unsigned* d = As + row * QAP + c4;
        d[0] = f2tf32(v.x); d[1] = f2tf32(v.y);
        d[2] = f2tf32(v.z); d[3] = f2tf32(v.w);
    }

    #pragma unroll
    for (int sel = 0; sel < 3; sel++) {
        const float* W = (sel == 0) ? Wq : (sel == 1) ? Wk : Wv;
        float*       C = (sel == 0) ? Q  : (sel == 1) ? Ko : V;

        __syncthreads();   // As ready (iter 0); Bs consumers done (iter>0)
        for (int idx = tid; idx < 128 * 64; idx += 256) {
            int k = idx >> 7, n = idx & 127;
            Bs[n * QAP + k] = f2tf32(W[k * 128 + n]);
        }
        __syncthreads();

        float acc[64];
        #pragma unroll
        for (int i = 0; i < 64; i++) acc[i] = 0.f;

        #pragma unroll
        for (int k0 = 0; k0 < 64; k0 += 8) {
            unsigned af[2][4];
            #pragma unroll
            for (int m = 0; m < 2; m++) {
                const unsigned* ab = As + (r0 + m * 16 + gi) * QAP + k0 + ti;
                af[m][0] = ab[0];
                af[m][1] = ab[8 * QAP];
                af[m][2] = ab[4];
                af[m][3] = ab[8 * QAP + 4];
            }
            #pragma unroll
            for (int nf = 0; nf < 8; nf++) {
                const unsigned* bb = Bs + (c0 + nf * 8 + gi) * QAP + k0 + ti;
                unsigned b0 = bb[0], b1 = bb[4];
                #pragma unroll
                for (int m = 0; m < 2; m++) {
                    float* c = &acc[(m * 8 + nf) * 4];
                    asm volatile(
                        "mma.sync.aligned.m16n8k8.row.col.f32.tf32.tf32.f32 "
                        "{%0,%1,%2,%3}, {%4,%5,%6,%7}, {%8,%9}, {%0,%1,%2,%3};"
                        : "+f"(c[0]), "+f"(c[1]), "+f"(c[2]), "+f"(c[3])
                        : "r"(af[m][0]), "r"(af[m][1]), "r"(af[m][2]), "r"(af[m][3]),
                          "r"(b0), "r"(b1));
                }
            }
        }

        #pragma unroll
        for (int m = 0; m < 2; m++)
            #pragma unroll
            for (int nf = 0; nf < 8; nf++) {
                const float* c = &acc[(m * 8 + nf) * 4];
                int row = by * 128 + r0 + m * 16 + gi;
                int col = c0 + nf * 8 + 2 * ti;
                *(float2*)(C + row * 128 + col)       = make_float2(c[0], c[1]);
                *(float2*)(C + (row + 8) * 128 + col) = make_float2(c[2], c[3]);
            }
    }
}

// ---------------------------------------------------------------------------
// Kernel 2c: P = att @ Wf on tf32 tensor cores, fp16 output.
// ---------------------------------------------------------------------------
#define PAP 132
#define PROJ_SMEM ((128 + 64) * PAP * 4)     // 101376 B

__global__ __launch_bounds__(256) void proj_tc_kernel(
    const float* __restrict__ A, const float* __restrict__ B,
    __half* __restrict__ C)
{
    extern __shared__ unsigned smu[];
    unsigned* As = smu;                  // [128][PAP]
    unsigned* Bs = smu + 128 * PAP;      // [64][PAP]
    const int bx = blockIdx.x, by = blockIdx.y;
    const int tid = threadIdx.x, lane = tid & 31, w = tid >> 5;
    const int gi = lane >> 2, ti = lane & 3;
    const int r0 = (w & 3) * 32, c0 = (w >> 2) * 32;

    const float* Ab = A + (size_t)by * 128 * 128;
    for (int idx = tid; idx < 128 * 32; idx += 256) {
        int row = idx >> 5, c4 = (idx & 31) << 2;
        float4 v = *(const float4*)(Ab + row * 128 + c4);
        unsigned* d = As + row * PAP + c4;
        d[0] = f2tf32(v.x); d[1] = f2tf32(v.y);
        d[2] = f2tf32(v.z); d[3] = f2tf32(v.w);
    }
    for (int idx = tid; idx < 64 * 128; idx += 256) {
        int k = idx >> 6, n = idx & 63;
        Bs[n * PAP + k] = f2tf32(B[k * 128 + bx * 64 + n]);
    }
    __syncthreads();

    float acc[32];
    #pragma unroll
    for (int i = 0; i < 32; i++) acc[i] = 0.f;

    #pragma unroll
    for (int k0 = 0; k0 < 128; k0 += 8) {
        unsigned af[2][4];
        #pragma unroll
        for (int m = 0; m < 2; m++) {
            const unsigned* ab = As + (r0 + m * 16 + gi) * PAP + k0 + ti;
            af[m][0] = ab[0];
            af[m][1] = ab[8 * PAP];
            af[m][2] = ab[4];
            af[m][3] = ab[8 * PAP + 4];
        }
        #pragma unroll
        for (int nf = 0; nf < 4; nf++) {
            const unsigned* bb = Bs + (c0 + nf * 8 + gi) * PAP + k0 + ti;
            unsigned b0 = bb[0], b1 = bb[4];
            #pragma unroll
            for (int m = 0; m < 2; m++) {
                float* c = &acc[(m * 4 + nf) * 4];
                asm volatile(
                    "mma.sync.aligned.m16n8k8.row.col.f32.tf32.tf32.f32 "
                    "{%0,%1,%2,%3}, {%4,%5,%6,%7}, {%8,%9}, {%0,%1,%2,%3};"
                    : "+f"(c[0]), "+f"(c[1]), "+f"(c[2]), "+f"(c[3])
                    : "r"(af[m][0]), "r"(af[m][1]), "r"(af[m][2]), "r"(af[m][3]),
                      "r"(b0), "r"(b1));
            }
        }
    }

    #pragma unroll
    for (int m = 0; m < 2; m++)
        #pragma unroll
        for (int nf = 0; nf < 4; nf++) {
            const float* c = &acc[(m * 4 + nf) * 4];
            int row = by * 128 + r0 + m * 16 + gi;
            int col = bx * 64 + c0 + nf * 8 + 2 * ti;
            *(__half2*)(C + row * 128 + col) = __floats2half2_rn(c[0], c[1]);
            *(__half2*)(C + (row + 8) * 128 + col) = __floats2half2_rn(c[2], c[3]);
        }
}

// ---------------------------------------------------------------------------
// Kernel 3: full-TC masked attention (tf32 QK^T, frag softmax, fp16 PV).
// ---------------------------------------------------------------------------
#define VP 36
#define ATTN_SMEM ((2 * 128 * QAP + 128 * VP) * 4)   // 88064 B

__global__ __launch_bounds__(128) void attn_tc_kernel(
    const float* __restrict__ Q, const float* __restrict__ K,
    const float* __restrict__ V, float* __restrict__ O)
{
    extern __shared__ unsigned smu[];
    unsigned* Qs = smu;                      // [128][QAP] tf32
    unsigned* Ks = smu + 128 * QAP;          // [128][QAP] tf32
    unsigned* Vs = smu + 2 * 128 * QAP;      // [128][VP]  half2 words

    const int g = blockIdx.x, h = blockIdx.y;
    const int tid = threadIdx.x, lane = tid & 31, w = tid >> 5;
    const int gi = lane >> 2, ti = lane & 3;
    const int r0 = w * 32;
    const int rowbase = g * NITEM, hc = h * 64;

    for (int idx = tid; idx < 128 * 16; idx += 128) {
        int row = idx >> 4, c4 = (idx & 15) << 2;
        float4 qv = *(const float4*)&Q[(rowbase + row) * 128 + hc + c4];
        float4 kv = *(const float4*)&K[(rowbase + row) * 128 + hc + c4];
        unsigned* qd = Qs + row * QAP + c4;
        unsigned* kd = Ks + row * QAP + c4;
        qd[0] = f2tf32(qv.x); qd[1] = f2tf32(qv.y);
        qd[2] = f2tf32(qv.z); qd[3] = f2tf32(qv.w);
        kd[0] = f2tf32(kv.x); kd[1] = f2tf32(kv.y);
        kd[2] = f2tf32(kv.z); kd[3] = f2tf32(kv.w);
    }
    for (int idx = tid; idx < 128 * 32; idx += 128) {
        int row = idx >> 5, c = idx & 31;
        float2 vv = *(const float2*)&V[(rowbase + row) * 128 + hc + 2 * c];
        Vs[row * VP + c] = pack_h16(vv.x, vv.y);
    }
    __syncthreads();

    // ---- S = Q @ K^T : sacc[m(2)][nf(16)][4] ----
    float sacc[2][16][4];
    #pragma unroll
    for (int m = 0; m < 2; m++)
        #pragma unroll
        for (int nf = 0; nf < 16; nf++)
            #pragma unroll
            for (int r = 0; r < 4; r++) sacc[m][nf][r] = 0.f;

    #pragma unroll
    for (int k0 = 0; k0 < 64; k0 += 8) {
        unsigned af[2][4];
        #pragma unroll
        for (int m = 0; m < 2; m++) {
            const unsigned* ab = Qs + (r0 + m * 16 + gi) * QAP + k0 + ti;
            af[m][0] = ab[0];
            af[m][1] = ab[8 * QAP];
            af[m][2] = ab[4];
            af[m][3] = ab[8 * QAP + 4];
        }
        #pragma unroll
        for (int nf = 0; nf < 16; nf++) {
            const unsigned* bb = Ks + (nf * 8 + gi) * QAP + k0 + ti;
            unsigned b0 = bb[0], b1 = bb[4];
            #pragma unroll
            for (int m = 0; m < 2; m++) {
                float* c = sacc[m][nf];
                asm volatile(
                    "mma.sync.aligned.m16n8k8.row.col.f32.tf32.tf32.f32 "
                    "{%0,%1,%2,%3}, {%4,%5,%6,%7}, {%8,%9}, {%0,%1,%2,%3};"
                    : "+f"(c[0]), "+f"(c[1]), "+f"(c[2]), "+f"(c[3])
                    : "r"(af[m][0]), "r"(af[m][1]), "r"(af[m][2]), "r"(af[m][3]),
                      "r"(b0), "r"(b1));
            }
        }
    }

    // ---- fragment softmax (mask raw!=0; scale folded into exponent) ----
    const float COEF = 0.125f * 1.44269504f;
    float invd0[2], invd1[2];
    unsigned pf[2][8][4];                    // fp16 A-frags of P

    #pragma unroll
    for (int mf = 0; mf < 2; mf++) {
        float mx0 = -3.4e38f, mx1 = -3.4e38f;
        #pragma unroll
        for (int nf = 0; nf < 16; nf++) {
            mx0 = fmaxf(mx0, fmaxf(sacc[mf][nf][0], sacc[mf][nf][1]));
            mx1 = fmaxf(mx1, fmaxf(sacc[mf][nf][2], sacc[mf][nf][3]));
        }
        #pragma unroll
        for (int o = 1; o < 4; o <<= 1) {
            mx0 = fmaxf(mx0, __shfl_xor_sync(0xffffffffu, mx0, o));
            mx1 = fmaxf(mx1, __shfl_xor_sync(0xffffffffu, mx1, o));
        }
        float d0 = 0.f, d1 = 0.f;
        #pragma unroll
        for (int nf = 0; nf < 16; nf++) {
            float raw0 = sacc[mf][nf][0], raw1 = sacc[mf][nf][1];
            float raw2 = sacc[mf][nf][2], raw3 = sacc[mf][nf][3];
            float p0 = (raw0 != 0.f) ? exp2f((raw0 - mx0) * COEF) : 0.f;
            float p1 = (raw1 != 0.f) ? exp2f((raw1 - mx0) * COEF) : 0.f;
            float p2 = (raw2 != 0.f) ? exp2f((raw2 - mx1) * COEF) : 0.f;
            float p3 = (raw3 != 0.f) ? exp2f((raw3 - mx1) * COEF) : 0.f;
            sacc[mf][nf][0] = p0; sacc[mf][nf][1] = p1;
            sacc[mf][nf][2] = p2; sacc[mf][nf][3] = p3;
            d0 += p0 + p1; d1 += p2 + p3;
        }
        #pragma unroll
        for (int o = 1; o < 4; o <<= 1) {
            d0 += __shfl_xor_sync(0xffffffffu, d0, o);
            d1 += __shfl_xor_sync(0xffffffffu, d1, o);
        }
        invd0[mf] = 1.0f / (d0 + 1e-10f);
        invd1[mf] = 1.0f / (d1 + 1e-10f);

        // C-frag -> fp16 A-frag packing (n-frag pair 2f',2f'+1 -> k-block f')
        #pragma unroll
        for (int fp = 0; fp < 8; fp++) {
            pf[mf][fp][0] = pack_h16(sacc[mf][2 * fp][0],     sacc[mf][2 * fp][1]);
            pf[mf][fp][1] = pack_h16(sacc[mf][2 * fp][2],     sacc[mf][2 * fp][3]);
            pf[mf][fp][2] = pack_h16(sacc[mf][2 * fp + 1][0], sacc[mf][2 * fp + 1][1]);
            pf[mf][fp][3] = pack_h16(sacc[mf][2 * fp + 1][2], sacc[mf][2 * fp + 1][3]);
        }
    }

    // ---- O = P @ V : oacc[m(2)][nf(8)][4] ----
    float oacc[2][8][4];
    #pragma unroll
    for (int m = 0; m < 2; m++)
        #pragma unroll
        for (int nf = 0; nf < 8; nf++)
            #pragma unroll
            for (int r = 0; r < 4; r++) oacc[m][nf][r] = 0.f;

    const unsigned vbase = smem_u32(Vs);
    #pragma unroll
    for (int kb = 0; kb < 8; kb++) {
        unsigned bfr[8][2];
        #pragma unroll
        for (int ng = 0; ng < 4; ng++) {
            unsigned t0, t1, t2, t3;
            unsigned addr = vbase +
                ((kb * 16 + (lane & 15)) * VP + ng * 8 + (lane >> 4) * 4) * 4;
            asm volatile(
                "ldmatrix.sync.aligned.m8n8.x4.trans.shared.b16 {%0,%1,%2,%3}, [%4];"
                : "=r"(t0), "=r"(t1), "=r"(t2), "=r"(t3) : "r"(addr));
            bfr[2 * ng][0]     = t0; bfr[2 * ng][1]     = t1;
            bfr[2 * ng + 1][0] = t2; bfr[2 * ng + 1][1] = t3;
        }
        #pragma unroll
        for (int nf = 0; nf < 8; nf++)
            #pragma unroll
            for (int m = 0; m < 2; m++) {
                float* c = oacc[m][nf];
                asm volatile(
                    "mma.sync.aligned.m16n8k16.row.col.f32.f16.f16.f32 "
                    "{%0,%1,%2,%3}, {%4,%5,%6,%7}, {%8,%9}, {%0,%1,%2,%3};"
                    : "+f"(c[0]), "+f"(c[1]), "+f"(c[2]), "+f"(c[3])
                    : "r"(pf[m][kb][0]), "r"(pf[m][kb][1]),
                      "r"(pf[m][kb][2]), "r"(pf[m][kb][3]),
                      "r"(bfr[nf][0]), "r"(bfr[nf][1]));
            }
    }

    #pragma unroll
    for (int m = 0; m < 2; m++)
        #pragma unroll
        for (int nf = 0; nf < 8; nf++) {
            const float* c = oacc[m][nf];
            int row = rowbase + r0 + m * 16 + gi;
            int col = hc + nf * 8 + 2 * ti;
            *(float2*)(O + row * 128 + col) =
                make_float2(c[0] * invd0[m], c[1] * invd0[m]);
            *(float2*)(O + (row + 8) * 128 + col) =
                make_float2(c[2] * invd1[m], c[3] * invd1[m]);
        }
}

// ---------------------------------------------------------------------------
// Kernel 4: fused cross-set score, fp16 m16n8k16 with ldmatrix.
// ---------------------------------------------------------------------------
#define BPW 68
#define CROSS_SMEM (2 * 128 * BPW * 4)       // 69632 B

__global__ __launch_bounds__(256) void cross_h16_kernel(
    const __half* __restrict__ P, const int* __restrict__ xsz,
    const float* __restrict__ Wc2, float* __restrict__ out)
{
    extern __shared__ unsigned smu[];
    unsigned* Xs = smu;
    unsigned* Ys = smu + 128 * BPW;
    __shared__ float red[16];

    const int b = blockIdx.x, a = blockIdx.y;
    const int tid  = threadIdx.x;
    const int lane = tid & 31, w = tid >> 5;
    const int r0 = (w & 3) * 32, c0 = (w >> 2) * 64;
    const int lrow = lane & 15;
    const int lhi  = lane >> 4;

    const __half* xp = P + (size_t)a * NITEM * 128;
    const __half* yp = P + (size_t)(ROWS_ONE + b * NITEM) * 128;

    for (int idx = tid; idx < 128 * 16; idx += 256) {
        int row = idx >> 4, w4 = (idx & 15) << 2;
        uint4 xv = *(const uint4*)(xp + row * 128 + (w4 << 1));
        uint4 yv = *(const uint4*)(yp + row * 128 + (w4 << 1));
        *(uint4*)(Xs + row * BPW + w4) = xv;
        *(uint4*)(Ys + row * BPW + w4) = yv;
    }
    __syncthreads();

    const unsigned xbase = smem_u32(Xs);
    const unsigned ybase = smem_u32(Ys);

    float hsum[2];
    #pragma unroll
    for (int h = 0; h < 2; h++) {
        const int hw = h * 32;
        float acc[64];
        #pragma unroll
        for (int i = 0; i < 64; i++) acc[i] = 0.f;

        #pragma unroll
        for (int ks = 0; ks < 4; ks++) {
            const int kw = hw + ks * 8;
            unsigned af[2][4];
            #pragma unroll
            for (int m = 0; m < 2; m++) {
                unsigned addr = xbase +
                    ((r0 + m * 16 + lrow) * BPW + kw) * 4 + lhi * 16;
                asm volatile(
                    "ldmatrix.sync.aligned.m8n8.x4.shared.b16 {%0,%1,%2,%3}, [%4];"
                    : "=r"(af[m][0]), "=r"(af[m][1]), "=r"(af[m][2]), "=r"(af[m][3])
                    : "r"(addr));
            }
            unsigned bf[8][2];
            #pragma unroll
            for (int nn = 0; nn < 4; nn++) {
                unsigned t0, t1, t2, t3;
                unsigned addr = ybase +
                    ((c0 + nn * 16 + lrow) * BPW + kw) * 4 + lhi * 16;
                asm volatile(
                    "ldmatrix.sync.aligned.m8n8.x4.shared.b16 {%0,%1,%2,%3}, [%4];"
                    : "=r"(t0), "=r"(t1), "=r"(t2), "=r"(t3)
                    : "r"(addr));
                bf[nn * 2][0]     = t0; bf[nn * 2][1]     = t2;
                bf[nn * 2 + 1][0] = t1; bf[nn * 2 + 1][1] = t3;
            }
            #pragma unroll
            for (int n = 0; n < 8; n++)
                #pragma unroll
                for (int m = 0; m < 2; m++) {
                    float* c = &acc[m * 32 + n * 4];
                    asm volatile(
                        "mma.sync.aligned.m16n8k16.row.col.f32.f16.f16.f32 "
                        "{%0,%1,%2,%3}, {%4,%5,%6,%7}, {%8,%9}, {%0,%1,%2,%3};"
                        : "+f"(c[0]), "+f"(c[1]), "+f"(c[2]), "+f"(c[3])
                        : "r"(af[m][0]), "r"(af[m][1]), "r"(af[m][2]), "r"(af[m][3]),
                          "r"(bf[n][0]), "r"(bf[n][1]));
                }
        }

        float s = 0.f;
        #pragma unroll
        for (int i = 0; i < 64; i++) {
            float v = acc[i];
            s += (v > 0.f) ? v : 0.3f * v;
        }
        hsum[h] = s;
    }

    float s0 = hsum[0], s1 = hsum[1];
    #pragma unroll
    for (int o = 16; o > 0; o >>= 1) {
        s0 += __shfl_xor_sync(0xffffffffu, s0, o);
        s1 += __shfl_xor_sync(0xffffffffu, s1, o);
    }
    if (lane == 0) { red[w] = s0; red[8 + w] = s1; }
    __syncthreads();
    if (tid == 0) {
        float S0 = 0.f, S1 = 0.f;
        #pragma unroll
        for (int i = 0; i < 8; i++) { S0 += red[i]; S1 += red[8 + i]; }
        float scale = 1.0f / (8.0f * (float)xsz[b] * 128.0f);
        out[a * NSET + b] = (S0 * Wc2[0] + S1 * Wc2[1]) * scale;
    }
}

// ---------------------------------------------------------------------------
// Launch
// ---------------------------------------------------------------------------
extern "C" void kernel_launch(void* const* d_in, const int* in_sizes, int n_in,
                              void* d_out, int out_size)
{
    const float* x    = (const float*)d_in[0];
    const float* y    = (const float*)d_in[1];
    const float* Wq   = (const float*)d_in[2];
    const float* Wk   = (const float*)d_in[3];
    const float* Wv   = (const float*)d_in[4];
    const float* Wh   = (const float*)d_in[5];
    const float* Wc   = (const float*)d_in[6];
    const float* Wc2  = (const float*)d_in[7];
    const int*   xsz  = (const int*)d_in[8];
    const int*   ysz  = (const int*)d_in[9];
    float* out = (float*)d_out;

    float *pXYN, *pQ, *pK, *pV, *pA, *pWf;
    __half* pPh;
    cudaGetSymbolAddress((void**)&pXYN, g_xyn);
    cudaGetSymbolAddress((void**)&pQ,   g_Q);
    cudaGetSymbolAddress((void**)&pK,   g_K);
    cudaGetSymbolAddress((void**)&pV,   g_V);
    cudaGetSymbolAddress((void**)&pA,   g_att);
    cudaGetSymbolAddress((void**)&pWf,  g_wf);
    cudaGetSymbolAddress((void**)&pPh,  g_ph);

    cudaFuncSetAttribute(attn_tc_kernel,    cudaFuncAttributeMaxDynamicSharedMemorySize, ATTN_SMEM);
    cudaFuncSetAttribute(cross_h16_kernel,  cudaFuncAttributeMaxDynamicSharedMemorySize, CROSS_SMEM);
    cudaFuncSetAttribute(qkv_merged_kernel, cudaFuncAttributeMaxDynamicSharedMemorySize, QKV_SMEM);
    cudaFuncSetAttribute(proj_tc_kernel,    cudaFuncAttributeMaxDynamicSharedMemorySize, PROJ_SMEM);

    sgemm_kernel<<<dim3(2, 2), 256>>>(Wh, Wc, pWf, 128, 128, 64);

    setnorm_kernel<<<NSET, 256>>>(x, xsz, pXYN);
    setnorm_kernel<<<NSET, 256>>>(y, ysz, pXYN + (size_t)ROWS_ONE * 64);

    qkv_merged_kernel<<<ROWS_ALL / 128, 256, QKV_SMEM>>>(
        pXYN, Wq, Wk, Wv, pQ, pK, pV);

    attn_tc_kernel<<<dim3(2 * NSET, 2), 128, ATTN_SMEM>>>(pQ, pK, pV, pA);

    proj_tc_kernel<<<dim3(2, ROWS_ALL / 128), 256, PROJ_SMEM>>>(pA, pWf, pPh);

    cross_h16_kernel<<<dim3(NSET, NSET), 256, CROSS_SMEM>>>(pPh, xsz, Wc2, out);
}

// round 10
// speedup vs baseline: 4.9848x; 1.0317x over previous
#include <cuda_runtime.h>
#include <cuda_fp16.h>
#include <math.h>

// ---------------------------------------------------------------------------
//   x,y: [64,128,64], HEADS=2, HS=64, LEAKY=0.3
//   set_norm -> pipelined tf32-TC QKV (cp.async + reg-side cvt.rna) ->
//   full-TC masked attention -> tf32-TC att@(Wh@Wc) [fp16] ->
//   streamed fp16-TC cross score
// ---------------------------------------------------------------------------

#define NSET   64
#define NITEM  128
#define DFEAT  64
#define ROWS_ONE (NSET * NITEM)        // 8192
#define ROWS_ALL (2 * ROWS_ONE)        // 16384

__device__ float g_xyn [ROWS_ALL * 64];
__device__ float g_Q   [ROWS_ALL * 128];
__device__ float g_K   [ROWS_ALL * 128];
__device__ float g_V   [ROWS_ALL * 128];
__device__ float g_att [ROWS_ALL * 128];
__device__ float g_wf  [128 * 128];                 // Wh @ Wc
__device__ __half g_ph [ROWS_ALL * 128];            // P in fp16

__device__ __forceinline__ unsigned f2tf32(float x) {
    unsigned r;
    asm("cvt.rna.tf32.f32 %0, %1;" : "=r"(r) : "f"(x));
    return r;
}
__device__ __forceinline__ unsigned u2tf32(unsigned u) {
    unsigned r;
    asm("cvt.rna.tf32.f32 %0, %1;" : "=r"(r) : "f"(__uint_as_float(u)));
    return r;
}
__device__ __forceinline__ unsigned smem_u32(const void* p) {
    return (unsigned)__cvta_generic_to_shared(p);
}
__device__ __forceinline__ unsigned pack_h16(float a, float b) {
    __half2 t = __floats2half2_rn(a, b);
    return *(unsigned*)&t;
}
#define CP_ASYNC16(dst_u32, src_ptr) \
    asm volatile("cp.async.cg.shared.global [%0], [%1], 16;" \
                 :: "r"(dst_u32), "l"(src_ptr))
#define CP_COMMIT() asm volatile("cp.async.commit_group;")
#define CP_WAIT0()  asm volatile("cp.async.wait_group 0;")

// ---------------------------------------------------------------------------
// Kernel 1: masked set normalization
// ---------------------------------------------------------------------------
__global__ __launch_bounds__(256) void setnorm_kernel(
    const float* __restrict__ X, const int* __restrict__ sz, float* __restrict__ O)
{
    const int n   = blockIdx.x;
    const int tid = threadIdx.x;
    const float* xb = X + n * (NITEM * DFEAT);
    float*       ob = O + n * (NITEM * DFEAT);

    __shared__ float rmask[NITEM];
    __shared__ float red[256];
    __shared__ float s_mean, s_inv;

    if (tid < NITEM) {
        float s = 0.f;
        #pragma unroll
        for (int e = 0; e < DFEAT; e++) s += xb[tid * DFEAT + e];
        rmask[tid] = (s != 0.0f) ? 1.0f : 0.0f;
    }

    float tot = 0.f;
    for (int idx = tid; idx < NITEM * DFEAT; idx += 256) tot += xb[idx];
    red[tid] = tot; __syncthreads();
    for (int s = 128; s > 0; s >>= 1) {
        if (tid < s) red[tid] += red[tid + s];
        __syncthreads();
    }
    const float denom = (float)sz[n] * (float)DFEAT;
    if (tid == 0) s_mean = red[0] / denom;
    __syncthreads();
    const float mean = s_mean;

    float ss = 0.f;
    for (int idx = tid; idx < NITEM * DFEAT; idx += 256) {
        float d = xb[idx] - mean;
        ss += d * d * rmask[idx >> 6];
    }
    __syncthreads();
    red[tid] = ss; __syncthreads();
    for (int s = 128; s > 0; s >>= 1) {
        if (tid < s) red[tid] += red[tid + s];
        __syncthreads();
    }
    if (tid == 0) s_inv = 1.0f / (sqrtf(red[0] / denom) + 1e-8f);
    __syncthreads();
    const float inv = s_inv;

    for (int idx = tid; idx < NITEM * DFEAT; idx += 256)
        ob[idx] = (xb[idx] - mean) * inv * rmask[idx >> 6];
}

// ---------------------------------------------------------------------------
// Kernel 2a: small fp32 SGEMM (for Wf = Wh @ Wc only)
// ---------------------------------------------------------------------------
__global__ __launch_bounds__(256) void sgemm_kernel(
    const float* __restrict__ A, const float* __restrict__ B,
    float* __restrict__ C, int M, int N, int K)
{
    __shared__ float As[16][65];
    __shared__ float Bs[16][65];
    const int bx = blockIdx.x, by = blockIdx.y;
    const int tid = threadIdx.x;
    const int tx = tid & 15, ty = tid >> 4;

    float acc[4][4] = {};
    for (int k0 = 0; k0 < K; k0 += 16) {
        #pragma unroll
        for (int i = tid; i < 64 * 16; i += 256) {
            int r = i >> 4, kk = i & 15;
            As[kk][r] = A[(by * 64 + r) * K + k0 + kk];
        }
        #pragma unroll
        for (int i = tid; i < 16 * 64; i += 256) {
            int kk = i >> 6, c = i & 63;
            Bs[kk][c] = B[(k0 + kk) * N + bx * 64 + c];
        }
        __syncthreads();
        #pragma unroll
        for (int kk = 0; kk < 16; kk++) {
            float a[4], b[4];
            #pragma unroll
            for (int i = 0; i < 4; i++) a[i] = As[kk][ty * 4 + i];
            #pragma unroll
            for (int j = 0; j < 4; j++) b[j] = Bs[kk][tx * 4 + j];
            #pragma unroll
            for (int i = 0; i < 4; i++)
                #pragma unroll
                for (int j = 0; j < 4; j++)
                    acc[i][j] = fmaf(a[i], b[j], acc[i][j]);
        }
        __syncthreads();
    }
    #pragma unroll
    for (int i = 0; i < 4; i++)
        #pragma unroll
        for (int j = 0; j < 4; j++)
            C[(by * 64 + ty * 4 + i) * N + bx * 64 + tx * 4 + j] = acc[i][j];
}

// ---------------------------------------------------------------------------
// Kernel 2b: pipelined QKV on tf32 TC. grid = 256 (64-row strips).
// cp.async loads raw fp32 bits; cvt.rna.tf32 applied to FRAGMENT REGISTERS
// (truncation-fed tf32 was the R9 bias bug). W kept K-MAJOR [64][132].
// ---------------------------------------------------------------------------
#define QAP 68
#define WP  132
#define QKV_SMEM ((64 * QAP + 2 * 64 * WP) * 4)   // 84992 B

__global__ __launch_bounds__(256) void qkv_pipe_kernel(
    const float* __restrict__ A,
    const float* __restrict__ Wq, const float* __restrict__ Wk,
    const float* __restrict__ Wv,
    float* __restrict__ Q, float* __restrict__ Ko, float* __restrict__ V)
{
    extern __shared__ unsigned smu[];
    unsigned* As = smu;                      // [64][QAP]
    unsigned* Ws0 = smu + 64 * QAP;          // [64][WP] double buffer
    unsigned* Ws1 = Ws0 + 64 * WP;
    const int sb = blockIdx.x;               // 64-row strip
    const int tid = threadIdx.x, lane = tid & 31, w = tid >> 5;
    const int gi = lane >> 2, ti = lane & 3;
    const int r0 = (w & 1) * 32, c0 = (w >> 1) * 32;
    const int rbase = sb * 64;

    const float* Warr[3] = {Wq, Wk, Wv};
    float*       Carr[3] = {Q, Ko, V};

    for (int idx = tid; idx < 64 * 16; idx += 256) {
        int row = idx >> 4, c4 = (idx & 15) << 2;
        CP_ASYNC16(smem_u32(As + row * QAP + c4),
                   A + (size_t)(rbase + row) * 64 + c4);
    }
    for (int idx = tid; idx < 64 * 32; idx += 256) {
        int k = idx >> 5, c4 = (idx & 31) << 2;
        CP_ASYNC16(smem_u32(Ws0 + k * WP + c4), Wq + k * 128 + c4);
    }
    CP_COMMIT();
    CP_WAIT0();
    __syncthreads();

    #pragma unroll
    for (int sel = 0; sel < 3; sel++) {
        unsigned* Wcur = (sel & 1) ? Ws1 : Ws0;
        unsigned* Wnxt = (sel & 1) ? Ws0 : Ws1;
        if (sel < 2) {
            const float* Wn = Warr[sel + 1];
            for (int idx = tid; idx < 64 * 32; idx += 256) {
                int k = idx >> 5, c4 = (idx & 31) << 2;
                CP_ASYNC16(smem_u32(Wnxt + k * WP + c4), Wn + k * 128 + c4);
            }
            CP_COMMIT();
        }

        float acc[32];
        #pragma unroll
        for (int i = 0; i < 32; i++) acc[i] = 0.f;

        #pragma unroll
        for (int k0 = 0; k0 < 64; k0 += 8) {
            unsigned af[2][4];
            #pragma unroll
            for (int m = 0; m < 2; m++) {
                const unsigned* ab = As + (r0 + m * 16 + gi) * QAP + k0 + ti;
                af[m][0] = u2tf32(ab[0]);
                af[m][1] = u2tf32(ab[8 * QAP]);
                af[m][2] = u2tf32(ab[4]);
                af[m][3] = u2tf32(ab[8 * QAP + 4]);
            }
            #pragma unroll
            for (int nf = 0; nf < 4; nf++) {
                const unsigned* bb = Wcur + (k0 + ti) * WP + c0 + nf * 8 + gi;
                unsigned b0 = u2tf32(bb[0]);
                unsigned b1 = u2tf32(bb[4 * WP]);
                #pragma unroll
                for (int m = 0; m < 2; m++) {
                    float* c = &acc[(m * 4 + nf) * 4];
                    asm volatile(
                        "mma.sync.aligned.m16n8k8.row.col.f32.tf32.tf32.f32 "
                        "{%0,%1,%2,%3}, {%4,%5,%6,%7}, {%8,%9}, {%0,%1,%2,%3};"
                        : "+f"(c[0]), "+f"(c[1]), "+f"(c[2]), "+f"(c[3])
                        : "r"(af[m][0]), "r"(af[m][1]), "r"(af[m][2]), "r"(af[m][3]),
                          "r"(b0), "r"(b1));
                }
            }
        }

        float* C = Carr[sel];
        #pragma unroll
        for (int m = 0; m < 2; m++)
            #pragma unroll
            for (int nf = 0; nf < 4; nf++) {
                const float* c = &acc[(m * 4 + nf) * 4];
                int row = rbase + r0 + m * 16 + gi;
                int col = c0 + nf * 8 + 2 * ti;
                *(float2*)(C + row * 128 + col)       = make_float2(c[0], c[1]);
                *(float2*)(C + (row + 8) * 128 + col) = make_float2(c[2], c[3]);
            }

        CP_WAIT0();
        __syncthreads();
    }
}

// ---------------------------------------------------------------------------
// Kernel 2c: P = att @ Wf on tf32 tensor cores, fp16 output.
// ---------------------------------------------------------------------------
#define PAP 132
#define PROJ_SMEM ((128 + 64) * PAP * 4)     // 101376 B

__global__ __launch_bounds__(256) void proj_tc_kernel(
    const float* __restrict__ A, const float* __restrict__ B,
    __half* __restrict__ C)
{
    extern __shared__ unsigned smu[];
    unsigned* As = smu;                  // [128][PAP]
    unsigned* Bs = smu + 128 * PAP;      // [64][PAP]
    const int bx = blockIdx.x, by = blockIdx.y;
    const int tid = threadIdx.x, lane = tid & 31, w = tid >> 5;
    const int gi = lane >> 2, ti = lane & 3;
    const int r0 = (w & 3) * 32, c0 = (w >> 2) * 32;

    const float* Ab = A + (size_t)by * 128 * 128;
    for (int idx = tid; idx < 128 * 32; idx += 256) {
        int row = idx >> 5, c4 = (idx & 31) << 2;
        float4 v = *(const float4*)(Ab + row * 128 + c4);
        unsigned* d = As + row * PAP + c4;
        d[0] = f2tf32(v.x); d[1] = f2tf32(v.y);
        d[2] = f2tf32(v.z); d[3] = f2tf32(v.w);
    }
    for (int idx = tid; idx < 64 * 128; idx += 256) {
        int k = idx >> 6, n = idx & 63;
        Bs[n * PAP + k] = f2tf32(B[k * 128 + bx * 64 + n]);
    }
    __syncthreads();

    float acc[32];
    #pragma unroll
    for (int i = 0; i < 32; i++) acc[i] = 0.f;

    #pragma unroll
    for (int k0 = 0; k0 < 128; k0 += 8) {
        unsigned af[2][4];
        #pragma unroll
        for (int m = 0; m < 2; m++) {
            const unsigned* ab = As + (r0 + m * 16 + gi) * PAP + k0 + ti;
            af[m][0] = ab[0];
            af[m][1] = ab[8 * PAP];
            af[m][2] = ab[4];
            af[m][3] = ab[8 * PAP + 4];
        }
        #pragma unroll
        for (int nf = 0; nf < 4; nf++) {
            const unsigned* bb = Bs + (c0 + nf * 8 + gi) * PAP + k0 + ti;
            unsigned b0 = bb[0], b1 = bb[4];
            #pragma unroll
            for (int m = 0; m < 2; m++) {
                float* c = &acc[(m * 4 + nf) * 4];
                asm volatile(
                    "mma.sync.aligned.m16n8k8.row.col.f32.tf32.tf32.f32 "
                    "{%0,%1,%2,%3}, {%4,%5,%6,%7}, {%8,%9}, {%0,%1,%2,%3};"
                    : "+f"(c[0]), "+f"(c[1]), "+f"(c[2]), "+f"(c[3])
                    : "r"(af[m][0]), "r"(af[m][1]), "r"(af[m][2]), "r"(af[m][3]),
                      "r"(b0), "r"(b1));
            }
        }
    }

    #pragma unroll
    for (int m = 0; m < 2; m++)
        #pragma unroll
        for (int nf = 0; nf < 4; nf++) {
            const float* c = &acc[(m * 4 + nf) * 4];
            int row = by * 128 + r0 + m * 16 + gi;
            int col = bx * 64 + c0 + nf * 8 + 2 * ti;
            *(__half2*)(C + row * 128 + col) = __floats2half2_rn(c[0], c[1]);
            *(__half2*)(C + (row + 8) * 128 + col) = __floats2half2_rn(c[2], c[3]);
        }
}

// ---------------------------------------------------------------------------
// Kernel 3: full-TC masked attention (tf32 QK^T, frag softmax, fp16 PV).
// ---------------------------------------------------------------------------
#define VP 36
#define ATTN_SMEM ((2 * 128 * QAP + 128 * VP) * 4)   // 88064 B

__global__ __launch_bounds__(128) void attn_tc_kernel(
    const float* __restrict__ Q, const float* __restrict__ K,
    const float* __restrict__ V, float* __restrict__ O)
{
    extern __shared__ unsigned smu[];
    unsigned* Qs = smu;                      // [128][QAP] tf32
    unsigned* Ks = smu + 128 * QAP;          // [128][QAP] tf32
    unsigned* Vs = smu + 2 * 128 * QAP;      // [128][VP]  half2 words

    const int g = blockIdx.x, h = blockIdx.y;
    const int tid = threadIdx.x, lane = tid & 31, w = tid >> 5;
    const int gi = lane >> 2, ti = lane & 3;
    const int r0 = w * 32;
    const int rowbase = g * NITEM, hc = h * 64;

    for (int idx = tid; idx < 128 * 16; idx += 128) {
        int row = idx >> 4, c4 = (idx & 15) << 2;
        float4 qv = *(const float4*)&Q[(rowbase + row) * 128 + hc + c4];
        float4 kv = *(const float4*)&K[(rowbase + row) * 128 + hc + c4];
        unsigned* qd = Qs + row * QAP + c4;
        unsigned* kd = Ks + row * QAP + c4;
        qd[0] = f2tf32(qv.x); qd[1] = f2tf32(qv.y);
        qd[2] = f2tf32(qv.z); qd[3] = f2tf32(qv.w);
        kd[0] = f2tf32(kv.x); kd[1] = f2tf32(kv.y);
        kd[2] = f2tf32(kv.z); kd[3] = f2tf32(kv.w);
    }
    for (int idx = tid; idx < 128 * 32; idx += 128) {
        int row = idx >> 5, c = idx & 31;
        float2 vv = *(const float2*)&V[(rowbase + row) * 128 + hc + 2 * c];
        Vs[row * VP + c] = pack_h16(vv.x, vv.y);
    }
    __syncthreads();

    // ---- S = Q @ K^T ----
    float sacc[2][16][4];
    #pragma unroll
    for (int m = 0; m < 2; m++)
        #pragma unroll
        for (int nf = 0; nf < 16; nf++)
            #pragma unroll
            for (int r = 0; r < 4; r++) sacc[m][nf][r] = 0.f;

    #pragma unroll
    for (int k0 = 0; k0 < 64; k0 += 8) {
        unsigned af[2][4];
        #pragma unroll
        for (int m = 0; m < 2; m++) {
            const unsigned* ab = Qs + (r0 + m * 16 + gi) * QAP + k0 + ti;
            af[m][0] = ab[0];
            af[m][1] = ab[8 * QAP];
            af[m][2] = ab[4];
            af[m][3] = ab[8 * QAP + 4];
        }
        #pragma unroll
        for (int nf = 0; nf < 16; nf++) {
            const unsigned* bb = Ks + (nf * 8 + gi) * QAP + k0 + ti;
            unsigned b0 = bb[0], b1 = bb[4];
            #pragma unroll
            for (int m = 0; m < 2; m++) {
                float* c = sacc[m][nf];
                asm volatile(
                    "mma.sync.aligned.m16n8k8.row.col.f32.tf32.tf32.f32 "
                    "{%0,%1,%2,%3}, {%4,%5,%6,%7}, {%8,%9}, {%0,%1,%2,%3};"
                    : "+f"(c[0]), "+f"(c[1]), "+f"(c[2]), "+f"(c[3])
                    : "r"(af[m][0]), "r"(af[m][1]), "r"(af[m][2]), "r"(af[m][3]),
                      "r"(b0), "r"(b1));
            }
        }
    }

    // ---- fragment softmax ----
    const float COEF = 0.125f * 1.44269504f;
    float invd0[2], invd1[2];
    unsigned pf[2][8][4];

    #pragma unroll
    for (int mf = 0; mf < 2; mf++) {
        float mx0 = -3.4e38f, mx1 = -3.4e38f;
        #pragma unroll
        for (int nf = 0; nf < 16; nf++) {
            mx0 = fmaxf(mx0, fmaxf(sacc[mf][nf][0], sacc[mf][nf][1]));
            mx1 = fmaxf(mx1, fmaxf(sacc[mf][nf][2], sacc[mf][nf][3]));
        }
        #pragma unroll
        for (int o = 1; o < 4; o <<= 1) {
            mx0 = fmaxf(mx0, __shfl_xor_sync(0xffffffffu, mx0, o));
            mx1 = fmaxf(mx1, __shfl_xor_sync(0xffffffffu, mx1, o));
        }
        float d0 = 0.f, d1 = 0.f;
        #pragma unroll
        for (int nf = 0; nf < 16; nf++) {
            float raw0 = sacc[mf][nf][0], raw1 = sacc[mf][nf][1];
            float raw2 = sacc[mf][nf][2], raw3 = sacc[mf][nf][3];
            float p0 = (raw0 != 0.f) ? exp2f((raw0 - mx0) * COEF) : 0.f;
            float p1 = (raw1 != 0.f) ? exp2f((raw1 - mx0) * COEF) : 0.f;
            float p2 = (raw2 != 0.f) ? exp2f((raw2 - mx1) * COEF) : 0.f;
            float p3 = (raw3 != 0.f) ? exp2f((raw3 - mx1) * COEF) : 0.f;
            sacc[mf][nf][0] = p0; sacc[mf][nf][1] = p1;
            sacc[mf][nf][2] = p2; sacc[mf][nf][3] = p3;
            d0 += p0 + p1; d1 += p2 + p3;
        }
        #pragma unroll
        for (int o = 1; o < 4; o <<= 1) {
            d0 += __shfl_xor_sync(0xffffffffu, d0, o);
            d1 += __shfl_xor_sync(0xffffffffu, d1, o);
        }
        invd0[mf] = 1.0f / (d0 + 1e-10f);
        invd1[mf] = 1.0f / (d1 + 1e-10f);

        #pragma unroll
        for (int fp = 0; fp < 8; fp++) {
            pf[mf][fp][0] = pack_h16(sacc[mf][2 * fp][0],     sacc[mf][2 * fp][1]);
            pf[mf][fp][1] = pack_h16(sacc[mf][2 * fp][2],     sacc[mf][2 * fp][3]);
            pf[mf][fp][2] = pack_h16(sacc[mf][2 * fp + 1][0], sacc[mf][2 * fp + 1][1]);
            pf[mf][fp][3] = pack_h16(sacc[mf][2 * fp + 1][2], sacc[mf][2 * fp + 1][3]);
        }
    }

    // ---- O = P @ V ----
    float oacc[2][8][4];
    #pragma unroll
    for (int m = 0; m < 2; m++)
        #pragma unroll
        for (int nf = 0; nf < 8; nf++)
            #pragma unroll
            for (int r = 0; r < 4; r++) oacc[m][nf][r] = 0.f;

    const unsigned vbase = smem_u32(Vs);
    #pragma unroll
    for (int kb = 0; kb < 8; kb++) {
        unsigned bfr[8][2];
        #pragma unroll
        for (int ng = 0; ng < 4; ng++) {
            unsigned t0, t1, t2, t3;
            unsigned addr = vbase +
                ((kb * 16 + (lane & 15)) * VP + ng * 8 + (lane >> 4) * 4) * 4;
            asm volatile(
                "ldmatrix.sync.aligned.m8n8.x4.trans.shared.b16 {%0,%1,%2,%3}, [%4];"
                : "=r"(t0), "=r"(t1), "=r"(t2), "=r"(t3) : "r"(addr));
            bfr[2 * ng][0]     = t0; bfr[2 * ng][1]     = t1;
            bfr[2 * ng + 1][0] = t2; bfr[2 * ng + 1][1] = t3;
        }
        #pragma unroll
        for (int nf = 0; nf < 8; nf++)
            #pragma unroll
            for (int m = 0; m < 2; m++) {
                float* c = oacc[m][nf];
                asm volatile(
                    "mma.sync.aligned.m16n8k16.row.col.f32.f16.f16.f32 "
                    "{%0,%1,%2,%3}, {%4,%5,%6,%7}, {%8,%9}, {%0,%1,%2,%3};"
                    : "+f"(c[0]), "+f"(c[1]), "+f"(c[2]), "+f"(c[3])
                    : "r"(pf[m][kb][0]), "r"(pf[m][kb][1]),
                      "r"(pf[m][kb][2]), "r"(pf[m][kb][3]),
                      "r"(bfr[nf][0]), "r"(bfr[nf][1]));
            }
    }

    #pragma unroll
    for (int m = 0; m < 2; m++)
        #pragma unroll
        for (int nf = 0; nf < 8; nf++) {
            const float* c = oacc[m][nf];
            int row = rowbase + r0 + m * 16 + gi;
            int col = hc + nf * 8 + 2 * ti;
            *(float2*)(O + row * 128 + col) =
                make_float2(c[0] * invd0[m], c[1] * invd0[m]);
            *(float2*)(O + (row + 8) * 128 + col) =
                make_float2(c[2] * invd1[m], c[3] * invd1[m]);
        }
}

// ---------------------------------------------------------------------------
// Kernel 4: STREAMED cross-set score. grid (4, 64): block = (a, 16 b's).
// X tile resident; Y tiles cp.async double-buffered.
// ---------------------------------------------------------------------------
#define BPW 68
#define CROSS_SMEM (3 * 128 * BPW * 4)       // 104448 B

__global__ __launch_bounds__(256) void cross_stream_kernel(
    const __half* __restrict__ P, const int* __restrict__ xsz,
    const float* __restrict__ Wc2, float* __restrict__ out)
{
    extern __shared__ unsigned smu[];
    unsigned* Xs  = smu;                     // [128][BPW]
    unsigned* Ys0 = smu + 128 * BPW;         // double buffer
    unsigned* Ys1 = Ys0 + 128 * BPW;
    __shared__ float red[16];

    const int bq = blockIdx.x, a = blockIdx.y;
    const int tid  = threadIdx.x;
    const int lane = tid & 31, w = tid >> 5;
    const int r0 = (w & 3) * 32, c0 = (w >> 2) * 64;
    const int lrow = lane & 15;
    const int lhi  = lane >> 4;

    const __half* xp = P + (size_t)a * NITEM * 128;
    const __half* ypb = P + (size_t)ROWS_ONE * 128;   // start of Y tiles

    for (int idx = tid; idx < 128 * 16; idx += 256) {
        int row = idx >> 4, w4 = (idx & 15) << 2;
        CP_ASYNC16(smem_u32(Xs + row * BPW + w4), xp + row * 128 + (w4 << 1));
        CP_ASYNC16(smem_u32(Ys0 + row * BPW + w4),
                   ypb + (size_t)(bq * 16) * NITEM * 128 + row * 128 + (w4 << 1));
    }
    CP_COMMIT();
    CP_WAIT0();
    __syncthreads();

    const unsigned xbase = smem_u32(Xs);
    const float wc0 = Wc2[0], wc1 = Wc2[1];

    for (int j = 0; j < 16; j++) {
        const int b = bq * 16 + j;
        unsigned* Ycur = (j & 1) ? Ys1 : Ys0;
        unsigned* Ynxt = (j & 1) ? Ys0 : Ys1;

        if (j < 15) {
            const __half* yn = ypb + (size_t)(b + 1) * NITEM * 128;
            for (int idx = tid; idx < 128 * 16; idx += 256) {
                int row = idx >> 4, w4 = (idx & 15) << 2;
                CP_ASYNC16(smem_u32(Ynxt + row * BPW + w4),
                           yn + row * 128 + (w4 << 1));
            }
            CP_COMMIT();
        }

        const unsigned ybase = smem_u32(Ycur);
        float hsum[2];
        #pragma unroll
        for (int h = 0; h < 2; h++) {
            const int hw = h * 32;
            float acc[64];
            #pragma unroll
            for (int i = 0; i < 64; i++) acc[i] = 0.f;

            #pragma unroll
            for (int ks = 0; ks < 4; ks++) {
                const int kw = hw + ks * 8;
                unsigned af[2][4];
                #pragma unroll
                for (int m = 0; m < 2; m++) {
                    unsigned addr = xbase +
                        ((r0 + m * 16 + lrow) * BPW + kw) * 4 + lhi * 16;
                    asm volatile(
                        "ldmatrix.sync.aligned.m8n8.x4.shared.b16 {%0,%1,%2,%3}, [%4];"
                        : "=r"(af[m][0]), "=r"(af[m][1]), "=r"(af[m][2]), "=r"(af[m][3])
                        : "r"(addr));
                }
                unsigned bf[8][2];
                #pragma unroll
                for (int nn = 0; nn < 4; nn++) {
                    unsigned t0, t1, t2, t3;
                    unsigned addr = ybase +
                        ((c0 + nn * 16 + lrow) * BPW + kw) * 4 + lhi * 16;
                    asm volatile(
                        "ldmatrix.sync.aligned.m8n8.x4.shared.b16 {%0,%1,%2,%3}, [%4];"
                        : "=r"(t0), "=r"(t1), "=r"(t2), "=r"(t3)
                        : "r"(addr));
                    bf[nn * 2][0]     = t0; bf[nn * 2][1]     = t2;
                    bf[nn * 2 + 1][0] = t1; bf[nn * 2 + 1][1] = t3;
                }
                #pragma unroll
                for (int n = 0; n < 8; n++)
                    #pragma unroll
                    for (int m = 0; m < 2; m++) {
                        float* c = &acc[m * 32 + n * 4];
                        asm volatile(
                            "mma.sync.aligned.m16n8k16.row.col.f32.f16.f16.f32 "
                            "{%0,%1,%2,%3}, {%4,%5,%6,%7}, {%8,%9}, {%0,%1,%2,%3};"
                            : "+f"(c[0]), "+f"(c[1]), "+f"(c[2]), "+f"(c[3])
                            : "r"(af[m][0]), "r"(af[m][1]), "r"(af[m][2]), "r"(af[m][3]),
                              "r"(bf[n][0]), "r"(bf[n][1]));
                    }
            }

            float s = 0.f;
            #pragma unroll
            for (int i = 0; i < 64; i++) {
                float v = acc[i];
                s += (v > 0.f) ? v : 0.3f * v;
            }
            hsum[h] = s;
        }

        float s0 = hsum[0], s1 = hsum[1];
        #pragma unroll
        for (int o = 16; o > 0; o >>= 1) {
            s0 += __shfl_xor_sync(0xffffffffu, s0, o);
            s1 += __shfl_xor_sync(0xffffffffu, s1, o);
        }
        if (lane == 0) { red[w] = s0; red[8 + w] = s1; }
        __syncthreads();                       // red complete
        if (tid == 0) {
            float S0 = 0.f, S1 = 0.f;
            #pragma unroll
            for (int i = 0; i < 8; i++) { S0 += red[i]; S1 += red[8 + i]; }
            float scale = 1.0f / (8.0f * (float)xsz[b] * 128.0f);
            out[a * NSET + b] = (S0 * wc0 + S1 * wc1) * scale;
        }
        CP_WAIT0();
        __syncthreads();                       // next Y tile ready; red reusable
    }
}

// ---------------------------------------------------------------------------
// Launch
// ---------------------------------------------------------------------------
extern "C" void kernel_launch(void* const* d_in, const int* in_sizes, int n_in,
                              void* d_out, int out_size)
{
    const float* x    = (const float*)d_in[0];
    const float* y    = (const float*)d_in[1];
    const float* Wq   = (const float*)d_in[2];
    const float* Wk   = (const float*)d_in[3];
    const float* Wv   = (const float*)d_in[4];
    const float* Wh   = (const float*)d_in[5];
    const float* Wc   = (const float*)d_in[6];
    const float* Wc2  = (const float*)d_in[7];
    const int*   xsz  = (const int*)d_in[8];
    const int*   ysz  = (const int*)d_in[9];
    float* out = (float*)d_out;

    float *pXYN, *pQ, *pK, *pV, *pA, *pWf;
    __half* pPh;
    cudaGetSymbolAddress((void**)&pXYN, g_xyn);
    cudaGetSymbolAddress((void**)&pQ,   g_Q);
    cudaGetSymbolAddress((void**)&pK,   g_K);
    cudaGetSymbolAddress((void**)&pV,   g_V);
    cudaGetSymbolAddress((void**)&pA,   g_att);
    cudaGetSymbolAddress((void**)&pWf,  g_wf);
    cudaGetSymbolAddress((void**)&pPh,  g_ph);

    cudaFuncSetAttribute(attn_tc_kernel,      cudaFuncAttributeMaxDynamicSharedMemorySize, ATTN_SMEM);
    cudaFuncSetAttribute(cross_stream_kernel, cudaFuncAttributeMaxDynamicSharedMemorySize, CROSS_SMEM);
    cudaFuncSetAttribute(qkv_pipe_kernel,     cudaFuncAttributeMaxDynamicSharedMemorySize, QKV_SMEM);
    cudaFuncSetAttribute(proj_tc_kernel,      cudaFuncAttributeMaxDynamicSharedMemorySize, PROJ_SMEM);

    sgemm_kernel<<<dim3(2, 2), 256>>>(Wh, Wc, pWf, 128, 128, 64);

    setnorm_kernel<<<NSET, 256>>>(x, xsz, pXYN);
    setnorm_kernel<<<NSET, 256>>>(y, ysz, pXYN + (size_t)ROWS_ONE * 64);

    qkv_pipe_kernel<<<ROWS_ALL / 64, 256, QKV_SMEM>>>(
        pXYN, Wq, Wk, Wv, pQ, pK, pV);

    attn_tc_kernel<<<dim3(2 * NSET, 2), 128, ATTN_SMEM>>>(pQ, pK, pV, pA);

    proj_tc_kernel<<<dim3(2, ROWS_ALL / 128), 256, PROJ_SMEM>>>(pA, pWf, pPh);

    cross_stream_kernel<<<dim3(4, NSET), 256, CROSS_SMEM>>>(pPh, xsz, Wc2, out);
}

// round 12
// speedup vs baseline: 5.6384x; 1.1311x over previous
#include <cuda_runtime.h>
#include <cuda_fp16.h>
#include <math.h>

// ---------------------------------------------------------------------------
//   x,y: [64,128,64], HEADS=2, HS=64, LEAKY=0.3
//   fused set_norm+QKV (tf32 TC, cp.async) -> full-TC masked attention ->
//   tf32-TC att@(Wh@Wc) [fp16] -> fp16-TC per-pair cross score (R8 version)
// ---------------------------------------------------------------------------

#define NSET   64
#define NITEM  128
#define DFEAT  64
#define ROWS_ONE (NSET * NITEM)        // 8192
#define ROWS_ALL (2 * ROWS_ONE)        // 16384

__device__ float g_Q   [ROWS_ALL * 128];
__device__ float g_K   [ROWS_ALL * 128];
__device__ float g_V   [ROWS_ALL * 128];
__device__ float g_att [ROWS_ALL * 128];
__device__ float g_wf  [128 * 128];                 // Wh @ Wc
__device__ __half g_ph [ROWS_ALL * 128];            // P in fp16

__device__ __forceinline__ unsigned f2tf32(float x) {
    unsigned r;
    asm("cvt.rna.tf32.f32 %0, %1;" : "=r"(r) : "f"(x));
    return r;
}
__device__ __forceinline__ unsigned u2tf32(unsigned u) {
    unsigned r;
    asm("cvt.rna.tf32.f32 %0, %1;" : "=r"(r) : "f"(__uint_as_float(u)));
    return r;
}
__device__ __forceinline__ unsigned smem_u32(const void* p) {
    return (unsigned)__cvta_generic_to_shared(p);
}
__device__ __forceinline__ unsigned pack_h16(float a, float b) {
    __half2 t = __floats2half2_rn(a, b);
    return *(unsigned*)&t;
}
#define CP_ASYNC16(dst_u32, src_ptr) \
    asm volatile("cp.async.cg.shared.global [%0], [%1], 16;" \
                 :: "r"(dst_u32), "l"(src_ptr))
#define CP_COMMIT() asm volatile("cp.async.commit_group;")
#define CP_WAIT0()  asm volatile("cp.async.wait_group 0;")

// ---------------------------------------------------------------------------
// Kernel 2a: small fp32 SGEMM (for Wf = Wh @ Wc only)
// ---------------------------------------------------------------------------
__global__ __launch_bounds__(256) void sgemm_kernel(
    const float* __restrict__ A, const float* __restrict__ B,
    float* __restrict__ C, int M, int N, int K)
{
    __shared__ float As[16][65];
    __shared__ float Bs[16][65];
    const int bx = blockIdx.x, by = blockIdx.y;
    const int tid = threadIdx.x;
    const int tx = tid & 15, ty = tid >> 4;

    float acc[4][4] = {};
    for (int k0 = 0; k0 < K; k0 += 16) {
        #pragma unroll
        for (int i = tid; i < 64 * 16; i += 256) {
            int r = i >> 4, kk = i & 15;
            As[kk][r] = A[(by * 64 + r) * K + k0 + kk];
        }
        #pragma unroll
        for (int i = tid; i < 16 * 64; i += 256) {
            int kk = i >> 6, c = i & 63;
            Bs[kk][c] = B[(k0 + kk) * N + bx * 64 + c];
        }
        __syncthreads();
        #pragma unroll
        for (int kk = 0; kk < 16; kk++) {
            float a[4], b[4];
            #pragma unroll
            for (int i = 0; i < 4; i++) a[i] = As[kk][ty * 4 + i];
            #pragma unroll
            for (int j = 0; j < 4; j++) b[j] = Bs[kk][tx * 4 + j];
            #pragma unroll
            for (int i = 0; i < 4; i++)
                #pragma unroll
                for (int j = 0; j < 4; j++)
                    acc[i][j] = fmaf(a[i], b[j], acc[i][j]);
        }
        __syncthreads();
    }
    #pragma unroll
    for (int i = 0; i < 4; i++)
        #pragma unroll
        for (int j = 0; j < 4; j++)
            C[(by * 64 + ty * 4 + i) * N + bx * 64 + tx * 4 + j] = acc[i][j];
}

// ---------------------------------------------------------------------------
// Kernel 1+2b FUSED: set-norm + QKV projection. One block per set (128 rows).
// X loaded to smem via cp.async (with Wq prefetch); mask/mean/std computed
// from smem; normalize in place; then 3 pipelined tf32 GEMMs (k-major W,
// double-buffered, reg-side cvt.rna). 8 warps, warp tile 32x64.
// ---------------------------------------------------------------------------
#define QAP 68
#define WP  132
#define SNQKV_SMEM ((128 * QAP + 2 * 64 * WP) * 4)   // 102400 B

__global__ __launch_bounds__(256) void snqkv_kernel(
    const float* __restrict__ X, const float* __restrict__ Y,
    const int* __restrict__ xsz, const int* __restrict__ ysz,
    const float* __restrict__ Wq, const float* __restrict__ Wk,
    const float* __restrict__ Wv,
    float* __restrict__ Q, float* __restrict__ Ko, float* __restrict__ V)
{
    extern __shared__ unsigned smu[];
    unsigned* As  = smu;                     // [128][QAP] floats (then tf32 at frag time)
    unsigned* Ws0 = smu + 128 * QAP;         // [64][WP] double buffer
    unsigned* Ws1 = Ws0 + 64 * WP;
    float* Asf = (float*)As;

    __shared__ float rmask[NITEM];
    __shared__ float red[256];
    __shared__ float s_mean, s_inv;

    const int n   = blockIdx.x;              // global set 0..127
    const int tid = threadIdx.x, lane = tid & 31, w = tid >> 5;
    const int gi = lane >> 2, ti = lane & 3;
    const int r0 = (w & 3) * 32, c0 = (w >> 2) * 64;
    const int rbase = n * NITEM;

    const float* xb = (n < NSET) ? (X + (size_t)n * NITEM * DFEAT)
                                 : (Y + (size_t)(n - NSET) * NITEM * DFEAT);
    const int   szv = (n < NSET) ? xsz[n] : ysz[n - NSET];

    // ---- async load X set + prefetch Wq ----
    for (int idx = tid; idx < 128 * 16; idx += 256) {
        int row = idx >> 4, c4 = (idx & 15) << 2;
        CP_ASYNC16(smem_u32(As + row * QAP + c4), xb + row * 64 + c4);
    }
    for (int idx = tid; idx < 64 * 32; idx += 256) {
        int k = idx >> 5, c4 = (idx & 31) << 2;
        CP_ASYNC16(smem_u32(Ws0 + k * WP + c4), Wq + k * 128 + c4);
    }
    CP_COMMIT();
    CP_WAIT0();
    __syncthreads();

    // ---- set-norm stats from smem ----
    if (tid < NITEM) {
        float s = 0.f;
        #pragma unroll
        for (int e = 0; e < DFEAT; e++) s += Asf[tid * QAP + e];
        rmask[tid] = (s != 0.0f) ? 1.0f : 0.0f;
    }

    float tot = 0.f;
    for (int idx = tid; idx < NITEM * DFEAT; idx += 256)
        tot += Asf[(idx >> 6) * QAP + (idx & 63)];
    red[tid] = tot; __syncthreads();
    for (int s = 128; s > 0; s >>= 1) {
        if (tid < s) red[tid] += red[tid + s];
        __syncthreads();
    }
    const float denom = (float)szv * (float)DFEAT;
    if (tid == 0) s_mean = red[0] / denom;
    __syncthreads();
    const float mean = s_mean;

    float ss = 0.f;
    for (int idx = tid; idx < NITEM * DFEAT; idx += 256) {
        float d = Asf[(idx >> 6) * QAP + (idx & 63)] - mean;
        ss += d * d * rmask[idx >> 6];
    }
    __syncthreads();
    red[tid] = ss; __syncthreads();
    for (int s = 128; s > 0; s >>= 1) {
        if (tid < s) red[tid] += red[tid + s];
        __syncthreads();
    }
    if (tid == 0) s_inv = 1.0f / (sqrtf(red[0] / denom) + 1e-8f);
    __syncthreads();
    const float inv = s_inv;

    // ---- normalize in place ----
    for (int idx = tid; idx < NITEM * DFEAT; idx += 256) {
        int row = idx >> 6, e = idx & 63;
        Asf[row * QAP + e] = (Asf[row * QAP + e] - mean) * inv * rmask[row];
    }
    __syncthreads();

    // ---- 3 pipelined QKV GEMMs ----
    const float* Warr[3] = {Wq, Wk, Wv};
    float*       Carr[3] = {Q, Ko, V};

    #pragma unroll
    for (int sel = 0; sel < 3; sel++) {
        unsigned* Wcur = (sel & 1) ? Ws1 : Ws0;
        unsigned* Wnxt = (sel & 1) ? Ws0 : Ws1;
        if (sel < 2) {
            const float* Wn = Warr[sel + 1];
            for (int idx = tid; idx < 64 * 32; idx += 256) {
                int k = idx >> 5, c4 = (idx & 31) << 2;
                CP_ASYNC16(smem_u32(Wnxt + k * WP + c4), Wn + k * 128 + c4);
            }
            CP_COMMIT();
        }

        float acc[64];
        #pragma unroll
        for (int i = 0; i < 64; i++) acc[i] = 0.f;

        #pragma unroll
        for (int k0 = 0; k0 < 64; k0 += 8) {
            unsigned af[2][4];
            #pragma unroll
            for (int m = 0; m < 2; m++) {
                const unsigned* ab = As + (r0 + m * 16 + gi) * QAP + k0 + ti;
                af[m][0] = u2tf32(ab[0]);
                af[m][1] = u2tf32(ab[8 * QAP]);
                af[m][2] = u2tf32(ab[4]);
                af[m][3] = u2tf32(ab[8 * QAP + 4]);
            }
            #pragma unroll
            for (int nf = 0; nf < 8; nf++) {
                const unsigned* bb = Wcur + (k0 + ti) * WP + c0 + nf * 8 + gi;
                unsigned b0 = u2tf32(bb[0]);
                unsigned b1 = u2tf32(bb[4 * WP]);
                #pragma unroll
                for (int m = 0; m < 2; m++) {
                    float* c = &acc[(m * 8 + nf) * 4];
                    asm volatile(
                        "mma.sync.aligned.m16n8k8.row.col.f32.tf32.tf32.f32 "
                        "{%0,%1,%2,%3}, {%4,%5,%6,%7}, {%8,%9}, {%0,%1,%2,%3};"
                        : "+f"(c[0]), "+f"(c[1]), "+f"(c[2]), "+f"(c[3])
                        : "r"(af[m][0]), "r"(af[m][1]), "r"(af[m][2]), "r"(af[m][3]),
                          "r"(b0), "r"(b1));
                }
            }
        }

        float* C = Carr[sel];
        #pragma unroll
        for (int m = 0; m < 2; m++)
            #pragma unroll
            for (int nf = 0; nf < 8; nf++) {
                const float* c = &acc[(m * 8 + nf) * 4];
                int row = rbase + r0 + m * 16 + gi;
                int col = c0 + nf * 8 + 2 * ti;
                *(float2*)(C + row * 128 + col)       = make_float2(c[0], c[1]);
                *(float2*)(C + (row + 8) * 128 + col) = make_float2(c[2], c[3]);
            }

        CP_WAIT0();
        __syncthreads();
    }
}

// ---------------------------------------------------------------------------
// Kernel 2c: P = att @ Wf on tf32 tensor cores, fp16 output.
// ---------------------------------------------------------------------------
#define PAP 132
#define PROJ_SMEM ((128 + 64) * PAP * 4)     // 101376 B

__global__ __launch_bounds__(256) void proj_tc_kernel(
    const float* __restrict__ A, const float* __restrict__ B,
    __half* __restrict__ C)
{
    extern __shared__ unsigned smu[];
    unsigned* As = smu;                  // [128][PAP]
    unsigned* Bs = smu + 128 * PAP;      // [64][PAP]
    const int bx = blockIdx.x, by = blockIdx.y;
    const int tid = threadIdx.x, lane = tid & 31, w = tid >> 5;
    const int gi = lane >> 2, ti = lane & 3;
    const int r0 = (w & 3) * 32, c0 = (w >> 2) * 32;

    const float* Ab = A + (size_t)by * 128 * 128;
    for (int idx = tid; idx < 128 * 32; idx += 256) {
        int row = idx >> 5, c4 = (idx & 31) << 2;
        float4 v = *(const float4*)(Ab + row * 128 + c4);
        unsigned* d = As + row * PAP + c4;
        d[0] = f2tf32(v.x); d[1] = f2tf32(v.y);
        d[2] = f2tf32(v.z); d[3] = f2tf32(v.w);
    }
    for (int idx = tid; idx < 64 * 128; idx += 256) {
        int k = idx >> 6, n = idx & 63;
        Bs[n * PAP + k] = f2tf32(B[k * 128 + bx * 64 + n]);
    }
    __syncthreads();

    float acc[32];
    #pragma unroll
    for (int i = 0; i < 32; i++) acc[i] = 0.f;

    #pragma unroll
    for (int k0 = 0; k0 < 128; k0 += 8) {
        unsigned af[2][4];
        #pragma unroll
        for (int m = 0; m < 2; m++) {
            const unsigned* ab = As + (r0 + m * 16 + gi) * PAP + k0 + ti;
            af[m][0] = ab[0];
            af[m][1] = ab[8 * PAP];
            af[m][2] = ab[4];
            af[m][3] = ab[8 * PAP + 4];
        }
        #pragma unroll
        for (int nf = 0; nf < 4; nf++) {
            const unsigned* bb = Bs + (c0 + nf * 8 + gi) * PAP + k0 + ti;
            unsigned b0 = bb[0], b1 = bb[4];
            #pragma unroll
            for (int m = 0; m < 2; m++) {
                float* c = &acc[(m * 4 + nf) * 4];
                asm volatile(
                    "mma.sync.aligned.m16n8k8.row.col.f32.tf32.tf32.f32 "
                    "{%0,%1,%2,%3}, {%4,%5,%6,%7}, {%8,%9}, {%0,%1,%2,%3};"
                    : "+f"(c[0]), "+f"(c[1]), "+f"(c[2]), "+f"(c[3])
                    : "r"(af[m][0]), "r"(af[m][1]), "r"(af[m][2]), "r"(af[m][3]),
                      "r"(b0), "r"(b1));
            }
        }
    }

    #pragma unroll
    for (int m = 0; m < 2; m++)
        #pragma unroll
        for (int nf = 0; nf < 4; nf++) {
            const float* c = &acc[(m * 4 + nf) * 4];
            int row = by * 128 + r0 + m * 16 + gi;
            int col = bx * 64 + c0 + nf * 8 + 2 * ti;
            *(__half2*)(C + row * 128 + col) = __floats2half2_rn(c[0], c[1]);
            *(__half2*)(C + (row + 8) * 128 + col) = __floats2half2_rn(c[2], c[3]);
        }
}

// ---------------------------------------------------------------------------
// Kernel 3: full-TC masked attention (tf32 QK^T, frag softmax, fp16 PV).
// ---------------------------------------------------------------------------
#define VP 36
#define ATTN_SMEM ((2 * 128 * QAP + 128 * VP) * 4)   // 88064 B

__global__ __launch_bounds__(128) void attn_tc_kernel(
    const float* __restrict__ Q, const float* __restrict__ K,
    const float* __restrict__ V, float* __restrict__ O)
{
    extern __shared__ unsigned smu[];
    unsigned* Qs = smu;                      // [128][QAP] tf32
    unsigned* Ks = smu + 128 * QAP;          // [128][QAP] tf32
    unsigned* Vs = smu + 2 * 128 * QAP;      // [128][VP]  half2 words

    const int g = blockIdx.x, h = blockIdx.y;
    const int tid = threadIdx.x, lane = tid & 31, w = tid >> 5;
    const int gi = lane >> 2, ti = lane & 3;
    const int r0 = w * 32;
    const int rowbase = g * NITEM, hc = h * 64;

    for (int idx = tid; idx < 128 * 16; idx += 128) {
        int row = idx >> 4, c4 = (idx & 15) << 2;
        float4 qv = *(const float4*)&Q[(rowbase + row) * 128 + hc + c4];
        float4 kv = *(const float4*)&K[(rowbase + row) * 128 + hc + c4];
        unsigned* qd = Qs + row * QAP + c4;
        unsigned* kd = Ks + row * QAP + c4;
        qd[0] = f2tf32(qv.x); qd[1] = f2tf32(qv.y);
        qd[2] = f2tf32(qv.z); qd[3] = f2tf32(qv.w);
        kd[0] = f2tf32(kv.x); kd[1] = f2tf32(kv.y);
        kd[2] = f2tf32(kv.z); kd[3] = f2tf32(kv.w);
    }
    for (int idx = tid; idx < 128 * 32; idx += 128) {
        int row = idx >> 5, c = idx & 31;
        float2 vv = *(const float2*)&V[(rowbase + row) * 128 + hc + 2 * c];
        Vs[row * VP + c] = pack_h16(vv.x, vv.y);
    }
    __syncthreads();

    float sacc[2][16][4];
    #pragma unroll
    for (int m = 0; m < 2; m++)
        #pragma unroll
        for (int nf = 0; nf < 16; nf++)
            #pragma unroll
            for (int r = 0; r < 4; r++) sacc[m][nf][r] = 0.f;

    #pragma unroll
    for (int k0 = 0; k0 < 64; k0 += 8) {
        unsigned af[2][4];
        #pragma unroll
        for (int m = 0; m < 2; m++) {
            const unsigned* ab = Qs + (r0 + m * 16 + gi) * QAP + k0 + ti;
            af[m][0] = ab[0];
            af[m][1] = ab[8 * QAP];
            af[m][2] = ab[4];
            af[m][3] = ab[8 * QAP + 4];
        }
        #pragma unroll
        for (int nf = 0; nf < 16; nf++) {
            const unsigned* bb = Ks + (nf * 8 + gi) * QAP + k0 + ti;
            unsigned b0 = bb[0], b1 = bb[4];
            #pragma unroll
            for (int m = 0; m < 2; m++) {
                float* c = sacc[m][nf];
                asm volatile(
                    "mma.sync.aligned.m16n8k8.row.col.f32.tf32.tf32.f32 "
                    "{%0,%1,%2,%3}, {%4,%5,%6,%7}, {%8,%9}, {%0,%1,%2,%3};"
                    : "+f"(c[0]), "+f"(c[1]), "+f"(c[2]), "+f"(c[3])
                    : "r"(af[m][0]), "r"(af[m][1]), "r"(af[m][2]), "r"(af[m][3]),
                      "r"(b0), "r"(b1));
            }
        }
    }

    const float COEF = 0.125f * 1.44269504f;
    float invd0[2], invd1[2];
    unsigned pf[2][8][4];

    #pragma unroll
    for (int mf = 0; mf < 2; mf++) {
        float mx0 = -3.4e38f, mx1 = -3.4e38f;
        #pragma unroll
        for (int nf = 0; nf < 16; nf++) {
            mx0 = fmaxf(mx0, fmaxf(sacc[mf][nf][0], sacc[mf][nf][1]));
            mx1 = fmaxf(mx1, fmaxf(sacc[mf][nf][2], sacc[mf][nf][3]));
        }
        #pragma unroll
        for (int o = 1; o < 4; o <<= 1) {
            mx0 = fmaxf(mx0, __shfl_xor_sync(0xffffffffu, mx0, o));
            mx1 = fmaxf(mx1, __shfl_xor_sync(0xffffffffu, mx1, o));
        }
        float d0 = 0.f, d1 = 0.f;
        #pragma unroll
        for (int nf = 0; nf < 16; nf++) {
            float raw0 = sacc[mf][nf][0], raw1 = sacc[mf][nf][1];
            float raw2 = sacc[mf][nf][2], raw3 = sacc[mf][nf][3];
            float p0 = (raw0 != 0.f) ? exp2f((raw0 - mx0) * COEF) : 0.f;
            float p1 = (raw1 != 0.f) ? exp2f((raw1 - mx0) * COEF) : 0.f;
            float p2 = (raw2 != 0.f) ? exp2f((raw2 - mx1) * COEF) : 0.f;
            float p3 = (raw3 != 0.f) ? exp2f((raw3 - mx1) * COEF) : 0.f;
            sacc[mf][nf][0] = p0; sacc[mf][nf][1] = p1;
            sacc[mf][nf][2] = p2; sacc[mf][nf][3] = p3;
            d0 += p0 + p1; d1 += p2 + p3;
        }
        #pragma unroll
        for (int o = 1; o < 4; o <<= 1) {
            d0 += __shfl_xor_sync(0xffffffffu, d0, o);
            d1 += __shfl_xor_sync(0xffffffffu, d1, o);
        }
        invd0[mf] = 1.0f / (d0 + 1e-10f);
        invd1[mf] = 1.0f / (d1 + 1e-10f);

        #pragma unroll
        for (int fp = 0; fp < 8; fp++) {
            pf[mf][fp][0] = pack_h16(sacc[mf][2 * fp][0],     sacc[mf][2 * fp][1]);
            pf[mf][fp][1] = pack_h16(sacc[mf][2 * fp][2],     sacc[mf][2 * fp][3]);
            pf[mf][fp][2] = pack_h16(sacc[mf][2 * fp + 1][0], sacc[mf][2 * fp + 1][1]);
            pf[mf][fp][3] = pack_h16(sacc[mf][2 * fp + 1][2], sacc[mf][2 * fp + 1][3]);
        }
    }

    float oacc[2][8][4];
    #pragma unroll
    for (int m = 0; m < 2; m++)
        #pragma unroll
        for (int nf = 0; nf < 8; nf++)
            #pragma unroll
            for (int r = 0; r < 4; r++) oacc[m][nf][r] = 0.f;

    const unsigned vbase = smem_u32(Vs);
    #pragma unroll
    for (int kb = 0; kb < 8; kb++) {
        unsigned bfr[8][2];
        #pragma unroll
        for (int ng = 0; ng < 4; ng++) {
            unsigned t0, t1, t2, t3;
            unsigned addr = vbase +
                ((kb * 16 + (lane & 15)) * VP + ng * 8 + (lane >> 4) * 4) * 4;
            asm volatile(
                "ldmatrix.sync.aligned.m8n8.x4.trans.shared.b16 {%0,%1,%2,%3}, [%4];"
                : "=r"(t0), "=r"(t1), "=r"(t2), "=r"(t3) : "r"(addr));
            bfr[2 * ng][0]     = t0; bfr[2 * ng][1]     = t1;
            bfr[2 * ng + 1][0] = t2; bfr[2 * ng + 1][1] = t3;
        }
        #pragma unroll
        for (int nf = 0; nf < 8; nf++)
            #pragma unroll
            for (int m = 0; m < 2; m++) {
                float* c = oacc[m][nf];
                asm volatile(
                    "mma.sync.aligned.m16n8k16.row.col.f32.f16.f16.f32 "
                    "{%0,%1,%2,%3}, {%4,%5,%6,%7}, {%8,%9}, {%0,%1,%2,%3};"
                    : "+f"(c[0]), "+f"(c[1]), "+f"(c[2]), "+f"(c[3])
                    : "r"(pf[m][kb][0]), "r"(pf[m][kb][1]),
                      "r"(pf[m][kb][2]), "r"(pf[m][kb][3]),
                      "r"(bfr[nf][0]), "r"(bfr[nf][1]));
            }
    }

    #pragma unroll
    for (int m = 0; m < 2; m++)
        #pragma unroll
        for (int nf = 0; nf < 8; nf++) {
            const float* c = oacc[m][nf];
            int row = rowbase + r0 + m * 16 + gi;
            int col = hc + nf * 8 + 2 * ti;
            *(float2*)(O + row * 128 + col) =
                make_float2(c[0] * invd0[m], c[1] * invd0[m]);
            *(float2*)(O + (row + 8) * 128 + col) =
                make_float2(c[2] * invd1[m], c[3] * invd1[m]);
        }
}

// ---------------------------------------------------------------------------
// Kernel 4: per-pair cross score (R8 version), fp16 m16n8k16 + ldmatrix.
// ---------------------------------------------------------------------------
#define BPW 68
#define CROSS_SMEM (2 * 128 * BPW * 4)       // 69632 B

__global__ __launch_bounds__(256) void cross_h16_kernel(
    const __half* __restrict__ P, const int* __restrict__ xsz,
    const float* __restrict__ Wc2, float* __restrict__ out)
{
    extern __shared__ unsigned smu[];
    unsigned* Xs = smu;
    unsigned* Ys = smu + 128 * BPW;
    __shared__ float red[16];

    const int b = blockIdx.x, a = blockIdx.y;
    const int tid  = threadIdx.x;
    const int lane = tid & 31, w = tid >> 5;
    const int r0 = (w & 3) * 32, c0 = (w >> 2) * 64;
    const int lrow = lane & 15;
    const int lhi  = lane >> 4;

    const __half* xp = P + (size_t)a * NITEM * 128;
    const __half* yp = P + (size_t)(ROWS_ONE + b * NITEM) * 128;

    for (int idx = tid; idx < 128 * 16; idx += 256) {
        int row = idx >> 4, w4 = (idx & 15) << 2;
        uint4 xv = *(const uint4*)(xp + row * 128 + (w4 << 1));
        uint4 yv = *(const uint4*)(yp + row * 128 + (w4 << 1));
        *(uint4*)(Xs + row * BPW + w4) = xv;
        *(uint4*)(Ys + row * BPW + w4) = yv;
    }
    __syncthreads();

    const unsigned xbase = smem_u32(Xs);
    const unsigned ybase = smem_u32(Ys);

    float hsum[2];
    #pragma unroll
    for (int h = 0; h < 2; h++) {
        const int hw = h * 32;
        float acc[64];
        #pragma unroll
        for (int i = 0; i < 64; i++) acc[i] = 0.f;

        #pragma unroll
        for (int ks = 0; ks < 4; ks++) {
            const int kw = hw + ks * 8;
            unsigned af[2][4];
            #pragma unroll
            for (int m = 0; m < 2; m++) {
                unsigned addr = xbase +
                    ((r0 + m * 16 + lrow) * BPW + kw) * 4 + lhi * 16;
                asm volatile(
                    "ldmatrix.sync.aligned.m8n8.x4.shared.b16 {%0,%1,%2,%3}, [%4];"
                    : "=r"(af[m][0]), "=r"(af[m][1]), "=r"(af[m][2]), "=r"(af[m][3])
                    : "r"(addr));
            }
            unsigned bf[8][2];
            #pragma unroll
            for (int nn = 0; nn < 4; nn++) {
                unsigned t0, t1, t2, t3;
                unsigned addr = ybase +
                    ((c0 + nn * 16 + lrow) * BPW + kw) * 4 + lhi * 16;
                asm volatile(
                    "ldmatrix.sync.aligned.m8n8.x4.shared.b16 {%0,%1,%2,%3}, [%4];"
                    : "=r"(t0), "=r"(t1), "=r"(t2), "=r"(t3)
                    : "r"(addr));
                bf[nn * 2][0]     = t0; bf[nn * 2][1]     = t2;
                bf[nn * 2 + 1][0] = t1; bf[nn * 2 + 1][1] = t3;
            }
            #pragma unroll
            for (int n = 0; n < 8; n++)
                #pragma unroll
                for (int m = 0; m < 2; m++) {
                    float* c = &acc[m * 32 + n * 4];
                    asm volatile(
                        "mma.sync.aligned.m16n8k16.row.col.f32.f16.f16.f32 "
                        "{%0,%1,%2,%3}, {%4,%5,%6,%7}, {%8,%9}, {%0,%1,%2,%3};"
                        : "+f"(c[0]), "+f"(c[1]), "+f"(c[2]), "+f"(c[3])
                        : "r"(af[m][0]), "r"(af[m][1]), "r"(af[m][2]), "r"(af[m][3]),
                          "r"(bf[n][0]), "r"(bf[n][1]));
                }
        }

        float s = 0.f;
        #pragma unroll
        for (int i = 0; i < 64; i++) {
            float v = acc[i];
            s += (v > 0.f) ? v : 0.3f * v;
        }
        hsum[h] = s;
    }

    float s0 = hsum[0], s1 = hsum[1];
    #pragma unroll
    for (int o = 16; o > 0; o >>= 1) {
        s0 += __shfl_xor_sync(0xffffffffu, s0, o);
        s1 += __shfl_xor_sync(0xffffffffu, s1, o);
    }
    if (lane == 0) { red[w] = s0; red[8 + w] = s1; }
    __syncthreads();
    if (tid == 0) {
        float S0 = 0.f, S1 = 0.f;
        #pragma unroll
        for (int i = 0; i < 8; i++) { S0 += red[i]; S1 += red[8 + i]; }
        float scale = 1.0f / (8.0f * (float)xsz[b] * 128.0f);
        out[a * NSET + b] = (S0 * Wc2[0] + S1 * Wc2[1]) * scale;
    }
}

// ---------------------------------------------------------------------------
// Launch
// ---------------------------------------------------------------------------
extern "C" void kernel_launch(void* const* d_in, const int* in_sizes, int n_in,
                              void* d_out, int out_size)
{
    const float* x    = (const float*)d_in[0];
    const float* y    = (const float*)d_in[1];
    const float* Wq   = (const float*)d_in[2];
    const float* Wk   = (const float*)d_in[3];
    const float* Wv   = (const float*)d_in[4];
    const float* Wh   = (const float*)d_in[5];
    const float* Wc   = (const float*)d_in[6];
    const float* Wc2  = (const float*)d_in[7];
    const int*   xsz  = (const int*)d_in[8];
    const int*   ysz  = (const int*)d_in[9];
    float* out = (float*)d_out;

    float *pQ, *pK, *pV, *pA, *pWf;
    __half* pPh;
    cudaGetSymbolAddress((void**)&pQ,   g_Q);
    cudaGetSymbolAddress((void**)&pK,   g_K);
    cudaGetSymbolAddress((void**)&pV,   g_V);
    cudaGetSymbolAddress((void**)&pA,   g_att);
    cudaGetSymbolAddress((void**)&pWf,  g_wf);
    cudaGetSymbolAddress((void**)&pPh,  g_ph);

    cudaFuncSetAttribute(attn_tc_kernel,   cudaFuncAttributeMaxDynamicSharedMemorySize, ATTN_SMEM);
    cudaFuncSetAttribute(cross_h16_kernel, cudaFuncAttributeMaxDynamicSharedMemorySize, CROSS_SMEM);
    cudaFuncSetAttribute(snqkv_kernel,     cudaFuncAttributeMaxDynamicSharedMemorySize, SNQKV_SMEM);
    cudaFuncSetAttribute(proj_tc_kernel,   cudaFuncAttributeMaxDynamicSharedMemorySize, PROJ_SMEM);

    sgemm_kernel<<<dim3(2, 2), 256>>>(Wh, Wc, pWf, 128, 128, 64);

    snqkv_kernel<<<2 * NSET, 256, SNQKV_SMEM>>>(
        x, y, xsz, ysz, Wq, Wk, Wv, pQ, pK, pV);

    attn_tc_kernel<<<dim3(2 * NSET, 2), 128, ATTN_SMEM>>>(pQ, pK, pV, pA);

    proj_tc_kernel<<<dim3(2, ROWS_ALL / 128), 256, PROJ_SMEM>>>(pA, pWf, pPh);

    cross_h16_kernel<<<dim3(NSET, NSET), 256, CROSS_SMEM>>>(pPh, xsz, Wc2, out);
}

// round 14
// speedup vs baseline: 5.6413x; 1.0005x over previous
#include <cuda_runtime.h>
#include <cuda_fp16.h>
#include <math.h>

// ---------------------------------------------------------------------------
//   x,y: [64,128,64], HEADS=2, HS=64, LEAKY=0.3
//   fused set_norm+QKV (tf32 TC, cp.async) -> full-TC masked attention ->
//   pipelined tf32-TC att@(Wh@Wc) [fp16, k-major W] -> fp16-TC cross score
// ---------------------------------------------------------------------------

#define NSET   64
#define NITEM  128
#define DFEAT  64
#define ROWS_ONE (NSET * NITEM)        // 8192
#define ROWS_ALL (2 * ROWS_ONE)        // 16384

__device__ float g_Q   [ROWS_ALL * 128];
__device__ float g_K   [ROWS_ALL * 128];
__device__ float g_V   [ROWS_ALL * 128];
__device__ float g_att [ROWS_ALL * 128];
__device__ float g_wf  [128 * 128];                 // Wh @ Wc
__device__ __half g_ph [ROWS_ALL * 128];            // P in fp16

__device__ __forceinline__ unsigned f2tf32(float x) {
    unsigned r;
    asm("cvt.rna.tf32.f32 %0, %1;" : "=r"(r) : "f"(x));
    return r;
}
__device__ __forceinline__ unsigned u2tf32(unsigned u) {
    unsigned r;
    asm("cvt.rna.tf32.f32 %0, %1;" : "=r"(r) : "f"(__uint_as_float(u)));
    return r;
}
__device__ __forceinline__ unsigned smem_u32(const void* p) {
    return (unsigned)__cvta_generic_to_shared(p);
}
__device__ __forceinline__ unsigned pack_h16(float a, float b) {
    __half2 t = __floats2half2_rn(a, b);
    return *(unsigned*)&t;
}
#define CP_ASYNC16(dst_u32, src_ptr) \
    asm volatile("cp.async.cg.shared.global [%0], [%1], 16;" \
                 :: "r"(dst_u32), "l"(src_ptr))
#define CP_COMMIT() asm volatile("cp.async.commit_group;")
#define CP_WAIT0()  asm volatile("cp.async.wait_group 0;")

// ---------------------------------------------------------------------------
// Kernel 2a: small fp32 SGEMM (for Wf = Wh @ Wc only)
// ---------------------------------------------------------------------------
__global__ __launch_bounds__(256) void sgemm_kernel(
    const float* __restrict__ A, const float* __restrict__ B,
    float* __restrict__ C, int M, int N, int K)
{
    __shared__ float As[16][65];
    __shared__ float Bs[16][65];
    const int bx = blockIdx.x, by = blockIdx.y;
    const int tid = threadIdx.x;
    const int tx = tid & 15, ty = tid >> 4;

    float acc[4][4] = {};
    for (int k0 = 0; k0 < K; k0 += 16) {
        #pragma unroll
        for (int i = tid; i < 64 * 16; i += 256) {
            int r = i >> 4, kk = i & 15;
            As[kk][r] = A[(by * 64 + r) * K + k0 + kk];
        }
        #pragma unroll
        for (int i = tid; i < 16 * 64; i += 256) {
            int kk = i >> 6, c = i & 63;
            Bs[kk][c] = B[(k0 + kk) * N + bx * 64 + c];
        }
        __syncthreads();
        #pragma unroll
        for (int kk = 0; kk < 16; kk++) {
            float a[4], b[4];
            #pragma unroll
            for (int i = 0; i < 4; i++) a[i] = As[kk][ty * 4 + i];
            #pragma unroll
            for (int j = 0; j < 4; j++) b[j] = Bs[kk][tx * 4 + j];
            #pragma unroll
            for (int i = 0; i < 4; i++)
                #pragma unroll
                for (int j = 0; j < 4; j++)
                    acc[i][j] = fmaf(a[i], b[j], acc[i][j]);
        }
        __syncthreads();
    }
    #pragma unroll
    for (int i = 0; i < 4; i++)
        #pragma unroll
        for (int j = 0; j < 4; j++)
            C[(by * 64 + ty * 4 + i) * N + bx * 64 + tx * 4 + j] = acc[i][j];
}

// ---------------------------------------------------------------------------
// Kernel 1+2b FUSED: set-norm + QKV projection. One block per set (128 rows).
// ---------------------------------------------------------------------------
#define QAP 68
#define WP  132
#define SNQKV_SMEM ((128 * QAP + 2 * 64 * WP) * 4)   // 102400 B

__global__ __launch_bounds__(256) void snqkv_kernel(
    const float* __restrict__ X, const float* __restrict__ Y,
    const int* __restrict__ xsz, const int* __restrict__ ysz,
    const float* __restrict__ Wq, const float* __restrict__ Wk,
    const float* __restrict__ Wv,
    float* __restrict__ Q, float* __restrict__ Ko, float* __restrict__ V)
{
    extern __shared__ unsigned smu[];
    unsigned* As  = smu;                     // [128][QAP]
    unsigned* Ws0 = smu + 128 * QAP;         // [64][WP] double buffer
    unsigned* Ws1 = Ws0 + 64 * WP;
    float* Asf = (float*)As;

    __shared__ float rmask[NITEM];
    __shared__ float red[256];
    __shared__ float s_mean, s_inv;

    const int n   = blockIdx.x;
    const int tid = threadIdx.x, lane = tid & 31, w = tid >> 5;
    const int gi = lane >> 2, ti = lane & 3;
    const int r0 = (w & 3) * 32, c0 = (w >> 2) * 64;
    const int rbase = n * NITEM;

    const float* xb = (n < NSET) ? (X + (size_t)n * NITEM * DFEAT)
                                 : (Y + (size_t)(n - NSET) * NITEM * DFEAT);
    const int   szv = (n < NSET) ? xsz[n] : ysz[n - NSET];

    for (int idx = tid; idx < 128 * 16; idx += 256) {
        int row = idx >> 4, c4 = (idx & 15) << 2;
        CP_ASYNC16(smem_u32(As + row * QAP + c4), xb + row * 64 + c4);
    }
    for (int idx = tid; idx < 64 * 32; idx += 256) {
        int k = idx >> 5, c4 = (idx & 31) << 2;
        CP_ASYNC16(smem_u32(Ws0 + k * WP + c4), Wq + k * 128 + c4);
    }
    CP_COMMIT();
    CP_WAIT0();
    __syncthreads();

    if (tid < NITEM) {
        float s = 0.f;
        #pragma unroll
        for (int e = 0; e < DFEAT; e++) s += Asf[tid * QAP + e];
        rmask[tid] = (s != 0.0f) ? 1.0f : 0.0f;
    }

    float tot = 0.f;
    for (int idx = tid; idx < NITEM * DFEAT; idx += 256)
        tot += Asf[(idx >> 6) * QAP + (idx & 63)];
    red[tid] = tot; __syncthreads();
    for (int s = 128; s > 0; s >>= 1) {
        if (tid < s) red[tid] += red[tid + s];
        __syncthreads();
    }
    const float denom = (float)szv * (float)DFEAT;
    if (tid == 0) s_mean = red[0] / denom;
    __syncthreads();
    const float mean = s_mean;

    float ss = 0.f;
    for (int idx = tid; idx < NITEM * DFEAT; idx += 256) {
        float d = Asf[(idx >> 6) * QAP + (idx & 63)] - mean;
        ss += d * d * rmask[idx >> 6];
    }
    __syncthreads();
    red[tid] = ss; __syncthreads();
    for (int s = 128; s > 0; s >>= 1) {
        if (tid < s) red[tid] += red[tid + s];
        __syncthreads();
    }
    if (tid == 0) s_inv = 1.0f / (sqrtf(red[0] / denom) + 1e-8f);
    __syncthreads();
    const float inv = s_inv;

    for (int idx = tid; idx < NITEM * DFEAT; idx += 256) {
        int row = idx >> 6, e = idx & 63;
        Asf[row * QAP + e] = (Asf[row * QAP + e] - mean) * inv * rmask[row];
    }
    __syncthreads();

    const float* Warr[3] = {Wq, Wk, Wv};
    float*       Carr[3] = {Q, Ko, V};

    #pragma unroll
    for (int sel = 0; sel < 3; sel++) {
        unsigned* Wcur = (sel & 1) ? Ws1 : Ws0;
        unsigned* Wnxt = (sel & 1) ? Ws0 : Ws1;
        if (sel < 2) {
            const float* Wn = Warr[sel + 1];
            for (int idx = tid; idx < 64 * 32; idx += 256) {
                int k = idx >> 5, c4 = (idx & 31) << 2;
                CP_ASYNC16(smem_u32(Wnxt + k * WP + c4), Wn + k * 128 + c4);
            }
            CP_COMMIT();
        }

        float acc[64];
        #pragma unroll
        for (int i = 0; i < 64; i++) acc[i] = 0.f;

        #pragma unroll
        for (int k0 = 0; k0 < 64; k0 += 8) {
            unsigned af[2][4];
            #pragma unroll
            for (int m = 0; m < 2; m++) {
                const unsigned* ab = As + (r0 + m * 16 + gi) * QAP + k0 + ti;
                af[m][0] = u2tf32(ab[0]);
                af[m][1] = u2tf32(ab[8 * QAP]);
                af[m][2] = u2tf32(ab[4]);
                af[m][3] = u2tf32(ab[8 * QAP + 4]);
            }
            #pragma unroll
            for (int nf = 0; nf < 8; nf++) {
                const unsigned* bb = Wcur + (k0 + ti) * WP + c0 + nf * 8 + gi;
                unsigned b0 = u2tf32(bb[0]);
                unsigned b1 = u2tf32(bb[4 * WP]);
                #pragma unroll
                for (int m = 0; m < 2; m++) {
                    float* c = &acc[(m * 8 + nf) * 4];
                    asm volatile(
                        "mma.sync.aligned.m16n8k8.row.col.f32.tf32.tf32.f32 "
                        "{%0,%1,%2,%3}, {%4,%5,%6,%7}, {%8,%9}, {%0,%1,%2,%3};"
                        : "+f"(c[0]), "+f"(c[1]), "+f"(c[2]), "+f"(c[3])
                        : "r"(af[m][0]), "r"(af[m][1]), "r"(af[m][2]), "r"(af[m][3]),
                          "r"(b0), "r"(b1));
                }
            }
        }

        float* C = Carr[sel];
        #pragma unroll
        for (int m = 0; m < 2; m++)
            #pragma unroll
            for (int nf = 0; nf < 8; nf++) {
                const float* c = &acc[(m * 8 + nf) * 4];
                int row = rbase + r0 + m * 16 + gi;
                int col = c0 + nf * 8 + 2 * ti;
                *(float2*)(C + row * 128 + col)       = make_float2(c[0], c[1]);
                *(float2*)(C + (row + 8) * 128 + col) = make_float2(c[2], c[3]);
            }

        CP_WAIT0();
        __syncthreads();
    }
}

// ---------------------------------------------------------------------------
// Kernel 2c: pipelined P = att @ Wf, fp16 out. grid = 256 (64-row strips).
// Wf kept K-MAJOR [128][WP] via cp.async (no transpose); A strip cp.async,
// reg-side cvt.rna. 8 warps, warp tile 32x32 (2x4 over 64x128), K=128.
// ---------------------------------------------------------------------------
#define PROJ_SMEM ((64 * WP + 128 * WP) * 4)     // 101376 B

__global__ __launch_bounds__(256) void proj_pipe_kernel(
    const float* __restrict__ A, const float* __restrict__ B,
    __half* __restrict__ C)
{
    extern __shared__ unsigned smu[];
    unsigned* As = smu;                  // [64][WP]  A strip (fp32 bits)
    unsigned* Bs = smu + 64 * WP;        // [128][WP] Wf k-major (fp32 bits)
    const int sb = blockIdx.x;           // 64-row strip
    const int tid = threadIdx.x, lane = tid & 31, w = tid >> 5;
    const int gi = lane >> 2, ti = lane & 3;
    const int r0 = (w & 1) * 32, c0 = (w >> 1) * 32;
    const int rbase = sb * 64;

    for (int idx = tid; idx < 64 * 32; idx += 256) {
        int row = idx >> 5, c4 = (idx & 31) << 2;
        CP_ASYNC16(smem_u32(As + row * WP + c4),
                   A + (size_t)(rbase + row) * 128 + c4);
    }
    for (int idx = tid; idx < 128 * 32; idx += 256) {
        int k = idx >> 5, c4 = (idx & 31) << 2;
        CP_ASYNC16(smem_u32(Bs + k * WP + c4), B + k * 128 + c4);
    }
    CP_COMMIT();
    CP_WAIT0();
    __syncthreads();

    float acc[32];
    #pragma unroll
    for (int i = 0; i < 32; i++) acc[i] = 0.f;

    #pragma unroll
    for (int k0 = 0; k0 < 128; k0 += 8) {
        unsigned af[2][4];
        #pragma unroll
        for (int m = 0; m < 2; m++) {
            const unsigned* ab = As + (r0 + m * 16 + gi) * WP + k0 + ti;
            af[m][0] = u2tf32(ab[0]);
            af[m][1] = u2tf32(ab[8 * WP]);
            af[m][2] = u2tf32(ab[4]);
            af[m][3] = u2tf32(ab[8 * WP + 4]);
        }
        #pragma unroll
        for (int nf = 0; nf < 4; nf++) {
            const unsigned* bb = Bs + (k0 + ti) * WP + c0 + nf * 8 + gi;
            unsigned b0 = u2tf32(bb[0]);
            unsigned b1 = u2tf32(bb[4 * WP]);
            #pragma unroll
            for (int m = 0; m < 2; m++) {
                float* c = &acc[(m * 4 + nf) * 4];
                asm volatile(
                    "mma.sync.aligned.m16n8k8.row.col.f32.tf32.tf32.f32 "
                    "{%0,%1,%2,%3}, {%4,%5,%6,%7}, {%8,%9}, {%0,%1,%2,%3};"
                    : "+f"(c[0]), "+f"(c[1]), "+f"(c[2]), "+f"(c[3])
                    : "r"(af[m][0]), "r"(af[m][1]), "r"(af[m][2]), "r"(af[m][3]),
                      "r"(b0), "r"(b1));
            }
        }
    }

    #pragma unroll
    for (int m = 0; m < 2; m++)
        #pragma unroll
        for (int nf = 0; nf < 4; nf++) {
            const float* c = &acc[(m * 4 + nf) * 4];
            int row = rbase + r0 + m * 16 + gi;
            int col = c0 + nf * 8 + 2 * ti;
            *(__half2*)(C + row * 128 + col) = __floats2half2_rn(c[0], c[1]);
            *(__half2*)(C + (row + 8) * 128 + col) = __floats2half2_rn(c[2], c[3]);
        }
}

// ---------------------------------------------------------------------------
// Kernel 3: full-TC masked attention (tf32 QK^T, frag softmax, fp16 PV).
// ---------------------------------------------------------------------------
#define VP 36
#define ATTN_SMEM ((2 * 128 * QAP + 128 * VP) * 4)   // 88064 B

__global__ __launch_bounds__(128) void attn_tc_kernel(
    const float* __restrict__ Q, const float* __restrict__ K,
    const float* __restrict__ V, float* __restrict__ O)
{
    extern __shared__ unsigned smu[];
    unsigned* Qs = smu;                      // [128][QAP] tf32
    unsigned* Ks = smu + 128 * QAP;          // [128][QAP] tf32
    unsigned* Vs = smu + 2 * 128 * QAP;      // [128][VP]  half2 words

    const int g = blockIdx.x, h = blockIdx.y;
    const int tid = threadIdx.x, lane = tid & 31, w = tid >> 5;
    const int gi = lane >> 2, ti = lane & 3;
    const int r0 = w * 32;
    const int rowbase = g * NITEM, hc = h * 64;

    for (int idx = tid; idx < 128 * 16; idx += 128) {
        int row = idx >> 4, c4 = (idx & 15) << 2;
        float4 qv = *(const float4*)&Q[(rowbase + row) * 128 + hc + c4];
        float4 kv = *(const float4*)&K[(rowbase + row) * 128 + hc + c4];
        unsigned* qd = Qs + row * QAP + c4;
        unsigned* kd = Ks + row * QAP + c4;
        qd[0] = f2tf32(qv.x); qd[1] = f2tf32(qv.y);
        qd[2] = f2tf32(qv.z); qd[3] = f2tf32(qv.w);
        kd[0] = f2tf32(kv.x); kd[1] = f2tf32(kv.y);
        kd[2] = f2tf32(kv.z); kd[3] = f2tf32(kv.w);
    }
    for (int idx = tid; idx < 128 * 32; idx += 128) {
        int row = idx >> 5, c = idx & 31;
        float2 vv = *(const float2*)&V[(rowbase + row) * 128 + hc + 2 * c];
        Vs[row * VP + c] = pack_h16(vv.x, vv.y);
    }
    __syncthreads();

    float sacc[2][16][4];
    #pragma unroll
    for (int m = 0; m < 2; m++)
        #pragma unroll
        for (int nf = 0; nf < 16; nf++)
            #pragma unroll
            for (int r = 0; r < 4; r++) sacc[m][nf][r] = 0.f;

    #pragma unroll
    for (int k0 = 0; k0 < 64; k0 += 8) {
        unsigned af[2][4];
        #pragma unroll
        for (int m = 0; m < 2; m++) {
            const unsigned* ab = Qs + (r0 + m * 16 + gi) * QAP + k0 + ti;
            af[m][0] = ab[0];
            af[m][1] = ab[8 * QAP];
            af[m][2] = ab[4];
            af[m][3] = ab[8 * QAP + 4];
        }
        #pragma unroll
        for (int nf = 0; nf < 16; nf++) {
            const unsigned* bb = Ks + (nf * 8 + gi) * QAP + k0 + ti;
            unsigned b0 = bb[0], b1 = bb[4];
            #pragma unroll
            for (int m = 0; m < 2; m++) {
                float* c = sacc[m][nf];
                asm volatile(
                    "mma.sync.aligned.m16n8k8.row.col.f32.tf32.tf32.f32 "
                    "{%0,%1,%2,%3}, {%4,%5,%6,%7}, {%8,%9}, {%0,%1,%2,%3};"
                    : "+f"(c[0]), "+f"(c[1]), "+f"(c[2]), "+f"(c[3])
                    : "r"(af[m][0]), "r"(af[m][1]), "r"(af[m][2]), "r"(af[m][3]),
                      "r"(b0), "r"(b1));
            }
        }
    }

    const float COEF = 0.125f * 1.44269504f;
    float invd0[2], invd1[2];
    unsigned pf[2][8][4];

    #pragma unroll
    for (int mf = 0; mf < 2; mf++) {
        float mx0 = -3.4e38f, mx1 = -3.4e38f;
        #pragma unroll
        for (int nf = 0; nf < 16; nf++) {
            mx0 = fmaxf(mx0, fmaxf(sacc[mf][nf][0], sacc[mf][nf][1]));
            mx1 = fmaxf(mx1, fmaxf(sacc[mf][nf][2], sacc[mf][nf][3]));
        }
        #pragma unroll
        for (int o = 1; o < 4; o <<= 1) {
            mx0 = fmaxf(mx0, __shfl_xor_sync(0xffffffffu, mx0, o));
            mx1 = fmaxf(mx1, __shfl_xor_sync(0xffffffffu, mx1, o));
        }
        float d0 = 0.f, d1 = 0.f;
        #pragma unroll
        for (int nf = 0; nf < 16; nf++) {
            float raw0 = sacc[mf][nf][0], raw1 = sacc[mf][nf][1];
            float raw2 = sacc[mf][nf][2], raw3 = sacc[mf][nf][3];
            float p0 = (raw0 != 0.f) ? exp2f((raw0 - mx0) * COEF) : 0.f;
            float p1 = (raw1 != 0.f) ? exp2f((raw1 - mx0) * COEF) : 0.f;
            float p2 = (raw2 != 0.f) ? exp2f((raw2 - mx1) * COEF) : 0.f;
            float p3 = (raw3 != 0.f) ? exp2f((raw3 - mx1) * COEF) : 0.f;
            sacc[mf][nf][0] = p0; sacc[mf][nf][1] = p1;
            sacc[mf][nf][2] = p2; sacc[mf][nf][3] = p3;
            d0 += p0 + p1; d1 += p2 + p3;
        }
        #pragma unroll
        for (int o = 1; o < 4; o <<= 1) {
            d0 += __shfl_xor_sync(0xffffffffu, d0, o);
            d1 += __shfl_xor_sync(0xffffffffu, d1, o);
        }
        invd0[mf] = 1.0f / (d0 + 1e-10f);
        invd1[mf] = 1.0f / (d1 + 1e-10f);

        #pragma unroll
        for (int fp = 0; fp < 8; fp++) {
            pf[mf][fp][0] = pack_h16(sacc[mf][2 * fp][0],     sacc[mf][2 * fp][1]);
            pf[mf][fp][1] = pack_h16(sacc[mf][2 * fp][2],     sacc[mf][2 * fp][3]);
            pf[mf][fp][2] = pack_h16(sacc[mf][2 * fp + 1][0], sacc[mf][2 * fp + 1][1]);
            pf[mf][fp][3] = pack_h16(sacc[mf][2 * fp + 1][2], sacc[mf][2 * fp + 1][3]);
        }
    }

    float oacc[2][8][4];
    #pragma unroll
    for (int m = 0; m < 2; m++)
        #pragma unroll
        for (int nf = 0; nf < 8; nf++)
            #pragma unroll
            for (int r = 0; r < 4; r++) oacc[m][nf][r] = 0.f;

    const unsigned vbase = smem_u32(Vs);
    #pragma unroll
    for (int kb = 0; kb < 8; kb++) {
        unsigned bfr[8][2];
        #pragma unroll
        for (int ng = 0; ng < 4; ng++) {
            unsigned t0, t1, t2, t3;
            unsigned addr = vbase +
                ((kb * 16 + (lane & 15)) * VP + ng * 8 + (lane >> 4) * 4) * 4;
            asm volatile(
                "ldmatrix.sync.aligned.m8n8.x4.trans.shared.b16 {%0,%1,%2,%3}, [%4];"
                : "=r"(t0), "=r"(t1), "=r"(t2), "=r"(t3) : "r"(addr));
            bfr[2 * ng][0]     = t0; bfr[2 * ng][1]     = t1;
            bfr[2 * ng + 1][0] = t2; bfr[2 * ng + 1][1] = t3;
        }
        #pragma unroll
        for (int nf = 0; nf < 8; nf++)
            #pragma unroll
            for (int m = 0; m < 2; m++) {
                float* c = oacc[m][nf];
                asm volatile(
                    "mma.sync.aligned.m16n8k16.row.col.f32.f16.f16.f32 "
                    "{%0,%1,%2,%3}, {%4,%5,%6,%7}, {%8,%9}, {%0,%1,%2,%3};"
                    : "+f"(c[0]), "+f"(c[1]), "+f"(c[2]), "+f"(c[3])
                    : "r"(pf[m][kb][0]), "r"(pf[m][kb][1]),
                      "r"(pf[m][kb][2]), "r"(pf[m][kb][3]),
                      "r"(bfr[nf][0]), "r"(bfr[nf][1]));
            }
    }

    #pragma unroll
    for (int m = 0; m < 2; m++)
        #pragma unroll
        for (int nf = 0; nf < 8; nf++) {
            const float* c = oacc[m][nf];
            int row = rowbase + r0 + m * 16 + gi;
            int col = hc + nf * 8 + 2 * ti;
            *(float2*)(O + row * 128 + col) =
                make_float2(c[0] * invd0[m], c[1] * invd0[m]);
            *(float2*)(O + (row + 8) * 128 + col) =
                make_float2(c[2] * invd1[m], c[3] * invd1[m]);
        }
}

// ---------------------------------------------------------------------------
// Kernel 4: per-pair cross score, fp16 m16n8k16 + ldmatrix.
// ---------------------------------------------------------------------------
#define BPW 68
#define CROSS_SMEM (2 * 128 * BPW * 4)       // 69632 B

__global__ __launch_bounds__(256) void cross_h16_kernel(
    const __half* __restrict__ P, const int* __restrict__ xsz,
    const float* __restrict__ Wc2, float* __restrict__ out)
{
    extern __shared__ unsigned smu[];
    unsigned* Xs = smu;
    unsigned* Ys = smu + 128 * BPW;
    __shared__ float red[16];

    const int b = blockIdx.x, a = blockIdx.y;
    const int tid  = threadIdx.x;
    const int lane = tid & 31, w = tid >> 5;
    const int r0 = (w & 3) * 32, c0 = (w >> 2) * 64;
    const int lrow = lane & 15;
    const int lhi  = lane >> 4;

    const __half* xp = P + (size_t)a * NITEM * 128;
    const __half* yp = P + (size_t)(ROWS_ONE + b * NITEM) * 128;

    for (int idx = tid; idx < 128 * 16; idx += 256) {
        int row = idx >> 4, w4 = (idx & 15) << 2;
        uint4 xv = *(const uint4*)(xp + row * 128 + (w4 << 1));
        uint4 yv = *(const uint4*)(yp + row * 128 + (w4 << 1));
        *(uint4*)(Xs + row * BPW + w4) = xv;
        *(uint4*)(Ys + row * BPW + w4) = yv;
    }
    __syncthreads();

    const unsigned xbase = smem_u32(Xs);
    const unsigned ybase = smem_u32(Ys);

    float hsum[2];
    #pragma unroll
    for (int h = 0; h < 2; h++) {
        const int hw = h * 32;
        float acc[64];
        #pragma unroll
        for (int i = 0; i < 64; i++) acc[i] = 0.f;

        #pragma unroll
        for (int ks = 0; ks < 4; ks++) {
            const int kw = hw + ks * 8;
            unsigned af[2][4];
            #pragma unroll
            for (int m = 0; m < 2; m++) {
                unsigned addr = xbase +
                    ((r0 + m * 16 + lrow) * BPW + kw) * 4 + lhi * 16;
                asm volatile(
                    "ldmatrix.sync.aligned.m8n8.x4.shared.b16 {%0,%1,%2,%3}, [%4];"
                    : "=r"(af[m][0]), "=r"(af[m][1]), "=r"(af[m][2]), "=r"(af[m][3])
                    : "r"(addr));
            }
            unsigned bf[8][2];
            #pragma unroll
            for (int nn = 0; nn < 4; nn++) {
                unsigned t0, t1, t2, t3;
                unsigned addr = ybase +
                    ((c0 + nn * 16 + lrow) * BPW + kw) * 4 + lhi * 16;
                asm volatile(
                    "ldmatrix.sync.aligned.m8n8.x4.shared.b16 {%0,%1,%2,%3}, [%4];"
                    : "=r"(t0), "=r"(t1), "=r"(t2), "=r"(t3)
                    : "r"(addr));
                bf[nn * 2][0]     = t0; bf[nn * 2][1]     = t2;
                bf[nn * 2 + 1][0] = t1; bf[nn * 2 + 1][1] = t3;
            }
            #pragma unroll
            for (int n = 0; n < 8; n++)
                #pragma unroll
                for (int m = 0; m < 2; m++) {
                    float* c = &acc[m * 32 + n * 4];
                    asm volatile(
                        "mma.sync.aligned.m16n8k16.row.col.f32.f16.f16.f32 "
                        "{%0,%1,%2,%3}, {%4,%5,%6,%7}, {%8,%9}, {%0,%1,%2,%3};"
                        : "+f"(c[0]), "+f"(c[1]), "+f"(c[2]), "+f"(c[3])
                        : "r"(af[m][0]), "r"(af[m][1]), "r"(af[m][2]), "r"(af[m][3]),
                          "r"(bf[n][0]), "r"(bf[n][1]));
                }
        }

        float s = 0.f;
        #pragma unroll
        for (int i = 0; i < 64; i++) {
            float v = acc[i];
            s += (v > 0.f) ? v : 0.3f * v;
        }
        hsum[h] = s;
    }

    float s0 = hsum[0], s1 = hsum[1];
    #pragma unroll
    for (int o = 16; o > 0; o >>= 1) {
        s0 += __shfl_xor_sync(0xffffffffu, s0, o);
        s1 += __shfl_xor_sync(0xffffffffu, s1, o);
    }
    if (lane == 0) { red[w] = s0; red[8 + w] = s1; }
    __syncthreads();
    if (tid == 0) {
        float S0 = 0.f, S1 = 0.f;
        #pragma unroll
        for (int i = 0; i < 8; i++) { S0 += red[i]; S1 += red[8 + i]; }
        float scale = 1.0f / (8.0f * (float)xsz[b] * 128.0f);
        out[a * NSET + b] = (S0 * Wc2[0] + S1 * Wc2[1]) * scale;
    }
}

// ---------------------------------------------------------------------------
// Launch
// ---------------------------------------------------------------------------
extern "C" void kernel_launch(void* const* d_in, const int* in_sizes, int n_in,
                              void* d_out, int out_size)
{
    const float* x    = (const float*)d_in[0];
    const float* y    = (const float*)d_in[1];
    const float* Wq   = (const float*)d_in[2];
    const float* Wk   = (const float*)d_in[3];
    const float* Wv   = (const float*)d_in[4];
    const float* Wh   = (const float*)d_in[5];
    const float* Wc   = (const float*)d_in[6];
    const float* Wc2  = (const float*)d_in[7];
    const int*   xsz  = (const int*)d_in[8];
    const int*   ysz  = (const int*)d_in[9];
    float* out = (float*)d_out;

    float *pQ, *pK, *pV, *pA, *pWf;
    __half* pPh;
    cudaGetSymbolAddress((void**)&pQ,   g_Q);
    cudaGetSymbolAddress((void**)&pK,   g_K);
    cudaGetSymbolAddress((void**)&pV,   g_V);
    cudaGetSymbolAddress((void**)&pA,   g_att);
    cudaGetSymbolAddress((void**)&pWf,  g_wf);
    cudaGetSymbolAddress((void**)&pPh,  g_ph);

    cudaFuncSetAttribute(attn_tc_kernel,   cudaFuncAttributeMaxDynamicSharedMemorySize, ATTN_SMEM);
    cudaFuncSetAttribute(cross_h16_kernel, cudaFuncAttributeMaxDynamicSharedMemorySize, CROSS_SMEM);
    cudaFuncSetAttribute(snqkv_kernel,     cudaFuncAttributeMaxDynamicSharedMemorySize, SNQKV_SMEM);
    cudaFuncSetAttribute(proj_pipe_kernel, cudaFuncAttributeMaxDynamicSharedMemorySize, PROJ_SMEM);

    sgemm_kernel<<<dim3(2, 2), 256>>>(Wh, Wc, pWf, 128, 128, 64);

    snqkv_kernel<<<2 * NSET, 256, SNQKV_SMEM>>>(
        x, y, xsz, ysz, Wq, Wk, Wv, pQ, pK, pV);

    attn_tc_kernel<<<dim3(2 * NSET, 2), 128, ATTN_SMEM>>>(pQ, pK, pV, pA);

    proj_pipe_kernel<<<ROWS_ALL / 64, 256, PROJ_SMEM>>>(pA, pWf, pPh);

    cross_h16_kernel<<<dim3(NSET, NSET), 256, CROSS_SMEM>>>(pPh, xsz, Wc2, out);
}

// round 16
// speedup vs baseline: 6.1093x; 1.0830x over previous
#include <cuda_runtime.h>
#include <cuda_fp16.h>
#include <math.h>

// ---------------------------------------------------------------------------
//   x,y: [64,128,64], HEADS=2, HS=64, LEAKY=0.3
//   fused set_norm+QKV (tf32 TC) -> fused attention+projection (tf32 QK^T,
//   frag softmax, fp16 PV, in-block fp16 att@WfT -> P) -> fp16-TC cross score
// ---------------------------------------------------------------------------

#define NSET   64
#define NITEM  128
#define DFEAT  64
#define ROWS_ONE (NSET * NITEM)        // 8192
#define ROWS_ALL (2 * ROWS_ONE)        // 16384

__device__ float g_Q   [ROWS_ALL * 128];
__device__ float g_K   [ROWS_ALL * 128];
__device__ float g_V   [ROWS_ALL * 128];
__device__ float g_wf  [128 * 128];                 // Wh @ Wc (fp32)
__device__ __half g_wfT[128 * 128];                 // (Wh@Wc)^T in fp16: [n][k]
__device__ __half g_ph [ROWS_ALL * 128];            // P in fp16

__device__ __forceinline__ unsigned f2tf32(float x) {
    unsigned r;
    asm("cvt.rna.tf32.f32 %0, %1;" : "=r"(r) : "f"(x));
    return r;
}
__device__ __forceinline__ unsigned u2tf32(unsigned u) {
    unsigned r;
    asm("cvt.rna.tf32.f32 %0, %1;" : "=r"(r) : "f"(__uint_as_float(u)));
    return r;
}
__device__ __forceinline__ unsigned smem_u32(const void* p) {
    return (unsigned)__cvta_generic_to_shared(p);
}
__device__ __forceinline__ unsigned pack_h16(float a, float b) {
    __half2 t = __floats2half2_rn(a, b);
    return *(unsigned*)&t;
}
#define CP_ASYNC16(dst_u32, src_ptr) \
    asm volatile("cp.async.cg.shared.global [%0], [%1], 16;" \
                 :: "r"(dst_u32), "l"(src_ptr))
#define CP_COMMIT() asm volatile("cp.async.commit_group;")
#define CP_WAIT0()  asm volatile("cp.async.wait_group 0;")

// ---------------------------------------------------------------------------
// Kernel 2a: small fp32 SGEMM for Wf = Wh @ Wc; also emits WfT in fp16.
// ---------------------------------------------------------------------------
__global__ __launch_bounds__(256) void sgemm_wf_kernel(
    const float* __restrict__ A, const float* __restrict__ B,
    float* __restrict__ C, __half* __restrict__ CT, int M, int N, int K)
{
    __shared__ float As[16][65];
    __shared__ float Bs[16][65];
    const int bx = blockIdx.x, by = blockIdx.y;
    const int tid = threadIdx.x;
    const int tx = tid & 15, ty = tid >> 4;

    float acc[4][4] = {};
    for (int k0 = 0; k0 < K; k0 += 16) {
        #pragma unroll
        for (int i = tid; i < 64 * 16; i += 256) {
            int r = i >> 4, kk = i & 15;
            As[kk][r] = A[(by * 64 + r) * K + k0 + kk];
        }
        #pragma unroll
        for (int i = tid; i < 16 * 64; i += 256) {
            int kk = i >> 6, c = i & 63;
            Bs[kk][c] = B[(k0 + kk) * N + bx * 64 + c];
        }
        __syncthreads();
        #pragma unroll
        for (int kk = 0; kk < 16; kk++) {
            float a[4], b[4];
            #pragma unroll
            for (int i = 0; i < 4; i++) a[i] = As[kk][ty * 4 + i];
            #pragma unroll
            for (int j = 0; j < 4; j++) b[j] = Bs[kk][tx * 4 + j];
            #pragma unroll
            for (int i = 0; i < 4; i++)
                #pragma unroll
                for (int j = 0; j < 4; j++)
                    acc[i][j] = fmaf(a[i], b[j], acc[i][j]);
        }
        __syncthreads();
    }
    #pragma unroll
    for (int i = 0; i < 4; i++)
        #pragma unroll
        for (int j = 0; j < 4; j++) {
            int row = by * 64 + ty * 4 + i, col = bx * 64 + tx * 4 + j;
            C[row * N + col] = acc[i][j];
            CT[col * 128 + row] = __float2half(acc[i][j]);
        }
}

// ---------------------------------------------------------------------------
// Kernel 1+2b FUSED: set-norm + QKV projection. One block per set (128 rows).
// ---------------------------------------------------------------------------
#define QAP 68
#define WP  132
#define SNQKV_SMEM ((128 * QAP + 2 * 64 * WP) * 4)   // 102400 B

__global__ __launch_bounds__(256) void snqkv_kernel(
    const float* __restrict__ X, const float* __restrict__ Y,
    const int* __restrict__ xsz, const int* __restrict__ ysz,
    const float* __restrict__ Wq, const float* __restrict__ Wk,
    const float* __restrict__ Wv,
    float* __restrict__ Q, float* __restrict__ Ko, float* __restrict__ V)
{
    extern __shared__ unsigned smu[];
    unsigned* As  = smu;                     // [128][QAP]
    unsigned* Ws0 = smu + 128 * QAP;         // [64][WP] double buffer
    unsigned* Ws1 = Ws0 + 64 * WP;
    float* Asf = (float*)As;

    __shared__ float rmask[NITEM];
    __shared__ float red[256];
    __shared__ float s_mean, s_inv;

    const int n   = blockIdx.x;
    const int tid = threadIdx.x, lane = tid & 31, w = tid >> 5;
    const int gi = lane >> 2, ti = lane & 3;
    const int r0 = (w & 3) * 32, c0 = (w >> 2) * 64;
    const int rbase = n * NITEM;

    const float* xb = (n < NSET) ? (X + (size_t)n * NITEM * DFEAT)
                                 : (Y + (size_t)(n - NSET) * NITEM * DFEAT);
    const int   szv = (n < NSET) ? xsz[n] : ysz[n - NSET];

    for (int idx = tid; idx < 128 * 16; idx += 256) {
        int row = idx >> 4, c4 = (idx & 15) << 2;
        CP_ASYNC16(smem_u32(As + row * QAP + c4), xb + row * 64 + c4);
    }
    for (int idx = tid; idx < 64 * 32; idx += 256) {
        int k = idx >> 5, c4 = (idx & 31) << 2;
        CP_ASYNC16(smem_u32(Ws0 + k * WP + c4), Wq + k * 128 + c4);
    }
    CP_COMMIT();
    CP_WAIT0();
    __syncthreads();

    if (tid < NITEM) {
        float s = 0.f;
        #pragma unroll
        for (int e = 0; e < DFEAT; e++) s += Asf[tid * QAP + e];
        rmask[tid] = (s != 0.0f) ? 1.0f : 0.0f;
    }

    float tot = 0.f;
    for (int idx = tid; idx < NITEM * DFEAT; idx += 256)
        tot += Asf[(idx >> 6) * QAP + (idx & 63)];
    red[tid] = tot; __syncthreads();
    for (int s = 128; s > 0; s >>= 1) {
        if (tid < s) red[tid] += red[tid + s];
        __syncthreads();
    }
    const float denom = (float)szv * (float)DFEAT;
    if (tid == 0) s_mean = red[0] / denom;
    __syncthreads();
    const float mean = s_mean;

    float ss = 0.f;
    for (int idx = tid; idx < NITEM * DFEAT; idx += 256) {
        float d = Asf[(idx >> 6) * QAP + (idx & 63)] - mean;
        ss += d * d * rmask[idx >> 6];
    }
    __syncthreads();
    red[tid] = ss; __syncthreads();
    for (int s = 128; s > 0; s >>= 1) {
        if (tid < s) red[tid] += red[tid + s];
        __syncthreads();
    }
    if (tid == 0) s_inv = 1.0f / (sqrtf(red[0] / denom) + 1e-8f);
    __syncthreads();
    const float inv = s_inv;

    for (int idx = tid; idx < NITEM * DFEAT; idx += 256) {
        int row = idx >> 6, e = idx & 63;
        Asf[row * QAP + e] = (Asf[row * QAP + e] - mean) * inv * rmask[row];
    }
    __syncthreads();

    const float* Warr[3] = {Wq, Wk, Wv};
    float*       Carr[3] = {Q, Ko, V};

    #pragma unroll
    for (int sel = 0; sel < 3; sel++) {
        unsigned* Wcur = (sel & 1) ? Ws1 : Ws0;
        unsigned* Wnxt = (sel & 1) ? Ws0 : Ws1;
        if (sel < 2) {
            const float* Wn = Warr[sel + 1];
            for (int idx = tid; idx < 64 * 32; idx += 256) {
                int k = idx >> 5, c4 = (idx & 31) << 2;
                CP_ASYNC16(smem_u32(Wnxt + k * WP + c4), Wn + k * 128 + c4);
            }
            CP_COMMIT();
        }

        float acc[64];
        #pragma unroll
        for (int i = 0; i < 64; i++) acc[i] = 0.f;

        #pragma unroll
        for (int k0 = 0; k0 < 64; k0 += 8) {
            unsigned af[2][4];
            #pragma unroll
            for (int m = 0; m < 2; m++) {
                const unsigned* ab = As + (r0 + m * 16 + gi) * QAP + k0 + ti;
                af[m][0] = u2tf32(ab[0]);
                af[m][1] = u2tf32(ab[8 * QAP]);
                af[m][2] = u2tf32(ab[4]);
                af[m][3] = u2tf32(ab[8 * QAP + 4]);
            }
            #pragma unroll
            for (int nf = 0; nf < 8; nf++) {
                const unsigned* bb = Wcur + (k0 + ti) * WP + c0 + nf * 8 + gi;
                unsigned b0 = u2tf32(bb[0]);
                unsigned b1 = u2tf32(bb[4 * WP]);
                #pragma unroll
                for (int m = 0; m < 2; m++) {
                    float* c = &acc[(m * 8 + nf) * 4];
                    asm volatile(
                        "mma.sync.aligned.m16n8k8.row.col.f32.tf32.tf32.f32 "
                        "{%0,%1,%2,%3}, {%4,%5,%6,%7}, {%8,%9}, {%0,%1,%2,%3};"
                        : "+f"(c[0]), "+f"(c[1]), "+f"(c[2]), "+f"(c[3])
                        : "r"(af[m][0]), "r"(af[m][1]), "r"(af[m][2]), "r"(af[m][3]),
                          "r"(b0), "r"(b1));
                }
            }
        }

        float* C = Carr[sel];
        #pragma unroll
        for (int m = 0; m < 2; m++)
            #pragma unroll
            for (int nf = 0; nf < 8; nf++) {
                const float* c = &acc[(m * 8 + nf) * 4];
                int row = rbase + r0 + m * 16 + gi;
                int col = c0 + nf * 8 + 2 * ti;
                *(float2*)(C + row * 128 + col)       = make_float2(c[0], c[1]);
                *(float2*)(C + (row + 8) * 128 + col) = make_float2(c[2], c[3]);
            }

        CP_WAIT0();
        __syncthreads();
    }
}

// ---------------------------------------------------------------------------
// Kernel 3 FUSED: attention + projection. One block (256 thr) per SET.
// Warps 0-3: head 0, warps 4-7: head 1 (same row ranges). After PV:
// att (fp16, normalized) -> Qs area; WfT fp16 -> Ks area (cp.async during
// softmax/PV); in-block P = att @ Wf via fp16 m16n8k16 + ldmatrix.
// ---------------------------------------------------------------------------
#define AP 132                               // Q/K tf32 pitch (words)
#define HP 68                                // fp16 tile pitch (words)
#define VPW 68                               // V pitch (words)
#define ATTN_SMEM ((2 * 128 * AP + 128 * VPW) * 4)   // 169984 B

__global__ __launch_bounds__(256) void attnproj_kernel(
    const float* __restrict__ Q, const float* __restrict__ K,
    const float* __restrict__ V, const __half* __restrict__ WfT,
    __half* __restrict__ P)
{
    extern __shared__ unsigned smu[];
    unsigned* Qs = smu;                      // [128][AP] tf32 (later: att fp16 [128][HP])
    unsigned* Ks = smu + 128 * AP;           // [128][AP] tf32 (later: WfT fp16 [128][HP])
    unsigned* Vs = smu + 2 * 128 * AP;       // [128][VPW] half2 words (both heads)

    const int g = blockIdx.x;                // global set 0..127
    const int tid = threadIdx.x, lane = tid & 31, w = tid >> 5;
    const int gi = lane >> 2, ti = lane & 3;
    const int hsel = w >> 2, wi = w & 3;
    const int r0 = wi * 32;
    const int hc = hsel * 64;
    const int rowbase = g * NITEM;

    // ---- load Q,K (tf32, full 128 cols) and V (fp16, both heads) ----
    for (int idx = tid; idx < 128 * 32; idx += 256) {
        int row = idx >> 5, c4 = (idx & 31) << 2;
        float4 qv = *(const float4*)&Q[(rowbase + row) * 128 + c4];
        float4 kv = *(const float4*)&K[(rowbase + row) * 128 + c4];
        unsigned* qd = Qs + row * AP + c4;
        unsigned* kd = Ks + row * AP + c4;
        qd[0] = f2tf32(qv.x); qd[1] = f2tf32(qv.y);
        qd[2] = f2tf32(qv.z); qd[3] = f2tf32(qv.w);
        kd[0] = f2tf32(kv.x); kd[1] = f2tf32(kv.y);
        kd[2] = f2tf32(kv.z); kd[3] = f2tf32(kv.w);
    }
    for (int idx = tid; idx < 128 * 64; idx += 256) {
        int row = idx >> 6, c = idx & 63;
        float2 vv = *(const float2*)&V[(rowbase + row) * 128 + 2 * c];
        Vs[row * VPW + c] = pack_h16(vv.x, vv.y);
    }
    __syncthreads();

    // ---- S = Q @ K^T (per-head cols) ----
    float sacc[2][16][4];
    #pragma unroll
    for (int m = 0; m < 2; m++)
        #pragma unroll
        for (int nf = 0; nf < 16; nf++)
            #pragma unroll
            for (int r = 0; r < 4; r++) sacc[m][nf][r] = 0.f;

    #pragma unroll
    for (int k0 = 0; k0 < 64; k0 += 8) {
        unsigned af[2][4];
        #pragma unroll
        for (int m = 0; m < 2; m++) {
            const unsigned* ab = Qs + (r0 + m * 16 + gi) * AP + hc + k0 + ti;
            af[m][0] = ab[0];
            af[m][1] = ab[8 * AP];
            af[m][2] = ab[4];
            af[m][3] = ab[8 * AP + 4];
        }
        #pragma unroll
        for (int nf = 0; nf < 16; nf++) {
            const unsigned* bb = Ks + (nf * 8 + gi) * AP + hc + k0 + ti;
            unsigned b0 = bb[0], b1 = bb[4];
            #pragma unroll
            for (int m = 0; m < 2; m++) {
                float* c = sacc[m][nf];
                asm volatile(
                    "mma.sync.aligned.m16n8k8.row.col.f32.tf32.tf32.f32 "
                    "{%0,%1,%2,%3}, {%4,%5,%6,%7}, {%8,%9}, {%0,%1,%2,%3};"
                    : "+f"(c[0]), "+f"(c[1]), "+f"(c[2]), "+f"(c[3])
                    : "r"(af[m][0]), "r"(af[m][1]), "r"(af[m][2]), "r"(af[m][3]),
                      "r"(b0), "r"(b1));
            }
        }
    }

    // all warps done with Ks -> start async WfT load into Ks area
    __syncthreads();
    for (int idx = tid; idx < 128 * 16; idx += 256) {
        int nrow = idx >> 4, w4 = (idx & 15) << 2;      // 4 words = 8 fp16
        CP_ASYNC16(smem_u32(Ks + nrow * HP + w4), WfT + nrow * 128 + (w4 << 1));
    }
    CP_COMMIT();

    // ---- fragment softmax (register-only) ----
    const float COEF = 0.125f * 1.44269504f;
    float invd0[2], invd1[2];
    unsigned pf[2][8][4];

    #pragma unroll
    for (int mf = 0; mf < 2; mf++) {
        float mx0 = -3.4e38f, mx1 = -3.4e38f;
        #pragma unroll
        for (int nf = 0; nf < 16; nf++) {
            mx0 = fmaxf(mx0, fmaxf(sacc[mf][nf][0], sacc[mf][nf][1]));
            mx1 = fmaxf(mx1, fmaxf(sacc[mf][nf][2], sacc[mf][nf][3]));
        }
        #pragma unroll
        for (int o = 1; o < 4; o <<= 1) {
            mx0 = fmaxf(mx0, __shfl_xor_sync(0xffffffffu, mx0, o));
            mx1 = fmaxf(mx1, __shfl_xor_sync(0xffffffffu, mx1, o));
        }
        float d0 = 0.f, d1 = 0.f;
        #pragma unroll
        for (int nf = 0; nf < 16; nf++) {
            float raw0 = sacc[mf][nf][0], raw1 = sacc[mf][nf][1];
            float raw2 = sacc[mf][nf][2], raw3 = sacc[mf][nf][3];
            float p0 = (raw0 != 0.f) ? exp2f((raw0 - mx0) * COEF) : 0.f;
            float p1 = (raw1 != 0.f) ? exp2f((raw1 - mx0) * COEF) : 0.f;
            float p2 = (raw2 != 0.f) ? exp2f((raw2 - mx1) * COEF) : 0.f;
            float p3 = (raw3 != 0.f) ? exp2f((raw3 - mx1) * COEF) : 0.f;
            sacc[mf][nf][0] = p0; sacc[mf][nf][1] = p1;
            sacc[mf][nf][2] = p2; sacc[mf][nf][3] = p3;
            d0 += p0 + p1; d1 += p2 + p3;
        }
        #pragma unroll
        for (int o = 1; o < 4; o <<= 1) {
            d0 += __shfl_xor_sync(0xffffffffu, d0, o);
            d1 += __shfl_xor_sync(0xffffffffu, d1, o);
        }
        invd0[mf] = 1.0f / (d0 + 1e-10f);
        invd1[mf] = 1.0f / (d1 + 1e-10f);

        #pragma unroll
        for (int fp = 0; fp < 8; fp++) {
            pf[mf][fp][0] = pack_h16(sacc[mf][2 * fp][0],     sacc[mf][2 * fp][1]);
            pf[mf][fp][1] = pack_h16(sacc[mf][2 * fp][2],     sacc[mf][2 * fp][3]);
            pf[mf][fp][2] = pack_h16(sacc[mf][2 * fp + 1][0], sacc[mf][2 * fp + 1][1]);
            pf[mf][fp][3] = pack_h16(sacc[mf][2 * fp + 1][2], sacc[mf][2 * fp + 1][3]);
        }
    }

    // ---- O = Pprob @ V (head cols of V) ----
    float oacc[2][8][4];
    #pragma unroll
    for (int m = 0; m < 2; m++)
        #pragma unroll
        for (int nf = 0; nf < 8; nf++)
            #pragma unroll
            for (int r = 0; r < 4; r++) oacc[m][nf][r] = 0.f;

    const unsigned vbase = smem_u32(Vs);
    #pragma unroll
    for (int kb = 0; kb < 8; kb++) {
        unsigned bfr[8][2];
        #pragma unroll
        for (int ng = 0; ng < 4; ng++) {
            unsigned t0, t1, t2, t3;
            unsigned addr = vbase +
                ((kb * 16 + (lane & 15)) * VPW + hsel * 32 + ng * 8 + (lane >> 4) * 4) * 4;
            asm volatile(
                "ldmatrix.sync.aligned.m8n8.x4.trans.shared.b16 {%0,%1,%2,%3}, [%4];"
                : "=r"(t0), "=r"(t1), "=r"(t2), "=r"(t3) : "r"(addr));
            bfr[2 * ng][0]     = t0; bfr[2 * ng][1]     = t1;
            bfr[2 * ng + 1][0] = t2; bfr[2 * ng + 1][1] = t3;
        }
        #pragma unroll
        for (int nf = 0; nf < 8; nf++)
            #pragma unroll
            for (int m = 0; m < 2; m++) {
                float* c = oacc[m][nf];
                asm volatile(
                    "mma.sync.aligned.m16n8k16.row.col.f32.f16.f16.f32 "
                    "{%0,%1,%2,%3}, {%4,%5,%6,%7}, {%8,%9}, {%0,%1,%2,%3};"
                    : "+f"(c[0]), "+f"(c[1]), "+f"(c[2]), "+f"(c[3])
                    : "r"(pf[m][kb][0]), "r"(pf[m][kb][1]),
                      "r"(pf[m][kb][2]), "r"(pf[m][kb][3]),
                      "r"(bfr[nf][0]), "r"(bfr[nf][1]));
            }
    }

    // ---- store normalized att (fp16) into Qs area; wait WfT ----
    CP_WAIT0();
    __syncthreads();                         // Qs reads (S phase) long done
    unsigned* atts = Qs;                     // [128][HP] half2 words
    #pragma unroll
    for (int m = 0; m < 2; m++)
        #pragma unroll
        for (int nf = 0; nf < 8; nf++) {
            const float* c = oacc[m][nf];
            int row = r0 + m * 16 + gi;
            int wcol = (hc >> 1) + nf * 4 + ti;
            atts[row * HP + wcol]       = pack_h16(c[0] * invd0[m], c[1] * invd0[m]);
            atts[(row + 8) * HP + wcol] = pack_h16(c[2] * invd1[m], c[3] * invd1[m]);
        }
    __syncthreads();

    // ---- P = att @ Wf : fp16 m16n8k16, ldmatrix on atts (A) + Ks=WfT (B) ----
    const int r0p = (w & 3) * 32, c0p = (w >> 2) * 64;
    const int lrow = lane & 15, lhi = lane >> 4;
    const unsigned abase = smem_u32(atts);
    const unsigned bbase = smem_u32(Ks);

    float acc[64];
    #pragma unroll
    for (int i = 0; i < 64; i++) acc[i] = 0.f;

    #pragma unroll
    for (int ks = 0; ks < 8; ks++) {
        const int kw = ks * 8;
        unsigned af[2][4];
        #pragma unroll
        for (int m = 0; m < 2; m++) {
            unsigned addr = abase + ((r0p + m * 16 + lrow) * HP + kw) * 4 + lhi * 16;
            asm volatile(
                "ldmatrix.sync.aligned.m8n8.x4.shared.b16 {%0,%1,%2,%3}, [%4];"
                : "=r"(af[m][0]), "=r"(af[m][1]), "=r"(af[m][2]), "=r"(af[m][3])
                : "r"(addr));
        }
        unsigned bf[8][2];
        #pragma unroll
        for (int nn = 0; nn < 4; nn++) {
            unsigned t0, t1, t2, t3;
            unsigned addr = bbase + ((c0p + nn * 16 + lrow) * HP + kw) * 4 + lhi * 16;
            asm volatile(
                "ldmatrix.sync.aligned.m8n8.x4.shared.b16 {%0,%1,%2,%3}, [%4];"
                : "=r"(t0), "=r"(t1), "=r"(t2), "=r"(t3)
                : "r"(addr));
            bf[nn * 2][0]     = t0; bf[nn * 2][1]     = t2;
            bf[nn * 2 + 1][0] = t1; bf[nn * 2 + 1][1] = t3;
        }
        #pragma unroll
        for (int n = 0; n < 8; n++)
            #pragma unroll
            for (int m = 0; m < 2; m++) {
                float* c = &acc[m * 32 + n * 4];
                asm volatile(
                    "mma.sync.aligned.m16n8k16.row.col.f32.f16.f16.f32 "
                    "{%0,%1,%2,%3}, {%4,%5,%6,%7}, {%8,%9}, {%0,%1,%2,%3};"
                    : "+f"(c[0]), "+f"(c[1]), "+f"(c[2]), "+f"(c[3])
                    : "r"(af[m][0]), "r"(af[m][1]), "r"(af[m][2]), "r"(af[m][3]),
                      "r"(bf[n][0]), "r"(bf[n][1]));
            }
    }

    #pragma unroll
    for (int m = 0; m < 2; m++)
        #pragma unroll
        for (int n = 0; n < 8; n++) {
            const float* c = &acc[m * 32 + n * 4];
            int row = rowbase + r0p + m * 16 + gi;
            int col = c0p + n * 8 + 2 * ti;
            *(__half2*)(P + row * 128 + col) = __floats2half2_rn(c[0], c[1]);
            *(__half2*)(P + (row + 8) * 128 + col) = __floats2half2_rn(c[2], c[3]);
        }
}

// ---------------------------------------------------------------------------
// Kernel 4: per-pair cross score, fp16 m16n8k16 + ldmatrix.
// ---------------------------------------------------------------------------
#define BPW 68
#define CROSS_SMEM (2 * 128 * BPW * 4)       // 69632 B

__global__ __launch_bounds__(256) void cross_h16_kernel(
    const __half* __restrict__ P, const int* __restrict__ xsz,
    const float* __restrict__ Wc2, float* __restrict__ out)
{
    extern __shared__ unsigned smu[];
    unsigned* Xs = smu;
    unsigned* Ys = smu + 128 * BPW;
    __shared__ float red[16];

    const int b = blockIdx.x, a = blockIdx.y;
    const int tid  = threadIdx.x;
    const int lane = tid & 31, w = tid >> 5;
    const int r0 = (w & 3) * 32, c0 = (w >> 2) * 64;
    const int lrow = lane & 15;
    const int lhi  = lane >> 4;

    const __half* xp = P + (size_t)a * NITEM * 128;
    const __half* yp = P + (size_t)(ROWS_ONE + b * NITEM) * 128;

    for (int idx = tid; idx < 128 * 16; idx += 256) {
        int row = idx >> 4, w4 = (idx & 15) << 2;
        uint4 xv = *(const uint4*)(xp + row * 128 + (w4 << 1));
        uint4 yv = *(const uint4*)(yp + row * 128 + (w4 << 1));
        *(uint4*)(Xs + row * BPW + w4) = xv;
        *(uint4*)(Ys + row * BPW + w4) = yv;
    }
    __syncthreads();

    const unsigned xbase = smem_u32(Xs);
    const unsigned ybase = smem_u32(Ys);

    float hsum[2];
    #pragma unroll
    for (int h = 0; h < 2; h++) {
        const int hw = h * 32;
        float acc[64];
        #pragma unroll
        for (int i = 0; i < 64; i++) acc[i] = 0.f;

        #pragma unroll
        for (int ks = 0; ks < 4; ks++) {
            const int kw = hw + ks * 8;
            unsigned af[2][4];
            #pragma unroll
            for (int m = 0; m < 2; m++) {
                unsigned addr = xbase +
                    ((r0 + m * 16 + lrow) * BPW + kw) * 4 + lhi * 16;
                asm volatile(
                    "ldmatrix.sync.aligned.m8n8.x4.shared.b16 {%0,%1,%2,%3}, [%4];"
                    : "=r"(af[m][0]), "=r"(af[m][1]), "=r"(af[m][2]), "=r"(af[m][3])
                    : "r"(addr));
            }
            unsigned bf[8][2];
            #pragma unroll
            for (int nn = 0; nn < 4; nn++) {
                unsigned t0, t1, t2, t3;
                unsigned addr = ybase +
                    ((c0 + nn * 16 + lrow) * BPW + kw) * 4 + lhi * 16;
                asm volatile(
                    "ldmatrix.sync.aligned.m8n8.x4.shared.b16 {%0,%1,%2,%3}, [%4];"
                    : "=r"(t0), "=r"(t1), "=r"(t2), "=r"(t3)
                    : "r"(addr));
                bf[nn * 2][0]     = t0; bf[nn * 2][1]     = t2;
                bf[nn * 2 + 1][0] = t1; bf[nn * 2 + 1][1] = t3;
            }
            #pragma unroll
            for (int n = 0; n < 8; n++)
                #pragma unroll
                for (int m = 0; m < 2; m++) {
                    float* c = &acc[m * 32 + n * 4];
                    asm volatile(
                        "mma.sync.aligned.m16n8k16.row.col.f32.f16.f16.f32 "
                        "{%0,%1,%2,%3}, {%4,%5,%6,%7}, {%8,%9}, {%0,%1,%2,%3};"
                        : "+f"(c[0]), "+f"(c[1]), "+f"(c[2]), "+f"(c[3])
                        : "r"(af[m][0]), "r"(af[m][1]), "r"(af[m][2]), "r"(af[m][3]),
                          "r"(bf[n][0]), "r"(bf[n][1]));
                }
        }

        float s = 0.f;
        #pragma unroll
        for (int i = 0; i < 64; i++) {
            float v = acc[i];
            s += (v > 0.f) ? v : 0.3f * v;
        }
        hsum[h] = s;
    }

    float s0 = hsum[0], s1 = hsum[1];
    #pragma unroll
    for (int o = 16; o > 0; o >>= 1) {
        s0 += __shfl_xor_sync(0xffffffffu, s0, o);
        s1 += __shfl_xor_sync(0xffffffffu, s1, o);
    }
    if (lane == 0) { red[w] = s0; red[8 + w] = s1; }
    __syncthreads();
    if (tid == 0) {
        float S0 = 0.f, S1 = 0.f;
        #pragma unroll
        for (int i = 0; i < 8; i++) { S0 += red[i]; S1 += red[8 + i]; }
        float scale = 1.0f / (8.0f * (float)xsz[b] * 128.0f);
        out[a * NSET + b] = (S0 * Wc2[0] + S1 * Wc2[1]) * scale;
    }
}

// ---------------------------------------------------------------------------
// Launch
// ---------------------------------------------------------------------------
extern "C" void kernel_launch(void* const* d_in, const int* in_sizes, int n_in,
                              void* d_out, int out_size)
{
    const float* x    = (const float*)d_in[0];
    const float* y    = (const float*)d_in[1];
    const float* Wq   = (const float*)d_in[2];
    const float* Wk   = (const float*)d_in[3];
    const float* Wv   = (const float*)d_in[4];
    const float* Wh   = (const float*)d_in[5];
    const float* Wc   = (const float*)d_in[6];
    const float* Wc2  = (const float*)d_in[7];
    const int*   xsz  = (const int*)d_in[8];
    const int*   ysz  = (const int*)d_in[9];
    float* out = (float*)d_out;

    float *pQ, *pK, *pV, *pWf;
    __half *pWfT, *pPh;
    cudaGetSymbolAddress((void**)&pQ,   g_Q);
    cudaGetSymbolAddress((void**)&pK,   g_K);
    cudaGetSymbolAddress((void**)&pV,   g_V);
    cudaGetSymbolAddress((void**)&pWf,  g_wf);
    cudaGetSymbolAddress((void**)&pWfT, g_wfT);
    cudaGetSymbolAddress((void**)&pPh,  g_ph);

    cudaFuncSetAttribute(attnproj_kernel,  cudaFuncAttributeMaxDynamicSharedMemorySize, ATTN_SMEM);
    cudaFuncSetAttribute(cross_h16_kernel, cudaFuncAttributeMaxDynamicSharedMemorySize, CROSS_SMEM);
    cudaFuncSetAttribute(snqkv_kernel,     cudaFuncAttributeMaxDynamicSharedMemorySize, SNQKV_SMEM);

    sgemm_wf_kernel<<<dim3(2, 2), 256>>>(Wh, Wc, pWf, pWfT, 128, 128, 64);

    snqkv_kernel<<<2 * NSET, 256, SNQKV_SMEM>>>(
        x, y, xsz, ysz, Wq, Wk, Wv, pQ, pK, pV);

    attnproj_kernel<<<2 * NSET, 256, ATTN_SMEM>>>(pQ, pK, pV, pWfT, pPh);

    cross_h16_kernel<<<dim3(NSET, NSET), 256, CROSS_SMEM>>>(pPh, xsz, Wc2, out);
}